// round 12
// baseline (speedup 1.0000x reference)
#include <cuda_runtime.h>
#include <cuda_bf16.h>
#include <math.h>
#include <stdint.h>

// Problem dims (fixed by the dataset)
#define BB   16
#define LL   512
#define DIN  1024
#define DH   1024
#define MTOT (BB * LL)   // 8192
#define WSZ  ((size_t)DH * DH)

typedef __nv_bfloat16 bf16;

// ---------------- scratch (static __device__: allocation-free) --------------
__device__ bf16 g_ohi [(size_t)MTOT * DH];
__device__ bf16 g_olo [(size_t)MTOT * DH];
__device__ bf16 g_thi [(size_t)MTOT * DH];
__device__ bf16 g_tlo [(size_t)MTOT * DH];
__device__ bf16 g_tarhi[(size_t)MTOT * DH];
__device__ bf16 g_tarlo[(size_t)MTOT * DH];
__device__ bf16 g_ofchi[(size_t)MTOT * DH];
__device__ bf16 g_ofclo[(size_t)MTOT * DH];
__device__ bf16 g_woris_hi[WSZ], g_woris_lo[WSZ];
__device__ bf16 g_wtars_hi[WSZ], g_wtars_lo[WSZ];
__device__ bf16 g_wftT_hi[WSZ],  g_wftT_lo[WSZ];
__device__ bf16 g_wfoT_hi[WSZ],  g_wfoT_lo[WSZ];
__device__ bf16 g_wfotT_hi[WSZ], g_wfotT_lo[WSZ];
__device__ bf16 g_wc_hi[3 * WSZ], g_wc_lo[3 * WSZ];
__device__ float g_bc[3][DH];
__device__ bf16 g_Qhi [(size_t)BB * LL * LL];
__device__ bf16 g_Qlo [(size_t)BB * LL * LL];
__device__ bf16 g_vthi[(size_t)BB * DH * LL];
__device__ bf16 g_vtlo[(size_t)BB * DH * LL];
__device__ float g_tar  [(size_t)MTOT * DH];
__device__ float g_ofc  [(size_t)MTOT * DH];
__device__ float g_otp  [(size_t)MTOT * DH];
__device__ float g_obuf [(size_t)MTOT * DH];
__device__ float g_Q    [(size_t)BB * LL * LL];
__device__ float g_itn  [MTOT];
__device__ float g_ifn  [MTOT];
__device__ float g_u    [MTOT];
__device__ float g_v    [MTOT];
__device__ float g_rs   [MTOT];

// ================= portable tensor-core helpers (sm_80 PTX) ==================
__device__ __forceinline__ uint32_t smem_u32(const void* p) {
    uint32_t a;
    asm("{ .reg .u64 t; cvta.to.shared.u64 t, %1; cvt.u32.u64 %0, t; }"
        : "=r"(a) : "l"(p));
    return a;
}
__device__ __forceinline__ void cp16(uint32_t s, const void* g) {
    asm volatile("cp.async.cg.shared.global [%0], [%1], 16;"
                 :: "r"(s), "l"(g) : "memory");
}
#define CP_COMMIT() asm volatile("cp.async.commit_group;" ::: "memory")
#define CP_WAIT(n)  asm volatile("cp.async.wait_group %0;" :: "n"(n) : "memory")

__device__ __forceinline__ void ldmx4(uint32_t* r, uint32_t addr) {
    asm volatile("ldmatrix.sync.aligned.m8n8.x4.shared.b16 {%0,%1,%2,%3}, [%4];"
        : "=r"(r[0]), "=r"(r[1]), "=r"(r[2]), "=r"(r[3]) : "r"(addr));
}
__device__ __forceinline__ void mma_bf16(float* d, const uint32_t* a,
                                         uint32_t b0, uint32_t b1) {
    asm volatile(
        "mma.sync.aligned.m16n8k16.row.col.f32.bf16.bf16.f32 "
        "{%0,%1,%2,%3}, {%4,%5,%6,%7}, {%8,%9}, {%0,%1,%2,%3};"
        : "+f"(d[0]), "+f"(d[1]), "+f"(d[2]), "+f"(d[3])
        : "r"(a[0]), "r"(a[1]), "r"(a[2]), "r"(a[3]), "r"(b0), "r"(b1));
}

// ===== shared mainloop: D(128x128 tile) = 3-term bf16-split, NT ==============
// 256 threads (8 warps), warp tile 64x32, K-chunk 64, 3-stage cp.async ring.
// Row stride 144 B: ldmatrix rows hit distinct banks; +ks*32B shifts uniformly.
// Segments: 0:(Ahi,Bhi)  1:(Ahi,Blo)  2:(Alo,Bhi)
#define TCSTG 3
#define CHUNKK 64
#define STAGE_BYTES (128 * 144)             // 18432
#define TC_SMEM (2 * TCSTG * STAGE_BYTES)   // 110592

template<int KDIM>
__device__ __forceinline__ void tc_core(
    const bf16* __restrict__ Ahi, const bf16* __restrict__ Alo,
    const bf16* __restrict__ Bhi, const bf16* __restrict__ Blo,
    int m0, int n0, char* dsm, float acc[4][4][4])
{
    const int CPS = KDIM / CHUNKK;    // chunks per segment
    const int NCHc = 3 * CPS;
    int tid = threadIdx.x;
    int lane = tid & 31, wid = tid >> 5;
    int warp_m = wid >> 2, warp_n = wid & 3;
    int prow = tid >> 1, pc0 = (tid & 1) * 4;   // 2 threads/row, 4x16B each

    uint32_t base = smem_u32(dsm);
    uint32_t sA[TCSTG], sB[TCSTG];
    #pragma unroll
    for (int s = 0; s < TCSTG; s++) {
        sA[s] = base + s * STAGE_BYTES;
        sB[s] = base + TCSTG * STAGE_BYTES + s * STAGE_BYTES;
    }

#define TC_PREFETCH(kc, st) {                                                  \
        int seg = (kc) / CPS;                                                  \
        int ko = ((kc) % CPS) * CHUNKK;                                        \
        const bf16* Asrc = (seg == 2) ? Alo : Ahi;                             \
        const bf16* Bsrc = (seg == 1) ? Blo : Bhi;                             \
        const bf16* ag = Asrc + (size_t)(m0 + prow) * KDIM + ko + pc0 * 8;     \
        const bf16* bg = Bsrc + (size_t)(n0 + prow) * KDIM + ko + pc0 * 8;     \
        uint32_t sa = sA[st] + prow * 144 + pc0 * 16;                          \
        uint32_t sb = sB[st] + prow * 144 + pc0 * 16;                          \
        _Pragma("unroll")                                                      \
        for (int j = 0; j < 4; j++) {                                          \
            cp16(sa + j * 16, ag + j * 8);                                     \
            cp16(sb + j * 16, bg + j * 8);                                     \
        }                                                                      \
        CP_COMMIT(); }

    int mat = lane >> 3, mr = lane & 7;
    uint32_t aoff = (uint32_t)((warp_m * 64 + (mat & 1) * 8 + mr) * 144
                               + (mat >> 1) * 16);
    uint32_t boff = (uint32_t)((warp_n * 32 + (mat >> 1) * 8 + mr) * 144
                               + (mat & 1) * 16);

    #pragma unroll
    for (int mi = 0; mi < 4; mi++)
        #pragma unroll
        for (int ni = 0; ni < 4; ni++)
            #pragma unroll
            for (int e = 0; e < 4; e++) acc[mi][ni][e] = 0.f;

    TC_PREFETCH(0, 0)
    TC_PREFETCH(1, 1)

    int st_c = 0;   // stage of current compute chunk
    for (int kc = 0; kc < NCHc; kc++) {
        CP_WAIT(TCSTG - 2);     // wait(1): stage kc complete
        __syncthreads();
        int pkc = kc + TCSTG - 1;
        int st_p = st_c + (TCSTG - 1); if (st_p >= TCSTG) st_p -= TCSTG;
        if (pkc < NCHc) { TC_PREFETCH(pkc, st_p) }
        else { CP_COMMIT(); }
        #pragma unroll
        for (int ks = 0; ks < CHUNKK; ks += 16) {
            uint32_t afr[4][4];
            #pragma unroll
            for (int mi = 0; mi < 4; mi++)
                ldmx4(afr[mi], sA[st_c] + aoff + mi * (16 * 144) + ks * 2);
            uint32_t bfr[2][4];
            #pragma unroll
            for (int np = 0; np < 2; np++)
                ldmx4(bfr[np], sB[st_c] + boff + np * (16 * 144) + ks * 2);
            #pragma unroll
            for (int mi = 0; mi < 4; mi++)
                #pragma unroll
                for (int ni = 0; ni < 4; ni++)
                    mma_bf16(acc[mi][ni], afr[mi],
                             bfr[ni >> 1][(ni & 1) * 2],
                             bfr[ni >> 1][(ni & 1) * 2 + 1]);
        }
        if (++st_c == TCSTG) st_c = 0;
    }
#undef TC_PREFETCH
}

// --------- epilogue helper: write fp32 / bf16 hi-lo from acc -----------------
__device__ __forceinline__ void tc_epilogue(
    float acc[4][4][4], int m0, int n0, const float* bias,
    float* outF, bf16* outHi, bf16* outLo)
{
    int lane = threadIdx.x & 31, wid = threadIdx.x >> 5;
    int warp_m = wid >> 2, warp_n = wid & 3;
    int gid = lane >> 2, tig = lane & 3;
    #pragma unroll
    for (int ni = 0; ni < 4; ni++) {
        int cn = n0 + warp_n * 32 + ni * 8 + tig * 2;
        float bz0 = bias ? bias[cn] : 0.f;
        float bz1 = bias ? bias[cn + 1] : 0.f;
        #pragma unroll
        for (int mi = 0; mi < 4; mi++) {
            int rm = m0 + warp_m * 64 + mi * 16 + gid;
            float c0 = acc[mi][ni][0] + bz0, c1 = acc[mi][ni][1] + bz1;
            float c2 = acc[mi][ni][2] + bz0, c3 = acc[mi][ni][3] + bz1;
            if (outF) {
                *(float2*)&outF[(size_t)rm * DH + cn]       = make_float2(c0, c1);
                *(float2*)&outF[(size_t)(rm + 8) * DH + cn] = make_float2(c2, c3);
            }
            if (outHi) {
                bf16 h0 = __float2bfloat16(c0), h1 = __float2bfloat16(c1);
                bf16 h2 = __float2bfloat16(c2), h3 = __float2bfloat16(c3);
                __nv_bfloat162 hp0; hp0.x = h0; hp0.y = h1;
                __nv_bfloat162 hp1; hp1.x = h2; hp1.y = h3;
                __nv_bfloat162 lp0;
                lp0.x = __float2bfloat16(c0 - __bfloat162float(h0));
                lp0.y = __float2bfloat16(c1 - __bfloat162float(h1));
                __nv_bfloat162 lp1;
                lp1.x = __float2bfloat16(c2 - __bfloat162float(h2));
                lp1.y = __float2bfloat16(c3 - __bfloat162float(h3));
                *(__nv_bfloat162*)&outHi[(size_t)rm * DH + cn]       = hp0;
                *(__nv_bfloat162*)&outHi[(size_t)(rm + 8) * DH + cn] = hp1;
                *(__nv_bfloat162*)&outLo[(size_t)rm * DH + cn]       = lp0;
                *(__nv_bfloat162*)&outLo[(size_t)(rm + 8) * DH + cn] = lp1;
            }
        }
    }
}

// --------- composite-weight GEMMs: WcT[z] = (Wz2^T) @ (Wz1)^T ---------------
__global__ __launch_bounds__(256) void wgemm3_kernel()
{
    extern __shared__ char dsm[];
    int z = blockIdx.z;
    int m0 = blockIdx.y * 128, n0 = blockIdx.x * 128;
    const bf16 *Ah, *Al, *Bh, *Bl;
    if (z == 0)      { Ah = g_wftT_hi;  Al = g_wftT_lo;  Bh = g_wtars_hi; Bl = g_wtars_lo; }
    else if (z == 1) { Ah = g_wfoT_hi;  Al = g_wfoT_lo;  Bh = g_woris_hi; Bl = g_woris_lo; }
    else             { Ah = g_wfotT_hi; Al = g_wfotT_lo; Bh = g_woris_hi; Bl = g_woris_lo; }
    float acc[4][4][4];
    tc_core<1024>(Ah, Al, Bh, Bl, m0, n0, dsm, acc);
    tc_epilogue(acc, m0, n0, nullptr, nullptr,
                g_wc_hi + (size_t)z * WSZ, g_wc_lo + (size_t)z * WSZ);
}

// --------- fused 3 big GEMMs -------------------------------------------------
// z=0: tar (fp32 + hi/lo)  z=1: ofc (fp32 + hi/lo)  z=2: otp (fp32)
__global__ __launch_bounds__(256) void gemm3_tc_kernel()
{
    extern __shared__ char dsm[];
    int z = blockIdx.z;
    int m0 = blockIdx.y * 128, n0 = blockIdx.x * 128;
    const bf16 *Ah, *Al;
    float* outF;
    bf16 *oH, *oL;
    if (z == 0)      { Ah = g_thi; Al = g_tlo; outF = g_tar; oH = g_tarhi; oL = g_tarlo; }
    else if (z == 1) { Ah = g_ohi; Al = g_olo; outF = g_ofc; oH = g_ofchi; oL = g_ofclo; }
    else             { Ah = g_ohi; Al = g_olo; outF = g_otp; oH = nullptr; oL = nullptr; }
    const bf16* Bh = g_wc_hi + (size_t)z * WSZ;
    const bf16* Bl = g_wc_lo + (size_t)z * WSZ;
    float acc[4][4][4];
    tc_core<1024>(Ah, Al, Bh, Bl, m0, n0, dsm, acc);
    tc_epilogue(acc, m0, n0, g_bc[z], outF, oH, oL);
}

// ---------------- Q-GEMM (NT, batched): Q = exp(20*cos) + hi/lo split --------
__global__ __launch_bounds__(256) void qgemm_tc_kernel()
{
    extern __shared__ char dsm[];
    int b = blockIdx.z;
    int m0 = blockIdx.y * 128, n0 = blockIdx.x * 128;
    const bf16* Ah = g_tarhi + (size_t)b * LL * DH;
    const bf16* Al = g_tarlo + (size_t)b * LL * DH;
    const bf16* Bh = g_ofchi + (size_t)b * LL * DH;
    const bf16* Bl = g_ofclo + (size_t)b * LL * DH;
    float acc[4][4][4];
    tc_core<1024>(Ah, Al, Bh, Bl, m0, n0, dsm, acc);

    int lane = threadIdx.x & 31, wid = threadIdx.x >> 5;
    int warp_m = wid >> 2, warp_n = wid & 3;
    int gid = lane >> 2, tig = lane & 3;
    #pragma unroll
    for (int ni = 0; ni < 4; ni++) {
        int cn = n0 + warp_n * 32 + ni * 8 + tig * 2;
        float f0 = g_ifn[b * LL + cn], f1 = g_ifn[b * LL + cn + 1];
        #pragma unroll
        for (int mi = 0; mi < 4; mi++) {
            int rm = m0 + warp_m * 64 + mi * 16 + gid;
            float s0 = g_itn[b * LL + rm] * 20.0f;
            float s1 = g_itn[b * LL + rm + 8] * 20.0f;
            float c0 = expf(acc[mi][ni][0] * s0 * f0);
            float c1 = expf(acc[mi][ni][1] * s0 * f1);
            float c2 = expf(acc[mi][ni][2] * s1 * f0);
            float c3 = expf(acc[mi][ni][3] * s1 * f1);
            size_t r0 = ((size_t)b * LL + rm) * LL + cn;
            size_t r1 = ((size_t)b * LL + rm + 8) * LL + cn;
            *(float2*)&g_Q[r0] = make_float2(c0, c1);
            *(float2*)&g_Q[r1] = make_float2(c2, c3);
            bf16 h0 = __float2bfloat16(c0), h1 = __float2bfloat16(c1);
            bf16 h2 = __float2bfloat16(c2), h3 = __float2bfloat16(c3);
            __nv_bfloat162 hp0; hp0.x = h0; hp0.y = h1;
            __nv_bfloat162 hp1; hp1.x = h2; hp1.y = h3;
            __nv_bfloat162 lp0;
            lp0.x = __float2bfloat16(c0 - __bfloat162float(h0));
            lp0.y = __float2bfloat16(c1 - __bfloat162float(h1));
            __nv_bfloat162 lp1;
            lp1.x = __float2bfloat16(c2 - __bfloat162float(h2));
            lp1.y = __float2bfloat16(c3 - __bfloat162float(h3));
            *(__nv_bfloat162*)&g_Qhi[r0] = hp0;
            *(__nv_bfloat162*)&g_Qhi[r1] = hp1;
            *(__nv_bfloat162*)&g_Qlo[r0] = lp0;
            *(__nv_bfloat162*)&g_Qlo[r1] = lp1;
        }
    }
}

// ---------------- Final GEMM (NT, batched): out = rs*(Q @ votp^T) + tar ------
__global__ __launch_bounds__(256) void fgemm_tc_kernel()
{
    extern __shared__ char dsm[];
    int b = blockIdx.z;
    int m0 = blockIdx.y * 128, n0 = blockIdx.x * 128;
    const bf16* Ah = g_Qhi + (size_t)b * LL * LL;
    const bf16* Al = g_Qlo + (size_t)b * LL * LL;
    const bf16* Bh = g_vthi + (size_t)b * DH * LL;
    const bf16* Bl = g_vtlo + (size_t)b * DH * LL;
    float acc[4][4][4];
    tc_core<512>(Ah, Al, Bh, Bl, m0, n0, dsm, acc);

    int lane = threadIdx.x & 31, wid = threadIdx.x >> 5;
    int warp_m = wid >> 2, warp_n = wid & 3;
    int gid = lane >> 2, tig = lane & 3;
    #pragma unroll
    for (int ni = 0; ni < 4; ni++) {
        int cn = n0 + warp_n * 32 + ni * 8 + tig * 2;
        #pragma unroll
        for (int mi = 0; mi < 4; mi++) {
            int rm = m0 + warp_m * 64 + mi * 16 + gid;
            int g0 = b * LL + rm, g1 = b * LL + rm + 8;
            float r0 = g_rs[g0], r1 = g_rs[g1];
            float2 t0 = *(const float2*)&g_tar[(size_t)g0 * DH + cn];
            float2 t1 = *(const float2*)&g_tar[(size_t)g1 * DH + cn];
            float2 o0 = make_float2(r0 * acc[mi][ni][0] + t0.x,
                                    r0 * acc[mi][ni][1] + t0.y);
            float2 o1 = make_float2(r1 * acc[mi][ni][2] + t1.x,
                                    r1 * acc[mi][ni][3] + t1.y);
            *(float2*)&g_obuf[(size_t)g0 * DH + cn] = o0;
            *(float2*)&g_obuf[(size_t)g1 * DH + cn] = o1;
        }
    }
}

// ---------------- fp32 -> bf16 hi/lo split -----------------------------------
__global__ __launch_bounds__(256) void split_kernel(
    const float* __restrict__ x, bf16* __restrict__ hi,
    bf16* __restrict__ lo, int n)
{
    int i = (blockIdx.x * 256 + threadIdx.x) * 4;
    if (i >= n) return;
    float4 v = *(const float4*)(x + i);
    bf16 h0 = __float2bfloat16(v.x), h1 = __float2bfloat16(v.y);
    bf16 h2 = __float2bfloat16(v.z), h3 = __float2bfloat16(v.w);
    __nv_bfloat162 hp0; hp0.x = h0; hp0.y = h1;
    __nv_bfloat162 hp1; hp1.x = h2; hp1.y = h3;
    __nv_bfloat162 lp0;
    lp0.x = __float2bfloat16(v.x - __bfloat162float(h0));
    lp0.y = __float2bfloat16(v.y - __bfloat162float(h1));
    __nv_bfloat162 lp1;
    lp1.x = __float2bfloat16(v.z - __bfloat162float(h2));
    lp1.y = __float2bfloat16(v.w - __bfloat162float(h3));
    *(__nv_bfloat162*)&hi[i]     = hp0;
    *(__nv_bfloat162*)&hi[i + 2] = hp1;
    *(__nv_bfloat162*)&lo[i]     = lp0;
    *(__nv_bfloat162*)&lo[i + 2] = lp1;
}

// ---------------- weight transpose + split: W[K,N] -> WT[N,K] hi/lo ----------
__global__ void trans_split_kernel(
    const float* __restrict__ W, bf16* __restrict__ hiT, bf16* __restrict__ loT)
{
    __shared__ float t[32][33];
    int n0 = blockIdx.x * 32, k0 = blockIdx.y * 32;
    int tx = threadIdx.x, ty = threadIdx.y;   // 32 x 8
    #pragma unroll
    for (int i = ty; i < 32; i += 8)
        t[i][tx] = W[(size_t)(k0 + i) * DH + n0 + tx];
    __syncthreads();
    #pragma unroll
    for (int i = ty; i < 32; i += 8) {
        float v = t[tx][i];
        bf16 h = __float2bfloat16(v);
        bf16 l = __float2bfloat16(v - __bfloat162float(h));
        hiT[(size_t)(n0 + i) * DH + k0 + tx] = h;
        loT[(size_t)(n0 + i) * DH + k0 + tx] = l;
    }
}

// ---------------- composite biases ------------------------------------------
__global__ void bias_comb_kernel(
    const float* __restrict__ b_tar, const float* __restrict__ b_ori,
    const float* __restrict__ W_ft, const float* __restrict__ W_fo,
    const float* __restrict__ W_fot,
    const float* __restrict__ b_ft, const float* __restrict__ b_fo,
    const float* __restrict__ b_fot)
{
    int z = blockIdx.y;
    int n = blockIdx.x * 256 + threadIdx.x;
    const float* b1 = (z == 0) ? b_tar : b_ori;
    const float* W2 = (z == 0) ? W_ft : (z == 1) ? W_fo : W_fot;
    const float* b2 = (z == 0) ? b_ft : (z == 1) ? b_fo : b_fot;
    float s = 0.f;
    for (int k = 0; k < DH; k++) s += b1[k] * W2[(size_t)k * DH + n];
    g_bc[z][n] = s + b2[n];
}

// ------- batched transpose+scale+split: vt[b][h][o] = otp[b][o][h]*v[b][o] ---
__global__ void vtrans_split_kernel()
{
    __shared__ float t[32][33];
    int b = blockIdx.z;
    int h0 = blockIdx.x * 32, o0 = blockIdx.y * 32;
    int tx = threadIdx.x, ty = threadIdx.y;   // 32 x 8
    const float* src = g_otp + (size_t)b * LL * DH;
    #pragma unroll
    for (int i = ty; i < 32; i += 8)
        t[i][tx] = src[(size_t)(o0 + i) * DH + h0 + tx] * g_v[b * LL + o0 + i];
    __syncthreads();
    bf16* hb = g_vthi + (size_t)b * DH * LL;
    bf16* lb = g_vtlo + (size_t)b * DH * LL;
    #pragma unroll
    for (int i = ty; i < 32; i += 8) {
        float x = t[tx][i];
        bf16 h = __float2bfloat16(x);
        bf16 l = __float2bfloat16(x - __bfloat162float(h));
        hb[(size_t)(h0 + i) * LL + o0 + tx] = h;
        lb[(size_t)(h0 + i) * LL + o0 + tx] = l;
    }
}

// ================= small SIMT kernels ========================================
__device__ __forceinline__ float block_reduce_sum_256(float val, float* red) {
    int tid = threadIdx.x;
    #pragma unroll
    for (int o = 16; o > 0; o >>= 1) val += __shfl_down_sync(0xffffffffu, val, o);
    if ((tid & 31) == 0) red[tid >> 5] = val;
    __syncthreads();
    if (tid < 8) {
        val = red[tid];
        #pragma unroll
        for (int o = 4; o > 0; o >>= 1) val += __shfl_down_sync(0xffu, val, o);
        if (tid == 0) red[0] = val;
    }
    __syncthreads();
    float r = red[0];
    __syncthreads();
    return r;
}

__global__ __launch_bounds__(256) void row_invnorm_kernel(
    const float* __restrict__ x, float* __restrict__ inv, float eps)
{
    __shared__ float red[8];
    int row = blockIdx.x;
    const float* p = x + (size_t)row * DH;
    float s = 0.f;
    for (int c = threadIdx.x; c < DH; c += 256) { float v = p[c]; s += v * v; }
    float tot = block_reduce_sum_256(s, red);
    if (threadIdx.x == 0) inv[row] = 1.0f / fmaxf(sqrtf(tot), eps);
}

__global__ void set_ones_kernel(float* p, int n) {
    int i = blockIdx.x * blockDim.x + threadIdx.x;
    if (i < n) p[i] = 1.0f;
}

__global__ void rowmv_kernel(const float* __restrict__ Q,
                             const float* __restrict__ v,
                             float* __restrict__ u)
{
    int t = blockIdx.x * 8 + threadIdx.y;
    int b = blockIdx.y;
    const float* row = Q + ((size_t)b * LL + t) * LL;
    const float* vv = v + b * LL;
    float s = 0.f;
    for (int o = threadIdx.x; o < LL; o += 32) s += row[o] * vv[o];
    #pragma unroll
    for (int off = 16; off > 0; off >>= 1) s += __shfl_down_sync(0xffffffffu, s, off);
    if (threadIdx.x == 0) u[b * LL + t] = 1.0f / s;
}

__global__ void colmv_kernel(const float* __restrict__ Q,
                             const float* __restrict__ u,
                             float* __restrict__ v)
{
    __shared__ float red[8][32];
    int o = blockIdx.x * 32 + threadIdx.x;
    int b = blockIdx.y;
    const float* uu = u + b * LL;
    float s = 0.f;
    for (int t = threadIdx.y; t < LL; t += 8)
        s += Q[((size_t)b * LL + t) * LL + o] * uu[t];
    red[threadIdx.y][threadIdx.x] = s;
    __syncthreads();
    if (threadIdx.y == 0) {
        float tot = 0.f;
        #pragma unroll
        for (int j = 0; j < 8; j++) tot += red[j][threadIdx.x];
        v[b * LL + o] = 1.0f / tot;
    }
}

__global__ void rowscale_kernel(const float* __restrict__ Q,
                                const float* __restrict__ v,
                                const float* __restrict__ u,
                                float* __restrict__ rs)
{
    int t = blockIdx.x * 8 + threadIdx.y;
    int b = blockIdx.y;
    const float* row = Q + ((size_t)b * LL + t) * LL;
    const float* vv = v + b * LL;
    float s = 0.f;
    for (int o = threadIdx.x; o < LL; o += 32) {
        float q = row[o] * vv[o];
        s += q * q;
    }
    #pragma unroll
    for (int off = 16; off > 0; off >>= 1) s += __shfl_down_sync(0xffffffffu, s, off);
    if (threadIdx.x == 0) {
        float ut = u[b * LL + t];
        rs[b * LL + t] = ut / fmaxf(ut * sqrtf(s), 1e-12f);
    }
}

__global__ __launch_bounds__(256) void ln_kernel(
    const float* __restrict__ x, const float* __restrict__ g,
    const float* __restrict__ beta, float* __restrict__ y)
{
    __shared__ float buf[DH];
    __shared__ float red[8];
    int row = blockIdx.x;
    const float* p = x + (size_t)row * DH;
    float s = 0.f;
    for (int c = threadIdx.x; c < DH; c += 256) { float v = p[c]; buf[c] = v; s += v; }
    float mean = block_reduce_sum_256(s, red) * (1.0f / DH);
    float s2 = 0.f;
    for (int c = threadIdx.x; c < DH; c += 256) { float d = buf[c] - mean; s2 += d * d; }
    float var = block_reduce_sum_256(s2, red) * (1.0f / DH);
    float inv = rsqrtf(var + 1e-5f);
    for (int c = threadIdx.x; c < DH; c += 256)
        y[(size_t)row * DH + c] = (buf[c] - mean) * inv * g[c] + beta[c];
}

// ---------------- launch -----------------------------------------------------
extern "C" void kernel_launch(void* const* d_in, const int* in_sizes, int n_in,
                              void* d_out, int out_size)
{
    const float* origin = (const float*)d_in[0];
    const float* target = (const float*)d_in[1];
    const float* W_ori = (const float*)d_in[2];  const float* b_ori = (const float*)d_in[3];
    const float* W_tar = (const float*)d_in[4];  const float* b_tar = (const float*)d_in[5];
    const float* W_ft  = (const float*)d_in[6];  const float* b_ft  = (const float*)d_in[7];
    const float* W_fo  = (const float*)d_in[8];  const float* b_fo  = (const float*)d_in[9];
    const float* W_fot = (const float*)d_in[10]; const float* b_fot = (const float*)d_in[11];
    const float* ln_g  = (const float*)d_in[12]; const float* ln_b  = (const float*)d_in[13];
    float* out = (float*)d_out;

    bf16 *ohi, *olo, *thi, *tlo, *woris_hi, *woris_lo, *wtars_hi, *wtars_lo;
    bf16 *wftT_hi, *wftT_lo, *wfoT_hi, *wfoT_lo, *wfotT_hi, *wfotT_lo;
    float *tar, *ofc, *obuf, *Q, *itn, *ifn, *u, *v, *rs;
    cudaGetSymbolAddress((void**)&ohi,      g_ohi);
    cudaGetSymbolAddress((void**)&olo,      g_olo);
    cudaGetSymbolAddress((void**)&thi,      g_thi);
    cudaGetSymbolAddress((void**)&tlo,      g_tlo);
    cudaGetSymbolAddress((void**)&woris_hi, g_woris_hi);
    cudaGetSymbolAddress((void**)&woris_lo, g_woris_lo);
    cudaGetSymbolAddress((void**)&wtars_hi, g_wtars_hi);
    cudaGetSymbolAddress((void**)&wtars_lo, g_wtars_lo);
    cudaGetSymbolAddress((void**)&wftT_hi,  g_wftT_hi);
    cudaGetSymbolAddress((void**)&wftT_lo,  g_wftT_lo);
    cudaGetSymbolAddress((void**)&wfoT_hi,  g_wfoT_hi);
    cudaGetSymbolAddress((void**)&wfoT_lo,  g_wfoT_lo);
    cudaGetSymbolAddress((void**)&wfotT_hi, g_wfotT_hi);
    cudaGetSymbolAddress((void**)&wfotT_lo, g_wfotT_lo);
    cudaGetSymbolAddress((void**)&tar,      g_tar);
    cudaGetSymbolAddress((void**)&ofc,      g_ofc);
    cudaGetSymbolAddress((void**)&obuf,     g_obuf);
    cudaGetSymbolAddress((void**)&Q,        g_Q);
    cudaGetSymbolAddress((void**)&itn,      g_itn);
    cudaGetSymbolAddress((void**)&ifn,      g_ifn);
    cudaGetSymbolAddress((void**)&u,        g_u);
    cudaGetSymbolAddress((void**)&v,        g_v);
    cudaGetSymbolAddress((void**)&rs,       g_rs);

    const int NELEM = MTOT * DH;
    const int WELEM = (int)WSZ;

    cudaFuncSetAttribute(wgemm3_kernel,
                         cudaFuncAttributeMaxDynamicSharedMemorySize, TC_SMEM);
    cudaFuncSetAttribute(gemm3_tc_kernel,
                         cudaFuncAttributeMaxDynamicSharedMemorySize, TC_SMEM);
    cudaFuncSetAttribute(qgemm_tc_kernel,
                         cudaFuncAttributeMaxDynamicSharedMemorySize, TC_SMEM);
    cudaFuncSetAttribute(fgemm_tc_kernel,
                         cudaFuncAttributeMaxDynamicSharedMemorySize, TC_SMEM);

    dim3 blk(256);

    // splits of activations + plain weight splits
    split_kernel<<<NELEM / 4 / 256, blk>>>(origin, ohi, olo, NELEM);
    split_kernel<<<NELEM / 4 / 256, blk>>>(target, thi, tlo, NELEM);
    split_kernel<<<WELEM / 4 / 256, blk>>>(W_ori, woris_hi, woris_lo, WELEM);
    split_kernel<<<WELEM / 4 / 256, blk>>>(W_tar, wtars_hi, wtars_lo, WELEM);

    // transposed splits of second-stage weights
    dim3 tsg(32, 32), tsb(32, 8);
    trans_split_kernel<<<tsg, tsb>>>(W_ft,  wftT_hi,  wftT_lo);
    trans_split_kernel<<<tsg, tsb>>>(W_fo,  wfoT_hi,  wfoT_lo);
    trans_split_kernel<<<tsg, tsb>>>(W_fot, wfotT_hi, wfotT_lo);

    // composite biases
    bias_comb_kernel<<<dim3(DH / 256, 3), blk>>>(
        b_tar, b_ori, W_ft, W_fo, W_fot, b_ft, b_fo, b_fot);

    // composite weights: WcT[z] via tensor cores (grid 8x8x3 = 192 CTAs)
    wgemm3_kernel<<<dim3(8, 8, 3), blk, TC_SMEM>>>();

    // fused 3 big GEMMs: tar / ofc / otp
    gemm3_tc_kernel<<<dim3(8, 64, 3), blk, TC_SMEM>>>();

    // row inverse norms for cosine similarity
    row_invnorm_kernel<<<MTOT, blk>>>(tar, itn, 1e-8f);
    row_invnorm_kernel<<<MTOT, blk>>>(ofc, ifn, 1e-8f);

    // Q = exp(cos/0.05) with hi/lo split
    qgemm_tc_kernel<<<dim3(LL / 128, LL / 128, BB), blk, TC_SMEM>>>();

    // Sinkhorn via scaling vectors: u = 1/(Qv), v = 1/(Q^T u), 5 iterations
    set_ones_kernel<<<(MTOT + 255) / 256, 256>>>(v, MTOT);
    for (int it = 0; it < 5; it++) {
        rowmv_kernel<<<dim3(LL / 8, BB), dim3(32, 8)>>>(Q, v, u);
        colmv_kernel<<<dim3(LL / 32, BB), dim3(32, 8)>>>(Q, u, v);
    }
    rowscale_kernel<<<dim3(LL / 8, BB), dim3(32, 8)>>>(Q, v, u, rs);

    // (v .* otp) transposed + split per batch
    vtrans_split_kernel<<<dim3(DH / 32, LL / 32, BB), tsb>>>();

    // out = rs_t * (Q @ vt^T) + tar
    fgemm_tc_kernel<<<dim3(DH / 128, LL / 128, BB), blk, TC_SMEM>>>();

    // LayerNorm
    ln_kernel<<<MTOT, blk>>>(obuf, ln_g, ln_b, out);
}

// round 13
// speedup vs baseline: 1.0840x; 1.0840x over previous
#include <cuda_runtime.h>
#include <cuda_bf16.h>
#include <math.h>
#include <stdint.h>

// Problem dims (fixed by the dataset)
#define BB   16
#define LL   512
#define DIN  1024
#define DH   1024
#define MTOT (BB * LL)   // 8192
#define WSZ  ((size_t)DH * DH)

typedef __nv_bfloat16 bf16;

// ---------------- scratch (static __device__: allocation-free) --------------
__device__ bf16 g_ohi [(size_t)MTOT * DH];
__device__ bf16 g_olo [(size_t)MTOT * DH];
__device__ bf16 g_thi [(size_t)MTOT * DH];
__device__ bf16 g_tlo [(size_t)MTOT * DH];
__device__ bf16 g_tarhi[(size_t)MTOT * DH];
__device__ bf16 g_tarlo[(size_t)MTOT * DH];
__device__ bf16 g_ofchi[(size_t)MTOT * DH];
__device__ bf16 g_ofclo[(size_t)MTOT * DH];
__device__ bf16 g_woris_hi[WSZ], g_woris_lo[WSZ];
__device__ bf16 g_wtars_hi[WSZ], g_wtars_lo[WSZ];
__device__ bf16 g_wftT_hi[WSZ],  g_wftT_lo[WSZ];
__device__ bf16 g_wfoT_hi[WSZ],  g_wfoT_lo[WSZ];
__device__ bf16 g_wfotT_hi[WSZ], g_wfotT_lo[WSZ];
__device__ bf16 g_wc_hi[3 * WSZ], g_wc_lo[3 * WSZ];
__device__ float g_bc[3][DH];
__device__ bf16 g_Qhi [(size_t)BB * LL * LL];
__device__ bf16 g_Qlo [(size_t)BB * LL * LL];
__device__ bf16 g_vthi[(size_t)BB * DH * LL];
__device__ bf16 g_vtlo[(size_t)BB * DH * LL];
__device__ float g_tar  [(size_t)MTOT * DH];
__device__ float g_ofc  [(size_t)MTOT * DH];
__device__ float g_otp  [(size_t)MTOT * DH];
__device__ float g_obuf [(size_t)MTOT * DH];
__device__ float g_Q    [(size_t)BB * LL * LL];
__device__ float g_itn  [MTOT];
__device__ float g_ifn  [MTOT];
__device__ float g_u    [MTOT];
__device__ float g_v    [MTOT];
__device__ float g_rs   [MTOT];

// ================= portable tensor-core helpers (sm_80 PTX) ==================
__device__ __forceinline__ uint32_t smem_u32(const void* p) {
    uint32_t a;
    asm("{ .reg .u64 t; cvta.to.shared.u64 t, %1; cvt.u32.u64 %0, t; }"
        : "=r"(a) : "l"(p));
    return a;
}
__device__ __forceinline__ void cp16(uint32_t s, const void* g) {
    asm volatile("cp.async.cg.shared.global [%0], [%1], 16;"
                 :: "r"(s), "l"(g) : "memory");
}
#define CP_COMMIT() asm volatile("cp.async.commit_group;" ::: "memory")
#define CP_WAIT(n)  asm volatile("cp.async.wait_group %0;" :: "n"(n) : "memory")

__device__ __forceinline__ void ldmx4(uint32_t* r, uint32_t addr) {
    asm volatile("ldmatrix.sync.aligned.m8n8.x4.shared.b16 {%0,%1,%2,%3}, [%4];"
        : "=r"(r[0]), "=r"(r[1]), "=r"(r[2]), "=r"(r[3]) : "r"(addr));
}
__device__ __forceinline__ void mma_bf16(float* d, const uint32_t* a,
                                         uint32_t b0, uint32_t b1) {
    asm volatile(
        "mma.sync.aligned.m16n8k16.row.col.f32.bf16.bf16.f32 "
        "{%0,%1,%2,%3}, {%4,%5,%6,%7}, {%8,%9}, {%0,%1,%2,%3};"
        : "+f"(d[0]), "+f"(d[1]), "+f"(d[2]), "+f"(d[3])
        : "r"(a[0]), "r"(a[1]), "r"(a[2]), "r"(a[3]), "r"(b0), "r"(b1));
}

// ===== shared mainloop (round-8 proven): 3-term bf16-split, NT ==============
// 256 threads (8 warps), warp tile 64x32, K-chunk 32, 4-stage cp.async ring.
#define TCSTG 4
#define STAGE_BYTES 10240            // 128 rows * 80 B
#define TC_SMEM (2 * TCSTG * STAGE_BYTES)   // 81920

template<int KDIM>
__device__ __forceinline__ void tc_core(
    const bf16* __restrict__ Ahi, const bf16* __restrict__ Alo,
    const bf16* __restrict__ Bhi, const bf16* __restrict__ Blo,
    int m0, int n0, char* dsm, float acc[4][4][4])
{
    const int CPS = KDIM / 32;        // chunks per segment
    const int NCHc = 3 * CPS;
    int tid = threadIdx.x;
    int lane = tid & 31, wid = tid >> 5;
    int warp_m = wid >> 2, warp_n = wid & 3;
    int prow = tid >> 1, pc0 = (tid & 1) * 2;

    uint32_t base = smem_u32(dsm);
    uint32_t sA[TCSTG], sB[TCSTG];
    #pragma unroll
    for (int s = 0; s < TCSTG; s++) {
        sA[s] = base + s * STAGE_BYTES;
        sB[s] = base + TCSTG * STAGE_BYTES + s * STAGE_BYTES;
    }

#define TC_PREFETCH(kc, st) {                                                  \
        int seg = (kc) / CPS;                                                  \
        int ko = ((kc) % CPS) * 32;                                            \
        const bf16* Asrc = (seg == 2) ? Alo : Ahi;                             \
        const bf16* Bsrc = (seg == 1) ? Blo : Bhi;                             \
        const bf16* ag = Asrc + (size_t)(m0 + prow) * KDIM + ko + pc0 * 8;     \
        const bf16* bg = Bsrc + (size_t)(n0 + prow) * KDIM + ko + pc0 * 8;     \
        uint32_t sa = sA[st] + prow * 80 + pc0 * 16;                           \
        uint32_t sb = sB[st] + prow * 80 + pc0 * 16;                           \
        cp16(sa, ag); cp16(sa + 16, ag + 8);                                   \
        cp16(sb, bg); cp16(sb + 16, bg + 8);                                   \
        CP_COMMIT(); }

    int mat = lane >> 3, mr = lane & 7;
    uint32_t aoff = (uint32_t)((warp_m * 64 + (mat & 1) * 8 + mr) * 80
                               + ((mat >> 1) * 8) * 2);
    uint32_t boff = (uint32_t)((warp_n * 32 + (mat >> 1) * 8 + mr) * 80
                               + ((mat & 1) * 8) * 2);

    #pragma unroll
    for (int mi = 0; mi < 4; mi++)
        #pragma unroll
        for (int ni = 0; ni < 4; ni++)
            #pragma unroll
            for (int e = 0; e < 4; e++) acc[mi][ni][e] = 0.f;

    TC_PREFETCH(0, 0)
    TC_PREFETCH(1, 1)
    TC_PREFETCH(2, 2)

    for (int kc = 0; kc < NCHc; kc++) {
        CP_WAIT(TCSTG - 2);
        __syncthreads();
        int pkc = kc + TCSTG - 1;
        if (pkc < NCHc) { TC_PREFETCH(pkc, pkc & (TCSTG - 1)) }
        else { CP_COMMIT(); }
        int b = kc & (TCSTG - 1);
        #pragma unroll
        for (int ks = 0; ks < 32; ks += 16) {
            uint32_t afr[4][4];
            #pragma unroll
            for (int mi = 0; mi < 4; mi++)
                ldmx4(afr[mi], sA[b] + aoff + mi * (16 * 80) + ks * 2);
            uint32_t bfr[2][4];
            #pragma unroll
            for (int np = 0; np < 2; np++)
                ldmx4(bfr[np], sB[b] + boff + np * (16 * 80) + ks * 2);
            #pragma unroll
            for (int mi = 0; mi < 4; mi++)
                #pragma unroll
                for (int ni = 0; ni < 4; ni++)
                    mma_bf16(acc[mi][ni], afr[mi],
                             bfr[ni >> 1][(ni & 1) * 2],
                             bfr[ni >> 1][(ni & 1) * 2 + 1]);
        }
    }
#undef TC_PREFETCH
}

// --------- epilogue helper: write fp32 / bf16 hi-lo from acc -----------------
__device__ __forceinline__ void tc_epilogue(
    float acc[4][4][4], int m0, int n0, const float* bias,
    float* outF, bf16* outHi, bf16* outLo)
{
    int lane = threadIdx.x & 31, wid = threadIdx.x >> 5;
    int warp_m = wid >> 2, warp_n = wid & 3;
    int gid = lane >> 2, tig = lane & 3;
    #pragma unroll
    for (int ni = 0; ni < 4; ni++) {
        int cn = n0 + warp_n * 32 + ni * 8 + tig * 2;
        float bz0 = bias ? bias[cn] : 0.f;
        float bz1 = bias ? bias[cn + 1] : 0.f;
        #pragma unroll
        for (int mi = 0; mi < 4; mi++) {
            int rm = m0 + warp_m * 64 + mi * 16 + gid;
            float c0 = acc[mi][ni][0] + bz0, c1 = acc[mi][ni][1] + bz1;
            float c2 = acc[mi][ni][2] + bz0, c3 = acc[mi][ni][3] + bz1;
            if (outF) {
                *(float2*)&outF[(size_t)rm * DH + cn]       = make_float2(c0, c1);
                *(float2*)&outF[(size_t)(rm + 8) * DH + cn] = make_float2(c2, c3);
            }
            if (outHi) {
                bf16 h0 = __float2bfloat16(c0), h1 = __float2bfloat16(c1);
                bf16 h2 = __float2bfloat16(c2), h3 = __float2bfloat16(c3);
                __nv_bfloat162 hp0; hp0.x = h0; hp0.y = h1;
                __nv_bfloat162 hp1; hp1.x = h2; hp1.y = h3;
                __nv_bfloat162 lp0;
                lp0.x = __float2bfloat16(c0 - __bfloat162float(h0));
                lp0.y = __float2bfloat16(c1 - __bfloat162float(h1));
                __nv_bfloat162 lp1;
                lp1.x = __float2bfloat16(c2 - __bfloat162float(h2));
                lp1.y = __float2bfloat16(c3 - __bfloat162float(h3));
                *(__nv_bfloat162*)&outHi[(size_t)rm * DH + cn]       = hp0;
                *(__nv_bfloat162*)&outHi[(size_t)(rm + 8) * DH + cn] = hp1;
                *(__nv_bfloat162*)&outLo[(size_t)rm * DH + cn]       = lp0;
                *(__nv_bfloat162*)&outLo[(size_t)(rm + 8) * DH + cn] = lp1;
            }
        }
    }
}

// --------- composite-weight GEMMs: WcT[z] = (Wz2^T) @ (Wz1)^T ---------------
__global__ __launch_bounds__(256) void wgemm3_kernel()
{
    extern __shared__ char dsm[];
    int z = blockIdx.z;
    int m0 = blockIdx.y * 128, n0 = blockIdx.x * 128;
    const bf16 *Ah, *Al, *Bh, *Bl;
    if (z == 0)      { Ah = g_wftT_hi;  Al = g_wftT_lo;  Bh = g_wtars_hi; Bl = g_wtars_lo; }
    else if (z == 1) { Ah = g_wfoT_hi;  Al = g_wfoT_lo;  Bh = g_woris_hi; Bl = g_woris_lo; }
    else             { Ah = g_wfotT_hi; Al = g_wfotT_lo; Bh = g_woris_hi; Bl = g_woris_lo; }
    float acc[4][4][4];
    tc_core<1024>(Ah, Al, Bh, Bl, m0, n0, dsm, acc);
    tc_epilogue(acc, m0, n0, nullptr, nullptr,
                g_wc_hi + (size_t)z * WSZ, g_wc_lo + (size_t)z * WSZ);
}

// --------- fused 3 big GEMMs -------------------------------------------------
// z=0: tar (fp32 + hi/lo)  z=1: ofc (fp32 + hi/lo)  z=2: otp (fp32)
__global__ __launch_bounds__(256) void gemm3_tc_kernel()
{
    extern __shared__ char dsm[];
    int z = blockIdx.z;
    int m0 = blockIdx.y * 128, n0 = blockIdx.x * 128;
    const bf16 *Ah, *Al;
    float* outF;
    bf16 *oH, *oL;
    if (z == 0)      { Ah = g_thi; Al = g_tlo; outF = g_tar; oH = g_tarhi; oL = g_tarlo; }
    else if (z == 1) { Ah = g_ohi; Al = g_olo; outF = g_ofc; oH = g_ofchi; oL = g_ofclo; }
    else             { Ah = g_ohi; Al = g_olo; outF = g_otp; oH = nullptr; oL = nullptr; }
    const bf16* Bh = g_wc_hi + (size_t)z * WSZ;
    const bf16* Bl = g_wc_lo + (size_t)z * WSZ;
    float acc[4][4][4];
    tc_core<1024>(Ah, Al, Bh, Bl, m0, n0, dsm, acc);
    tc_epilogue(acc, m0, n0, g_bc[z], outF, oH, oL);
}

// ---------------- Q-GEMM (NT, batched): Q = exp(20*cos) + hi/lo split --------
__global__ __launch_bounds__(256) void qgemm_tc_kernel()
{
    extern __shared__ char dsm[];
    int b = blockIdx.z;
    int m0 = blockIdx.y * 128, n0 = blockIdx.x * 128;
    const bf16* Ah = g_tarhi + (size_t)b * LL * DH;
    const bf16* Al = g_tarlo + (size_t)b * LL * DH;
    const bf16* Bh = g_ofchi + (size_t)b * LL * DH;
    const bf16* Bl = g_ofclo + (size_t)b * LL * DH;
    float acc[4][4][4];
    tc_core<1024>(Ah, Al, Bh, Bl, m0, n0, dsm, acc);

    int lane = threadIdx.x & 31, wid = threadIdx.x >> 5;
    int warp_m = wid >> 2, warp_n = wid & 3;
    int gid = lane >> 2, tig = lane & 3;
    #pragma unroll
    for (int ni = 0; ni < 4; ni++) {
        int cn = n0 + warp_n * 32 + ni * 8 + tig * 2;
        float f0 = g_ifn[b * LL + cn], f1 = g_ifn[b * LL + cn + 1];
        #pragma unroll
        for (int mi = 0; mi < 4; mi++) {
            int rm = m0 + warp_m * 64 + mi * 16 + gid;
            float s0 = g_itn[b * LL + rm] * 20.0f;
            float s1 = g_itn[b * LL + rm + 8] * 20.0f;
            float c0 = expf(acc[mi][ni][0] * s0 * f0);
            float c1 = expf(acc[mi][ni][1] * s0 * f1);
            float c2 = expf(acc[mi][ni][2] * s1 * f0);
            float c3 = expf(acc[mi][ni][3] * s1 * f1);
            size_t r0 = ((size_t)b * LL + rm) * LL + cn;
            size_t r1 = ((size_t)b * LL + rm + 8) * LL + cn;
            *(float2*)&g_Q[r0] = make_float2(c0, c1);
            *(float2*)&g_Q[r1] = make_float2(c2, c3);
            bf16 h0 = __float2bfloat16(c0), h1 = __float2bfloat16(c1);
            bf16 h2 = __float2bfloat16(c2), h3 = __float2bfloat16(c3);
            __nv_bfloat162 hp0; hp0.x = h0; hp0.y = h1;
            __nv_bfloat162 hp1; hp1.x = h2; hp1.y = h3;
            __nv_bfloat162 lp0;
            lp0.x = __float2bfloat16(c0 - __bfloat162float(h0));
            lp0.y = __float2bfloat16(c1 - __bfloat162float(h1));
            __nv_bfloat162 lp1;
            lp1.x = __float2bfloat16(c2 - __bfloat162float(h2));
            lp1.y = __float2bfloat16(c3 - __bfloat162float(h3));
            *(__nv_bfloat162*)&g_Qhi[r0] = hp0;
            *(__nv_bfloat162*)&g_Qhi[r1] = hp1;
            *(__nv_bfloat162*)&g_Qlo[r0] = lp0;
            *(__nv_bfloat162*)&g_Qlo[r1] = lp1;
        }
    }
}

// ---------------- Final GEMM (NT, batched): out = rs*(Q @ votp^T) + tar ------
__global__ __launch_bounds__(256) void fgemm_tc_kernel()
{
    extern __shared__ char dsm[];
    int b = blockIdx.z;
    int m0 = blockIdx.y * 128, n0 = blockIdx.x * 128;
    const bf16* Ah = g_Qhi + (size_t)b * LL * LL;
    const bf16* Al = g_Qlo + (size_t)b * LL * LL;
    const bf16* Bh = g_vthi + (size_t)b * DH * LL;
    const bf16* Bl = g_vtlo + (size_t)b * DH * LL;
    float acc[4][4][4];
    tc_core<512>(Ah, Al, Bh, Bl, m0, n0, dsm, acc);

    int lane = threadIdx.x & 31, wid = threadIdx.x >> 5;
    int warp_m = wid >> 2, warp_n = wid & 3;
    int gid = lane >> 2, tig = lane & 3;
    #pragma unroll
    for (int ni = 0; ni < 4; ni++) {
        int cn = n0 + warp_n * 32 + ni * 8 + tig * 2;
        #pragma unroll
        for (int mi = 0; mi < 4; mi++) {
            int rm = m0 + warp_m * 64 + mi * 16 + gid;
            int g0 = b * LL + rm, g1 = b * LL + rm + 8;
            float r0 = g_rs[g0], r1 = g_rs[g1];
            float2 t0 = *(const float2*)&g_tar[(size_t)g0 * DH + cn];
            float2 t1 = *(const float2*)&g_tar[(size_t)g1 * DH + cn];
            float2 o0 = make_float2(r0 * acc[mi][ni][0] + t0.x,
                                    r0 * acc[mi][ni][1] + t0.y);
            float2 o1 = make_float2(r1 * acc[mi][ni][2] + t1.x,
                                    r1 * acc[mi][ni][3] + t1.y);
            *(float2*)&g_obuf[(size_t)g0 * DH + cn] = o0;
            *(float2*)&g_obuf[(size_t)g1 * DH + cn] = o1;
        }
    }
}

// ---------------- fp32 -> bf16 hi/lo split (paired launches) -----------------
__global__ __launch_bounds__(256) void split2_kernel(
    const float* __restrict__ x0, bf16* __restrict__ hi0, bf16* __restrict__ lo0,
    const float* __restrict__ x1, bf16* __restrict__ hi1, bf16* __restrict__ lo1,
    int n)
{
    const float* x = blockIdx.y ? x1 : x0;
    bf16* hi = blockIdx.y ? hi1 : hi0;
    bf16* lo = blockIdx.y ? lo1 : lo0;
    int i = (blockIdx.x * 256 + threadIdx.x) * 4;
    if (i >= n) return;
    float4 v = *(const float4*)(x + i);
    bf16 h0 = __float2bfloat16(v.x), h1 = __float2bfloat16(v.y);
    bf16 h2 = __float2bfloat16(v.z), h3 = __float2bfloat16(v.w);
    __nv_bfloat162 hp0; hp0.x = h0; hp0.y = h1;
    __nv_bfloat162 hp1; hp1.x = h2; hp1.y = h3;
    __nv_bfloat162 lp0;
    lp0.x = __float2bfloat16(v.x - __bfloat162float(h0));
    lp0.y = __float2bfloat16(v.y - __bfloat162float(h1));
    __nv_bfloat162 lp1;
    lp1.x = __float2bfloat16(v.z - __bfloat162float(h2));
    lp1.y = __float2bfloat16(v.w - __bfloat162float(h3));
    *(__nv_bfloat162*)&hi[i]     = hp0;
    *(__nv_bfloat162*)&hi[i + 2] = hp1;
    *(__nv_bfloat162*)&lo[i]     = lp0;
    *(__nv_bfloat162*)&lo[i + 2] = lp1;
}

// ------- weight transpose + split (3 weights in one launch, grid.z) ----------
__global__ void trans_split3_kernel(
    const float* __restrict__ W0, const float* __restrict__ W1,
    const float* __restrict__ W2)
{
    __shared__ float t[32][33];
    int z = blockIdx.z;
    const float* W = (z == 0) ? W0 : (z == 1) ? W1 : W2;
    bf16* hiT = (z == 0) ? g_wftT_hi : (z == 1) ? g_wfoT_hi : g_wfotT_hi;
    bf16* loT = (z == 0) ? g_wftT_lo : (z == 1) ? g_wfoT_lo : g_wfotT_lo;
    int n0 = blockIdx.x * 32, k0 = blockIdx.y * 32;
    int tx = threadIdx.x, ty = threadIdx.y;   // 32 x 8
    #pragma unroll
    for (int i = ty; i < 32; i += 8)
        t[i][tx] = W[(size_t)(k0 + i) * DH + n0 + tx];
    __syncthreads();
    #pragma unroll
    for (int i = ty; i < 32; i += 8) {
        float v = t[tx][i];
        bf16 h = __float2bfloat16(v);
        bf16 l = __float2bfloat16(v - __bfloat162float(h));
        hiT[(size_t)(n0 + i) * DH + k0 + tx] = h;
        loT[(size_t)(n0 + i) * DH + k0 + tx] = l;
    }
}

// ---------------- composite biases ------------------------------------------
__global__ void bias_comb_kernel(
    const float* __restrict__ b_tar, const float* __restrict__ b_ori,
    const float* __restrict__ W_ft, const float* __restrict__ W_fo,
    const float* __restrict__ W_fot,
    const float* __restrict__ b_ft, const float* __restrict__ b_fo,
    const float* __restrict__ b_fot)
{
    int z = blockIdx.y;
    int n = blockIdx.x * 256 + threadIdx.x;
    const float* b1 = (z == 0) ? b_tar : b_ori;
    const float* W2 = (z == 0) ? W_ft : (z == 1) ? W_fo : W_fot;
    const float* b2 = (z == 0) ? b_ft : (z == 1) ? b_fo : b_fot;
    float s = 0.f;
    for (int k = 0; k < DH; k++) s += b1[k] * W2[(size_t)k * DH + n];
    g_bc[z][n] = s + b2[n];
}

// ------- batched transpose+scale+split: vt[b][h][o] = otp[b][o][h]*v[b][o] ---
__global__ void vtrans_split_kernel()
{
    __shared__ float t[32][33];
    int b = blockIdx.z;
    int h0 = blockIdx.x * 32, o0 = blockIdx.y * 32;
    int tx = threadIdx.x, ty = threadIdx.y;   // 32 x 8
    const float* src = g_otp + (size_t)b * LL * DH;
    #pragma unroll
    for (int i = ty; i < 32; i += 8)
        t[i][tx] = src[(size_t)(o0 + i) * DH + h0 + tx] * g_v[b * LL + o0 + i];
    __syncthreads();
    bf16* hb = g_vthi + (size_t)b * DH * LL;
    bf16* lb = g_vtlo + (size_t)b * DH * LL;
    #pragma unroll
    for (int i = ty; i < 32; i += 8) {
        float x = t[tx][i];
        bf16 h = __float2bfloat16(x);
        bf16 l = __float2bfloat16(x - __bfloat162float(h));
        hb[(size_t)(h0 + i) * LL + o0 + tx] = h;
        lb[(size_t)(h0 + i) * LL + o0 + tx] = l;
    }
}

// ================= small SIMT kernels ========================================
__device__ __forceinline__ float block_reduce_sum_256(float val, float* red) {
    int tid = threadIdx.x;
    #pragma unroll
    for (int o = 16; o > 0; o >>= 1) val += __shfl_down_sync(0xffffffffu, val, o);
    if ((tid & 31) == 0) red[tid >> 5] = val;
    __syncthreads();
    if (tid < 8) {
        val = red[tid];
        #pragma unroll
        for (int o = 4; o > 0; o >>= 1) val += __shfl_down_sync(0xffu, val, o);
        if (tid == 0) red[0] = val;
    }
    __syncthreads();
    float r = red[0];
    __syncthreads();
    return r;
}

// inv row norms: y==0 -> tar->itn, y==1 -> ofc->ifn (one launch)
__global__ __launch_bounds__(256) void invnorm2_kernel()
{
    __shared__ float red[8];
    int row = blockIdx.x;
    int which = blockIdx.y;
    const float* x = which ? g_ofc : g_tar;
    float* inv = which ? g_ifn : g_itn;
    const float* p = x + (size_t)row * DH;
    float s = 0.f;
    for (int c = threadIdx.x; c < DH; c += 256) { float v = p[c]; s += v * v; }
    float tot = block_reduce_sum_256(s, red);
    if (threadIdx.x == 0) inv[row] = 1.0f / fmaxf(sqrtf(tot), 1e-8f);
}

// u[b,t] = 1 / rowsum(Q)     (first Sinkhorn iteration: v = 1 exactly)
__global__ void rowmv_first_kernel()
{
    int t = blockIdx.x * 8 + threadIdx.y;
    int b = blockIdx.y;
    const float* row = g_Q + ((size_t)b * LL + t) * LL;
    float s = 0.f;
    for (int o = threadIdx.x; o < LL; o += 32) s += row[o];
    #pragma unroll
    for (int off = 16; off > 0; off >>= 1) s += __shfl_down_sync(0xffffffffu, s, off);
    if (threadIdx.x == 0) g_u[b * LL + t] = 1.0f / s;
}

__global__ void rowmv_kernel()
{
    int t = blockIdx.x * 8 + threadIdx.y;
    int b = blockIdx.y;
    const float* row = g_Q + ((size_t)b * LL + t) * LL;
    const float* vv = g_v + b * LL;
    float s = 0.f;
    for (int o = threadIdx.x; o < LL; o += 32) s += row[o] * vv[o];
    #pragma unroll
    for (int off = 16; off > 0; off >>= 1) s += __shfl_down_sync(0xffffffffu, s, off);
    if (threadIdx.x == 0) g_u[b * LL + t] = 1.0f / s;
}

__global__ void colmv_kernel()
{
    __shared__ float red[8][32];
    int o = blockIdx.x * 32 + threadIdx.x;
    int b = blockIdx.y;
    const float* uu = g_u + b * LL;
    float s = 0.f;
    for (int t = threadIdx.y; t < LL; t += 8)
        s += g_Q[((size_t)b * LL + t) * LL + o] * uu[t];
    red[threadIdx.y][threadIdx.x] = s;
    __syncthreads();
    if (threadIdx.y == 0) {
        float tot = 0.f;
        #pragma unroll
        for (int j = 0; j < 8; j++) tot += red[j][threadIdx.x];
        g_v[b * LL + o] = 1.0f / tot;
    }
}

__global__ void rowscale_kernel()
{
    int t = blockIdx.x * 8 + threadIdx.y;
    int b = blockIdx.y;
    const float* row = g_Q + ((size_t)b * LL + t) * LL;
    const float* vv = g_v + b * LL;
    float s = 0.f;
    for (int o = threadIdx.x; o < LL; o += 32) {
        float q = row[o] * vv[o];
        s += q * q;
    }
    #pragma unroll
    for (int off = 16; off > 0; off >>= 1) s += __shfl_down_sync(0xffffffffu, s, off);
    if (threadIdx.x == 0) {
        float ut = g_u[b * LL + t];
        g_rs[b * LL + t] = ut / fmaxf(ut * sqrtf(s), 1e-12f);
    }
}

__global__ __launch_bounds__(256) void ln_kernel(
    const float* __restrict__ x, const float* __restrict__ g,
    const float* __restrict__ beta, float* __restrict__ y)
{
    __shared__ float buf[DH];
    __shared__ float red[8];
    int row = blockIdx.x;
    const float* p = x + (size_t)row * DH;
    float s = 0.f;
    for (int c = threadIdx.x; c < DH; c += 256) { float v = p[c]; buf[c] = v; s += v; }
    float mean = block_reduce_sum_256(s, red) * (1.0f / DH);
    float s2 = 0.f;
    for (int c = threadIdx.x; c < DH; c += 256) { float d = buf[c] - mean; s2 += d * d; }
    float var = block_reduce_sum_256(s2, red) * (1.0f / DH);
    float inv = rsqrtf(var + 1e-5f);
    for (int c = threadIdx.x; c < DH; c += 256)
        y[(size_t)row * DH + c] = (buf[c] - mean) * inv * g[c] + beta[c];
}

// ---------------- launch -----------------------------------------------------
extern "C" void kernel_launch(void* const* d_in, const int* in_sizes, int n_in,
                              void* d_out, int out_size)
{
    const float* origin = (const float*)d_in[0];
    const float* target = (const float*)d_in[1];
    const float* W_ori = (const float*)d_in[2];  const float* b_ori = (const float*)d_in[3];
    const float* W_tar = (const float*)d_in[4];  const float* b_tar = (const float*)d_in[5];
    const float* W_ft  = (const float*)d_in[6];  const float* b_ft  = (const float*)d_in[7];
    const float* W_fo  = (const float*)d_in[8];  const float* b_fo  = (const float*)d_in[9];
    const float* W_fot = (const float*)d_in[10]; const float* b_fot = (const float*)d_in[11];
    const float* ln_g  = (const float*)d_in[12]; const float* ln_b  = (const float*)d_in[13];
    float* out = (float*)d_out;

    bf16 *ohi, *olo, *thi, *tlo, *woris_hi, *woris_lo, *wtars_hi, *wtars_lo;
    float *obuf;
    cudaGetSymbolAddress((void**)&ohi,      g_ohi);
    cudaGetSymbolAddress((void**)&olo,      g_olo);
    cudaGetSymbolAddress((void**)&thi,      g_thi);
    cudaGetSymbolAddress((void**)&tlo,      g_tlo);
    cudaGetSymbolAddress((void**)&woris_hi, g_woris_hi);
    cudaGetSymbolAddress((void**)&woris_lo, g_woris_lo);
    cudaGetSymbolAddress((void**)&wtars_hi, g_wtars_hi);
    cudaGetSymbolAddress((void**)&wtars_lo, g_wtars_lo);
    cudaGetSymbolAddress((void**)&obuf,     g_obuf);

    const int NELEM = MTOT * DH;
    const int WELEM = (int)WSZ;

    cudaFuncSetAttribute(wgemm3_kernel,
                         cudaFuncAttributeMaxDynamicSharedMemorySize, TC_SMEM);
    cudaFuncSetAttribute(gemm3_tc_kernel,
                         cudaFuncAttributeMaxDynamicSharedMemorySize, TC_SMEM);
    cudaFuncSetAttribute(qgemm_tc_kernel,
                         cudaFuncAttributeMaxDynamicSharedMemorySize, TC_SMEM);
    cudaFuncSetAttribute(fgemm_tc_kernel,
                         cudaFuncAttributeMaxDynamicSharedMemorySize, TC_SMEM);

    dim3 blk(256);

    // activation splits (one launch) + plain weight splits (one launch)
    split2_kernel<<<dim3(NELEM / 4 / 256, 2), blk>>>(
        origin, ohi, olo, target, thi, tlo, NELEM);
    split2_kernel<<<dim3(WELEM / 4 / 256, 2), blk>>>(
        W_ori, woris_hi, woris_lo, W_tar, wtars_hi, wtars_lo, WELEM);

    // transposed splits of second-stage weights (one launch)
    trans_split3_kernel<<<dim3(32, 32, 3), dim3(32, 8)>>>(W_ft, W_fo, W_fot);

    // composite biases
    bias_comb_kernel<<<dim3(DH / 256, 3), blk>>>(
        b_tar, b_ori, W_ft, W_fo, W_fot, b_ft, b_fo, b_fot);

    // composite weights: WcT[z] via tensor cores (192 CTAs)
    wgemm3_kernel<<<dim3(8, 8, 3), blk, TC_SMEM>>>();

    // fused 3 big GEMMs: tar / ofc / otp
    gemm3_tc_kernel<<<dim3(8, 64, 3), blk, TC_SMEM>>>();

    // row inverse norms (one launch, both arrays)
    invnorm2_kernel<<<dim3(MTOT, 2), blk>>>();

    // Q = exp(cos/0.05) with hi/lo split
    qgemm_tc_kernel<<<dim3(LL / 128, LL / 128, BB), blk, TC_SMEM>>>();

    // Sinkhorn: u = 1/(Qv), v = 1/(Q^T u), 5 iterations (first has v = 1)
    rowmv_first_kernel<<<dim3(LL / 8, BB), dim3(32, 8)>>>();
    colmv_kernel<<<dim3(LL / 32, BB), dim3(32, 8)>>>();
    for (int it = 0; it < 4; it++) {
        rowmv_kernel<<<dim3(LL / 8, BB), dim3(32, 8)>>>();
        colmv_kernel<<<dim3(LL / 32, BB), dim3(32, 8)>>>();
    }
    rowscale_kernel<<<dim3(LL / 8, BB), dim3(32, 8)>>>();

    // (v .* otp) transposed + split per batch
    vtrans_split_kernel<<<dim3(DH / 32, LL / 32, BB), dim3(32, 8)>>>();

    // out = rs_t * (Q @ vt^T) + tar
    fgemm_tc_kernel<<<dim3(DH / 128, LL / 128, BB), blk, TC_SMEM>>>();

    // LayerNorm
    ln_kernel<<<MTOT, blk>>>(obuf, ln_g, ln_b, out);
}

// round 14
// speedup vs baseline: 1.1107x; 1.0246x over previous
#include <cuda_runtime.h>
#include <cuda_bf16.h>
#include <math.h>
#include <stdint.h>

// Problem dims (fixed by the dataset)
#define BB   16
#define LL   512
#define DIN  1024
#define DH   1024
#define MTOT (BB * LL)   // 8192
#define WSZ  ((size_t)DH * DH)

typedef __nv_bfloat16 bf16;

// ---------------- scratch (static __device__: allocation-free) --------------
__device__ bf16 g_ohi [(size_t)MTOT * DH];
__device__ bf16 g_olo [(size_t)MTOT * DH];
__device__ bf16 g_thi [(size_t)MTOT * DH];
__device__ bf16 g_tlo [(size_t)MTOT * DH];
__device__ bf16 g_tarhi[(size_t)MTOT * DH];
__device__ bf16 g_tarlo[(size_t)MTOT * DH];
__device__ bf16 g_ofchi[(size_t)MTOT * DH];
__device__ bf16 g_ofclo[(size_t)MTOT * DH];
__device__ bf16 g_woris_hi[WSZ], g_woris_lo[WSZ];
__device__ bf16 g_wtars_hi[WSZ], g_wtars_lo[WSZ];
__device__ bf16 g_wftT_hi[WSZ],  g_wftT_lo[WSZ];
__device__ bf16 g_wfoT_hi[WSZ],  g_wfoT_lo[WSZ];
__device__ bf16 g_wfotT_hi[WSZ], g_wfotT_lo[WSZ];
__device__ bf16 g_wc_hi[3 * WSZ], g_wc_lo[3 * WSZ];
__device__ float g_bc[3][DH];
__device__ bf16 g_Qhi [(size_t)BB * LL * LL];
__device__ bf16 g_Qlo [(size_t)BB * LL * LL];
__device__ bf16 g_vthi[(size_t)BB * DH * LL];
__device__ bf16 g_vtlo[(size_t)BB * DH * LL];
__device__ float g_tar  [(size_t)MTOT * DH];
__device__ float g_ofc  [(size_t)MTOT * DH];
__device__ float g_otp  [(size_t)MTOT * DH];
__device__ float g_obuf [(size_t)MTOT * DH];
__device__ float g_Q    [(size_t)BB * LL * LL];
__device__ float g_itn  [MTOT];
__device__ float g_ifn  [MTOT];
__device__ float g_u    [MTOT];
__device__ float g_v    [MTOT];
__device__ float g_rs   [MTOT];

// ================= portable tensor-core helpers (sm_80 PTX) ==================
__device__ __forceinline__ uint32_t smem_u32(const void* p) {
    uint32_t a;
    asm("{ .reg .u64 t; cvta.to.shared.u64 t, %1; cvt.u32.u64 %0, t; }"
        : "=r"(a) : "l"(p));
    return a;
}
__device__ __forceinline__ void cp16(uint32_t s, const void* g) {
    asm volatile("cp.async.cg.shared.global [%0], [%1], 16;"
                 :: "r"(s), "l"(g) : "memory");
}
#define CP_COMMIT() asm volatile("cp.async.commit_group;" ::: "memory")
#define CP_WAIT(n)  asm volatile("cp.async.wait_group %0;" :: "n"(n) : "memory")

__device__ __forceinline__ void ldmx4(uint32_t* r, uint32_t addr) {
    asm volatile("ldmatrix.sync.aligned.m8n8.x4.shared.b16 {%0,%1,%2,%3}, [%4];"
        : "=r"(r[0]), "=r"(r[1]), "=r"(r[2]), "=r"(r[3]) : "r"(addr));
}
__device__ __forceinline__ void mma_bf16(float* d, const uint32_t* a,
                                         uint32_t b0, uint32_t b1) {
    asm volatile(
        "mma.sync.aligned.m16n8k16.row.col.f32.bf16.bf16.f32 "
        "{%0,%1,%2,%3}, {%4,%5,%6,%7}, {%8,%9}, {%0,%1,%2,%3};"
        : "+f"(d[0]), "+f"(d[1]), "+f"(d[2]), "+f"(d[3])
        : "r"(a[0]), "r"(a[1]), "r"(a[2]), "r"(a[3]), "r"(b0), "r"(b1));
}

// ===== shared mainloop (round-8 proven): 3-term bf16-split, NT ==============
// 256 threads (8 warps), warp tile 64x32, K-chunk 32, 4-stage cp.async ring.
#define TCSTG 4
#define STAGE_BYTES 10240            // 128 rows * 80 B
#define TC_SMEM (2 * TCSTG * STAGE_BYTES)   // 81920

template<int KDIM>
__device__ __forceinline__ void tc_core(
    const bf16* __restrict__ Ahi, const bf16* __restrict__ Alo,
    const bf16* __restrict__ Bhi, const bf16* __restrict__ Blo,
    int m0, int n0, char* dsm, float acc[4][4][4])
{
    const int CPS = KDIM / 32;        // chunks per segment
    const int NCHc = 3 * CPS;
    int tid = threadIdx.x;
    int lane = tid & 31, wid = tid >> 5;
    int warp_m = wid >> 2, warp_n = wid & 3;
    int prow = tid >> 1, pc0 = (tid & 1) * 2;

    uint32_t base = smem_u32(dsm);
    uint32_t sA[TCSTG], sB[TCSTG];
    #pragma unroll
    for (int s = 0; s < TCSTG; s++) {
        sA[s] = base + s * STAGE_BYTES;
        sB[s] = base + TCSTG * STAGE_BYTES + s * STAGE_BYTES;
    }

#define TC_PREFETCH(kc, st) {                                                  \
        int seg = (kc) / CPS;                                                  \
        int ko = ((kc) % CPS) * 32;                                            \
        const bf16* Asrc = (seg == 2) ? Alo : Ahi;                             \
        const bf16* Bsrc = (seg == 1) ? Blo : Bhi;                             \
        const bf16* ag = Asrc + (size_t)(m0 + prow) * KDIM + ko + pc0 * 8;     \
        const bf16* bg = Bsrc + (size_t)(n0 + prow) * KDIM + ko + pc0 * 8;     \
        uint32_t sa = sA[st] + prow * 80 + pc0 * 16;                           \
        uint32_t sb = sB[st] + prow * 80 + pc0 * 16;                           \
        cp16(sa, ag); cp16(sa + 16, ag + 8);                                   \
        cp16(sb, bg); cp16(sb + 16, bg + 8);                                   \
        CP_COMMIT(); }

    int mat = lane >> 3, mr = lane & 7;
    uint32_t aoff = (uint32_t)((warp_m * 64 + (mat & 1) * 8 + mr) * 80
                               + ((mat >> 1) * 8) * 2);
    uint32_t boff = (uint32_t)((warp_n * 32 + (mat >> 1) * 8 + mr) * 80
                               + ((mat & 1) * 8) * 2);

    #pragma unroll
    for (int mi = 0; mi < 4; mi++)
        #pragma unroll
        for (int ni = 0; ni < 4; ni++)
            #pragma unroll
            for (int e = 0; e < 4; e++) acc[mi][ni][e] = 0.f;

    TC_PREFETCH(0, 0)
    TC_PREFETCH(1, 1)
    TC_PREFETCH(2, 2)

    for (int kc = 0; kc < NCHc; kc++) {
        CP_WAIT(TCSTG - 2);
        __syncthreads();
        int pkc = kc + TCSTG - 1;
        if (pkc < NCHc) { TC_PREFETCH(pkc, pkc & (TCSTG - 1)) }
        else { CP_COMMIT(); }
        int b = kc & (TCSTG - 1);
        #pragma unroll
        for (int ks = 0; ks < 32; ks += 16) {
            uint32_t afr[4][4];
            #pragma unroll
            for (int mi = 0; mi < 4; mi++)
                ldmx4(afr[mi], sA[b] + aoff + mi * (16 * 80) + ks * 2);
            uint32_t bfr[2][4];
            #pragma unroll
            for (int np = 0; np < 2; np++)
                ldmx4(bfr[np], sB[b] + boff + np * (16 * 80) + ks * 2);
            #pragma unroll
            for (int mi = 0; mi < 4; mi++)
                #pragma unroll
                for (int ni = 0; ni < 4; ni++)
                    mma_bf16(acc[mi][ni], afr[mi],
                             bfr[ni >> 1][(ni & 1) * 2],
                             bfr[ni >> 1][(ni & 1) * 2 + 1]);
        }
    }
#undef TC_PREFETCH
}

// --------- epilogue helper: write fp32 / bf16 hi-lo from acc -----------------
__device__ __forceinline__ void tc_epilogue(
    float acc[4][4][4], int m0, int n0, const float* bias,
    float* outF, bf16* outHi, bf16* outLo)
{
    int lane = threadIdx.x & 31, wid = threadIdx.x >> 5;
    int warp_m = wid >> 2, warp_n = wid & 3;
    int gid = lane >> 2, tig = lane & 3;
    #pragma unroll
    for (int ni = 0; ni < 4; ni++) {
        int cn = n0 + warp_n * 32 + ni * 8 + tig * 2;
        float bz0 = bias ? bias[cn] : 0.f;
        float bz1 = bias ? bias[cn + 1] : 0.f;
        #pragma unroll
        for (int mi = 0; mi < 4; mi++) {
            int rm = m0 + warp_m * 64 + mi * 16 + gid;
            float c0 = acc[mi][ni][0] + bz0, c1 = acc[mi][ni][1] + bz1;
            float c2 = acc[mi][ni][2] + bz0, c3 = acc[mi][ni][3] + bz1;
            if (outF) {
                *(float2*)&outF[(size_t)rm * DH + cn]       = make_float2(c0, c1);
                *(float2*)&outF[(size_t)(rm + 8) * DH + cn] = make_float2(c2, c3);
            }
            if (outHi) {
                bf16 h0 = __float2bfloat16(c0), h1 = __float2bfloat16(c1);
                bf16 h2 = __float2bfloat16(c2), h3 = __float2bfloat16(c3);
                __nv_bfloat162 hp0; hp0.x = h0; hp0.y = h1;
                __nv_bfloat162 hp1; hp1.x = h2; hp1.y = h3;
                __nv_bfloat162 lp0;
                lp0.x = __float2bfloat16(c0 - __bfloat162float(h0));
                lp0.y = __float2bfloat16(c1 - __bfloat162float(h1));
                __nv_bfloat162 lp1;
                lp1.x = __float2bfloat16(c2 - __bfloat162float(h2));
                lp1.y = __float2bfloat16(c3 - __bfloat162float(h3));
                *(__nv_bfloat162*)&outHi[(size_t)rm * DH + cn]       = hp0;
                *(__nv_bfloat162*)&outHi[(size_t)(rm + 8) * DH + cn] = hp1;
                *(__nv_bfloat162*)&outLo[(size_t)rm * DH + cn]       = lp0;
                *(__nv_bfloat162*)&outLo[(size_t)(rm + 8) * DH + cn] = lp1;
            }
        }
    }
}

// --------- composite-weight GEMMs: WcT[z] = (Wz2^T) @ (Wz1)^T ---------------
__global__ __launch_bounds__(256) void wgemm3_kernel()
{
    extern __shared__ char dsm[];
    int z = blockIdx.z;
    int m0 = blockIdx.y * 128, n0 = blockIdx.x * 128;
    const bf16 *Ah, *Al, *Bh, *Bl;
    if (z == 0)      { Ah = g_wftT_hi;  Al = g_wftT_lo;  Bh = g_wtars_hi; Bl = g_wtars_lo; }
    else if (z == 1) { Ah = g_wfoT_hi;  Al = g_wfoT_lo;  Bh = g_woris_hi; Bl = g_woris_lo; }
    else             { Ah = g_wfotT_hi; Al = g_wfotT_lo; Bh = g_woris_hi; Bl = g_woris_lo; }
    float acc[4][4][4];
    tc_core<1024>(Ah, Al, Bh, Bl, m0, n0, dsm, acc);
    tc_epilogue(acc, m0, n0, nullptr, nullptr,
                g_wc_hi + (size_t)z * WSZ, g_wc_lo + (size_t)z * WSZ);
}

// --------- fused 3 big GEMMs -------------------------------------------------
// z=0: tar (fp32 + hi/lo)  z=1: ofc (fp32 + hi/lo)  z=2: otp (fp32)
__global__ __launch_bounds__(256) void gemm3_tc_kernel()
{
    extern __shared__ char dsm[];
    int z = blockIdx.z;
    int m0 = blockIdx.y * 128, n0 = blockIdx.x * 128;
    const bf16 *Ah, *Al;
    float* outF;
    bf16 *oH, *oL;
    if (z == 0)      { Ah = g_thi; Al = g_tlo; outF = g_tar; oH = g_tarhi; oL = g_tarlo; }
    else if (z == 1) { Ah = g_ohi; Al = g_olo; outF = g_ofc; oH = g_ofchi; oL = g_ofclo; }
    else             { Ah = g_ohi; Al = g_olo; outF = g_otp; oH = nullptr; oL = nullptr; }
    const bf16* Bh = g_wc_hi + (size_t)z * WSZ;
    const bf16* Bl = g_wc_lo + (size_t)z * WSZ;
    float acc[4][4][4];
    tc_core<1024>(Ah, Al, Bh, Bl, m0, n0, dsm, acc);
    tc_epilogue(acc, m0, n0, g_bc[z], outF, oH, oL);
}

// ---------------- Q-GEMM (NT, batched): Q = exp(20*cos) + hi/lo split --------
__global__ __launch_bounds__(256) void qgemm_tc_kernel()
{
    extern __shared__ char dsm[];
    int b = blockIdx.z;
    int m0 = blockIdx.y * 128, n0 = blockIdx.x * 128;
    const bf16* Ah = g_tarhi + (size_t)b * LL * DH;
    const bf16* Al = g_tarlo + (size_t)b * LL * DH;
    const bf16* Bh = g_ofchi + (size_t)b * LL * DH;
    const bf16* Bl = g_ofclo + (size_t)b * LL * DH;
    float acc[4][4][4];
    tc_core<1024>(Ah, Al, Bh, Bl, m0, n0, dsm, acc);

    int lane = threadIdx.x & 31, wid = threadIdx.x >> 5;
    int warp_m = wid >> 2, warp_n = wid & 3;
    int gid = lane >> 2, tig = lane & 3;
    #pragma unroll
    for (int ni = 0; ni < 4; ni++) {
        int cn = n0 + warp_n * 32 + ni * 8 + tig * 2;
        float f0 = g_ifn[b * LL + cn], f1 = g_ifn[b * LL + cn + 1];
        #pragma unroll
        for (int mi = 0; mi < 4; mi++) {
            int rm = m0 + warp_m * 64 + mi * 16 + gid;
            float s0 = g_itn[b * LL + rm] * 20.0f;
            float s1 = g_itn[b * LL + rm + 8] * 20.0f;
            float c0 = expf(acc[mi][ni][0] * s0 * f0);
            float c1 = expf(acc[mi][ni][1] * s0 * f1);
            float c2 = expf(acc[mi][ni][2] * s1 * f0);
            float c3 = expf(acc[mi][ni][3] * s1 * f1);
            size_t r0 = ((size_t)b * LL + rm) * LL + cn;
            size_t r1 = ((size_t)b * LL + rm + 8) * LL + cn;
            *(float2*)&g_Q[r0] = make_float2(c0, c1);
            *(float2*)&g_Q[r1] = make_float2(c2, c3);
            bf16 h0 = __float2bfloat16(c0), h1 = __float2bfloat16(c1);
            bf16 h2 = __float2bfloat16(c2), h3 = __float2bfloat16(c3);
            __nv_bfloat162 hp0; hp0.x = h0; hp0.y = h1;
            __nv_bfloat162 hp1; hp1.x = h2; hp1.y = h3;
            __nv_bfloat162 lp0;
            lp0.x = __float2bfloat16(c0 - __bfloat162float(h0));
            lp0.y = __float2bfloat16(c1 - __bfloat162float(h1));
            __nv_bfloat162 lp1;
            lp1.x = __float2bfloat16(c2 - __bfloat162float(h2));
            lp1.y = __float2bfloat16(c3 - __bfloat162float(h3));
            *(__nv_bfloat162*)&g_Qhi[r0] = hp0;
            *(__nv_bfloat162*)&g_Qhi[r1] = hp1;
            *(__nv_bfloat162*)&g_Qlo[r0] = lp0;
            *(__nv_bfloat162*)&g_Qlo[r1] = lp1;
        }
    }
}

// ---------------- Final GEMM (NT, batched): out = rs*(Q @ votp^T) + tar ------
__global__ __launch_bounds__(256) void fgemm_tc_kernel()
{
    extern __shared__ char dsm[];
    int b = blockIdx.z;
    int m0 = blockIdx.y * 128, n0 = blockIdx.x * 128;
    const bf16* Ah = g_Qhi + (size_t)b * LL * LL;
    const bf16* Al = g_Qlo + (size_t)b * LL * LL;
    const bf16* Bh = g_vthi + (size_t)b * DH * LL;
    const bf16* Bl = g_vtlo + (size_t)b * DH * LL;
    float acc[4][4][4];
    tc_core<512>(Ah, Al, Bh, Bl, m0, n0, dsm, acc);

    int lane = threadIdx.x & 31, wid = threadIdx.x >> 5;
    int warp_m = wid >> 2, warp_n = wid & 3;
    int gid = lane >> 2, tig = lane & 3;
    #pragma unroll
    for (int ni = 0; ni < 4; ni++) {
        int cn = n0 + warp_n * 32 + ni * 8 + tig * 2;
        #pragma unroll
        for (int mi = 0; mi < 4; mi++) {
            int rm = m0 + warp_m * 64 + mi * 16 + gid;
            int g0 = b * LL + rm, g1 = b * LL + rm + 8;
            float r0 = g_rs[g0], r1 = g_rs[g1];
            float2 t0 = *(const float2*)&g_tar[(size_t)g0 * DH + cn];
            float2 t1 = *(const float2*)&g_tar[(size_t)g1 * DH + cn];
            float2 o0 = make_float2(r0 * acc[mi][ni][0] + t0.x,
                                    r0 * acc[mi][ni][1] + t0.y);
            float2 o1 = make_float2(r1 * acc[mi][ni][2] + t1.x,
                                    r1 * acc[mi][ni][3] + t1.y);
            *(float2*)&g_obuf[(size_t)g0 * DH + cn] = o0;
            *(float2*)&g_obuf[(size_t)g1 * DH + cn] = o1;
        }
    }
}

// ---------------- fp32 -> bf16 hi/lo split (paired launches) -----------------
__global__ __launch_bounds__(256) void split2_kernel(
    const float* __restrict__ x0, bf16* __restrict__ hi0, bf16* __restrict__ lo0,
    const float* __restrict__ x1, bf16* __restrict__ hi1, bf16* __restrict__ lo1,
    int n)
{
    const float* x = blockIdx.y ? x1 : x0;
    bf16* hi = blockIdx.y ? hi1 : hi0;
    bf16* lo = blockIdx.y ? lo1 : lo0;
    int i = (blockIdx.x * 256 + threadIdx.x) * 4;
    if (i >= n) return;
    float4 v = *(const float4*)(x + i);
    bf16 h0 = __float2bfloat16(v.x), h1 = __float2bfloat16(v.y);
    bf16 h2 = __float2bfloat16(v.z), h3 = __float2bfloat16(v.w);
    __nv_bfloat162 hp0; hp0.x = h0; hp0.y = h1;
    __nv_bfloat162 hp1; hp1.x = h2; hp1.y = h3;
    __nv_bfloat162 lp0;
    lp0.x = __float2bfloat16(v.x - __bfloat162float(h0));
    lp0.y = __float2bfloat16(v.y - __bfloat162float(h1));
    __nv_bfloat162 lp1;
    lp1.x = __float2bfloat16(v.z - __bfloat162float(h2));
    lp1.y = __float2bfloat16(v.w - __bfloat162float(h3));
    *(__nv_bfloat162*)&hi[i]     = hp0;
    *(__nv_bfloat162*)&hi[i + 2] = hp1;
    *(__nv_bfloat162*)&lo[i]     = lp0;
    *(__nv_bfloat162*)&lo[i + 2] = lp1;
}

// ------- weight transpose + split (3 weights in one launch, grid.z) ----------
__global__ void trans_split3_kernel(
    const float* __restrict__ W0, const float* __restrict__ W1,
    const float* __restrict__ W2)
{
    __shared__ float t[32][33];
    int z = blockIdx.z;
    const float* W = (z == 0) ? W0 : (z == 1) ? W1 : W2;
    bf16* hiT = (z == 0) ? g_wftT_hi : (z == 1) ? g_wfoT_hi : g_wfotT_hi;
    bf16* loT = (z == 0) ? g_wftT_lo : (z == 1) ? g_wfoT_lo : g_wfotT_lo;
    int n0 = blockIdx.x * 32, k0 = blockIdx.y * 32;
    int tx = threadIdx.x, ty = threadIdx.y;   // 32 x 8
    #pragma unroll
    for (int i = ty; i < 32; i += 8)
        t[i][tx] = W[(size_t)(k0 + i) * DH + n0 + tx];
    __syncthreads();
    #pragma unroll
    for (int i = ty; i < 32; i += 8) {
        float v = t[tx][i];
        bf16 h = __float2bfloat16(v);
        bf16 l = __float2bfloat16(v - __bfloat162float(h));
        hiT[(size_t)(n0 + i) * DH + k0 + tx] = h;
        loT[(size_t)(n0 + i) * DH + k0 + tx] = l;
    }
}

// ---------------- composite biases (split-k, parallel) -----------------------
// bc[z][n] = sum_k b1[k] * W2[k*DH+n] + b2[n]
// block (32 n, 8 k-split), grid (DH/32, 3)
__global__ __launch_bounds__(256) void bias_comb_kernel(
    const float* __restrict__ b_tar, const float* __restrict__ b_ori,
    const float* __restrict__ W_ft, const float* __restrict__ W_fo,
    const float* __restrict__ W_fot,
    const float* __restrict__ b_ft, const float* __restrict__ b_fo,
    const float* __restrict__ b_fot)
{
    __shared__ float red[8][33];
    int z = blockIdx.y;
    int n = blockIdx.x * 32 + threadIdx.x;
    int ky = threadIdx.y;   // 0..7
    const float* b1 = (z == 0) ? b_tar : b_ori;
    const float* W2 = (z == 0) ? W_ft : (z == 1) ? W_fo : W_fot;
    const float* b2 = (z == 0) ? b_ft : (z == 1) ? b_fo : b_fot;
    float s = 0.f;
    #pragma unroll 4
    for (int k = ky; k < DH; k += 8)
        s += b1[k] * W2[(size_t)k * DH + n];
    red[ky][threadIdx.x] = s;
    __syncthreads();
    if (ky == 0) {
        float tot = 0.f;
        #pragma unroll
        for (int j = 0; j < 8; j++) tot += red[j][threadIdx.x];
        g_bc[z][n] = tot + b2[n];
    }
}

// ------- batched transpose+scale+split: vt[b][h][o] = otp[b][o][h]*v[b][o] ---
__global__ void vtrans_split_kernel()
{
    __shared__ float t[32][33];
    int b = blockIdx.z;
    int h0 = blockIdx.x * 32, o0 = blockIdx.y * 32;
    int tx = threadIdx.x, ty = threadIdx.y;   // 32 x 8
    const float* src = g_otp + (size_t)b * LL * DH;
    #pragma unroll
    for (int i = ty; i < 32; i += 8)
        t[i][tx] = src[(size_t)(o0 + i) * DH + h0 + tx] * g_v[b * LL + o0 + i];
    __syncthreads();
    bf16* hb = g_vthi + (size_t)b * DH * LL;
    bf16* lb = g_vtlo + (size_t)b * DH * LL;
    #pragma unroll
    for (int i = ty; i < 32; i += 8) {
        float x = t[tx][i];
        bf16 h = __float2bfloat16(x);
        bf16 l = __float2bfloat16(x - __bfloat162float(h));
        hb[(size_t)(h0 + i) * LL + o0 + tx] = h;
        lb[(size_t)(h0 + i) * LL + o0 + tx] = l;
    }
}

// ================= small SIMT kernels ========================================
__device__ __forceinline__ float block_reduce_sum_256(float val, float* red) {
    int tid = threadIdx.x;
    #pragma unroll
    for (int o = 16; o > 0; o >>= 1) val += __shfl_down_sync(0xffffffffu, val, o);
    if ((tid & 31) == 0) red[tid >> 5] = val;
    __syncthreads();
    if (tid < 8) {
        val = red[tid];
        #pragma unroll
        for (int o = 4; o > 0; o >>= 1) val += __shfl_down_sync(0xffu, val, o);
        if (tid == 0) red[0] = val;
    }
    __syncthreads();
    float r = red[0];
    __syncthreads();
    return r;
}

// inv row norms: y==0 -> tar->itn, y==1 -> ofc->ifn (one launch)
__global__ __launch_bounds__(256) void invnorm2_kernel()
{
    __shared__ float red[8];
    int row = blockIdx.x;
    int which = blockIdx.y;
    const float* x = which ? g_ofc : g_tar;
    float* inv = which ? g_ifn : g_itn;
    const float* p = x + (size_t)row * DH;
    float s = 0.f;
    for (int c = threadIdx.x; c < DH; c += 256) { float v = p[c]; s += v * v; }
    float tot = block_reduce_sum_256(s, red);
    if (threadIdx.x == 0) inv[row] = 1.0f / fmaxf(sqrtf(tot), 1e-8f);
}

// u[b,t] = 1 / rowsum(Q)     (first Sinkhorn iteration: v = 1 exactly)
__global__ void rowmv_first_kernel()
{
    int t = blockIdx.x * 8 + threadIdx.y;
    int b = blockIdx.y;
    const float* row = g_Q + ((size_t)b * LL + t) * LL;
    float s = 0.f;
    for (int o = threadIdx.x; o < LL; o += 32) s += row[o];
    #pragma unroll
    for (int off = 16; off > 0; off >>= 1) s += __shfl_down_sync(0xffffffffu, s, off);
    if (threadIdx.x == 0) g_u[b * LL + t] = 1.0f / s;
}

__global__ void rowmv_kernel()
{
    int t = blockIdx.x * 8 + threadIdx.y;
    int b = blockIdx.y;
    const float* row = g_Q + ((size_t)b * LL + t) * LL;
    const float* vv = g_v + b * LL;
    float s = 0.f;
    for (int o = threadIdx.x; o < LL; o += 32) s += row[o] * vv[o];
    #pragma unroll
    for (int off = 16; off > 0; off >>= 1) s += __shfl_down_sync(0xffffffffu, s, off);
    if (threadIdx.x == 0) g_u[b * LL + t] = 1.0f / s;
}

__global__ void colmv_kernel()
{
    __shared__ float red[8][32];
    int o = blockIdx.x * 32 + threadIdx.x;
    int b = blockIdx.y;
    const float* uu = g_u + b * LL;
    float s = 0.f;
    for (int t = threadIdx.y; t < LL; t += 8)
        s += g_Q[((size_t)b * LL + t) * LL + o] * uu[t];
    red[threadIdx.y][threadIdx.x] = s;
    __syncthreads();
    if (threadIdx.y == 0) {
        float tot = 0.f;
        #pragma unroll
        for (int j = 0; j < 8; j++) tot += red[j][threadIdx.x];
        g_v[b * LL + o] = 1.0f / tot;
    }
}

__global__ void rowscale_kernel()
{
    int t = blockIdx.x * 8 + threadIdx.y;
    int b = blockIdx.y;
    const float* row = g_Q + ((size_t)b * LL + t) * LL;
    const float* vv = g_v + b * LL;
    float s = 0.f;
    for (int o = threadIdx.x; o < LL; o += 32) {
        float q = row[o] * vv[o];
        s += q * q;
    }
    #pragma unroll
    for (int off = 16; off > 0; off >>= 1) s += __shfl_down_sync(0xffffffffu, s, off);
    if (threadIdx.x == 0) {
        float ut = g_u[b * LL + t];
        g_rs[b * LL + t] = ut / fmaxf(ut * sqrtf(s), 1e-12f);
    }
}

__global__ __launch_bounds__(256) void ln_kernel(
    const float* __restrict__ x, const float* __restrict__ g,
    const float* __restrict__ beta, float* __restrict__ y)
{
    __shared__ float buf[DH];
    __shared__ float red[8];
    int row = blockIdx.x;
    const float* p = x + (size_t)row * DH;
    float s = 0.f;
    for (int c = threadIdx.x; c < DH; c += 256) { float v = p[c]; buf[c] = v; s += v; }
    float mean = block_reduce_sum_256(s, red) * (1.0f / DH);
    float s2 = 0.f;
    for (int c = threadIdx.x; c < DH; c += 256) { float d = buf[c] - mean; s2 += d * d; }
    float var = block_reduce_sum_256(s2, red) * (1.0f / DH);
    float inv = rsqrtf(var + 1e-5f);
    for (int c = threadIdx.x; c < DH; c += 256)
        y[(size_t)row * DH + c] = (buf[c] - mean) * inv * g[c] + beta[c];
}

// ---------------- launch -----------------------------------------------------
extern "C" void kernel_launch(void* const* d_in, const int* in_sizes, int n_in,
                              void* d_out, int out_size)
{
    const float* origin = (const float*)d_in[0];
    const float* target = (const float*)d_in[1];
    const float* W_ori = (const float*)d_in[2];  const float* b_ori = (const float*)d_in[3];
    const float* W_tar = (const float*)d_in[4];  const float* b_tar = (const float*)d_in[5];
    const float* W_ft  = (const float*)d_in[6];  const float* b_ft  = (const float*)d_in[7];
    const float* W_fo  = (const float*)d_in[8];  const float* b_fo  = (const float*)d_in[9];
    const float* W_fot = (const float*)d_in[10]; const float* b_fot = (const float*)d_in[11];
    const float* ln_g  = (const float*)d_in[12]; const float* ln_b  = (const float*)d_in[13];
    float* out = (float*)d_out;

    bf16 *ohi, *olo, *thi, *tlo, *woris_hi, *woris_lo, *wtars_hi, *wtars_lo;
    float *obuf;
    cudaGetSymbolAddress((void**)&ohi,      g_ohi);
    cudaGetSymbolAddress((void**)&olo,      g_olo);
    cudaGetSymbolAddress((void**)&thi,      g_thi);
    cudaGetSymbolAddress((void**)&tlo,      g_tlo);
    cudaGetSymbolAddress((void**)&woris_hi, g_woris_hi);
    cudaGetSymbolAddress((void**)&woris_lo, g_woris_lo);
    cudaGetSymbolAddress((void**)&wtars_hi, g_wtars_hi);
    cudaGetSymbolAddress((void**)&wtars_lo, g_wtars_lo);
    cudaGetSymbolAddress((void**)&obuf,     g_obuf);

    const int NELEM = MTOT * DH;
    const int WELEM = (int)WSZ;

    cudaFuncSetAttribute(wgemm3_kernel,
                         cudaFuncAttributeMaxDynamicSharedMemorySize, TC_SMEM);
    cudaFuncSetAttribute(gemm3_tc_kernel,
                         cudaFuncAttributeMaxDynamicSharedMemorySize, TC_SMEM);
    cudaFuncSetAttribute(qgemm_tc_kernel,
                         cudaFuncAttributeMaxDynamicSharedMemorySize, TC_SMEM);
    cudaFuncSetAttribute(fgemm_tc_kernel,
                         cudaFuncAttributeMaxDynamicSharedMemorySize, TC_SMEM);

    dim3 blk(256);

    // activation splits (one launch) + plain weight splits (one launch)
    split2_kernel<<<dim3(NELEM / 4 / 256, 2), blk>>>(
        origin, ohi, olo, target, thi, tlo, NELEM);
    split2_kernel<<<dim3(WELEM / 4 / 256, 2), blk>>>(
        W_ori, woris_hi, woris_lo, W_tar, wtars_hi, wtars_lo, WELEM);

    // transposed splits of second-stage weights (one launch)
    trans_split3_kernel<<<dim3(32, 32, 3), dim3(32, 8)>>>(W_ft, W_fo, W_fot);

    // composite biases (split-k parallel)
    bias_comb_kernel<<<dim3(DH / 32, 3), dim3(32, 8)>>>(
        b_tar, b_ori, W_ft, W_fo, W_fot, b_ft, b_fo, b_fot);

    // composite weights: WcT[z] via tensor cores (192 CTAs)
    wgemm3_kernel<<<dim3(8, 8, 3), blk, TC_SMEM>>>();

    // fused 3 big GEMMs: tar / ofc / otp
    gemm3_tc_kernel<<<dim3(8, 64, 3), blk, TC_SMEM>>>();

    // row inverse norms (one launch, both arrays)
    invnorm2_kernel<<<dim3(MTOT, 2), blk>>>();

    // Q = exp(cos/0.05) with hi/lo split
    qgemm_tc_kernel<<<dim3(LL / 128, LL / 128, BB), blk, TC_SMEM>>>();

    // Sinkhorn: u = 1/(Qv), v = 1/(Q^T u), 5 iterations (first has v = 1)
    rowmv_first_kernel<<<dim3(LL / 8, BB), dim3(32, 8)>>>();
    colmv_kernel<<<dim3(LL / 32, BB), dim3(32, 8)>>>();
    for (int it = 0; it < 4; it++) {
        rowmv_kernel<<<dim3(LL / 8, BB), dim3(32, 8)>>>();
        colmv_kernel<<<dim3(LL / 32, BB), dim3(32, 8)>>>();
    }
    rowscale_kernel<<<dim3(LL / 8, BB), dim3(32, 8)>>>();

    // (v .* otp) transposed + split per batch
    vtrans_split_kernel<<<dim3(DH / 32, LL / 32, BB), dim3(32, 8)>>>();

    // out = rs_t * (Q @ vt^T) + tar
    fgemm_tc_kernel<<<dim3(DH / 128, LL / 128, BB), blk, TC_SMEM>>>();

    // LayerNorm
    ln_kernel<<<MTOT, blk>>>(obuf, ln_g, ln_b, out);
}

// round 15
// speedup vs baseline: 1.1164x; 1.0052x over previous
#include <cuda_runtime.h>
#include <cuda_bf16.h>
#include <math.h>
#include <stdint.h>

// Problem dims (fixed by the dataset)
#define BB   16
#define LL   512
#define DIN  1024
#define DH   1024
#define MTOT (BB * LL)   // 8192
#define WSZ  ((size_t)DH * DH)

typedef __nv_bfloat16 bf16;

// ---------------- scratch (static __device__: allocation-free) --------------
__device__ bf16 g_ohi [(size_t)MTOT * DH];
__device__ bf16 g_olo [(size_t)MTOT * DH];
__device__ bf16 g_thi [(size_t)MTOT * DH];
__device__ bf16 g_tlo [(size_t)MTOT * DH];
__device__ bf16 g_tarhi[(size_t)MTOT * DH];
__device__ bf16 g_tarlo[(size_t)MTOT * DH];
__device__ bf16 g_ofchi[(size_t)MTOT * DH];
__device__ bf16 g_ofclo[(size_t)MTOT * DH];
__device__ bf16 g_woris_hi[WSZ], g_woris_lo[WSZ];
__device__ bf16 g_wtars_hi[WSZ], g_wtars_lo[WSZ];
__device__ bf16 g_wftT_hi[WSZ],  g_wftT_lo[WSZ];
__device__ bf16 g_wfoT_hi[WSZ],  g_wfoT_lo[WSZ];
__device__ bf16 g_wfotT_hi[WSZ], g_wfotT_lo[WSZ];
__device__ bf16 g_wc_hi[3 * WSZ], g_wc_lo[3 * WSZ];
__device__ float g_bc[3][DH];
__device__ float g_bcp[3][4][DH];
__device__ bf16 g_Qhi [(size_t)BB * LL * LL];
__device__ bf16 g_Qlo [(size_t)BB * LL * LL];
__device__ bf16 g_vthi[(size_t)BB * DH * LL];
__device__ bf16 g_vtlo[(size_t)BB * DH * LL];
__device__ float g_tar  [(size_t)MTOT * DH];
__device__ float g_ofc  [(size_t)MTOT * DH];
__device__ float g_otp  [(size_t)MTOT * DH];
__device__ float g_obuf [(size_t)MTOT * DH];
__device__ float g_Q    [(size_t)BB * LL * LL];
__device__ float g_itn  [MTOT];
__device__ float g_ifn  [MTOT];
__device__ float g_u    [MTOT];
__device__ float g_v    [MTOT];
__device__ float g_rs   [MTOT];

// ================= portable tensor-core helpers (sm_80 PTX) ==================
__device__ __forceinline__ uint32_t smem_u32(const void* p) {
    uint32_t a;
    asm("{ .reg .u64 t; cvta.to.shared.u64 t, %1; cvt.u32.u64 %0, t; }"
        : "=r"(a) : "l"(p));
    return a;
}
__device__ __forceinline__ void cp16(uint32_t s, const void* g) {
    asm volatile("cp.async.cg.shared.global [%0], [%1], 16;"
                 :: "r"(s), "l"(g) : "memory");
}
#define CP_COMMIT() asm volatile("cp.async.commit_group;" ::: "memory")
#define CP_WAIT(n)  asm volatile("cp.async.wait_group %0;" :: "n"(n) : "memory")

__device__ __forceinline__ void ldmx4(uint32_t* r, uint32_t addr) {
    asm volatile("ldmatrix.sync.aligned.m8n8.x4.shared.b16 {%0,%1,%2,%3}, [%4];"
        : "=r"(r[0]), "=r"(r[1]), "=r"(r[2]), "=r"(r[3]) : "r"(addr));
}
__device__ __forceinline__ void mma_bf16(float* d, const uint32_t* a,
                                         uint32_t b0, uint32_t b1) {
    asm volatile(
        "mma.sync.aligned.m16n8k16.row.col.f32.bf16.bf16.f32 "
        "{%0,%1,%2,%3}, {%4,%5,%6,%7}, {%8,%9}, {%0,%1,%2,%3};"
        : "+f"(d[0]), "+f"(d[1]), "+f"(d[2]), "+f"(d[3])
        : "r"(a[0]), "r"(a[1]), "r"(a[2]), "r"(a[3]), "r"(b0), "r"(b1));
}

// ===== shared mainloop (round-8 proven): 3-term bf16-split, NT ==============
// 256 threads (8 warps), warp tile 64x32, K-chunk 32, 4-stage cp.async ring.
#define TCSTG 4
#define STAGE_BYTES 10240            // 128 rows * 80 B
#define TC_SMEM (2 * TCSTG * STAGE_BYTES)   // 81920

template<int KDIM>
__device__ __forceinline__ void tc_core(
    const bf16* __restrict__ Ahi, const bf16* __restrict__ Alo,
    const bf16* __restrict__ Bhi, const bf16* __restrict__ Blo,
    int m0, int n0, char* dsm, float acc[4][4][4])
{
    const int CPS = KDIM / 32;        // chunks per segment
    const int NCHc = 3 * CPS;
    int tid = threadIdx.x;
    int lane = tid & 31, wid = tid >> 5;
    int warp_m = wid >> 2, warp_n = wid & 3;
    int prow = tid >> 1, pc0 = (tid & 1) * 2;

    uint32_t base = smem_u32(dsm);
    uint32_t sA[TCSTG], sB[TCSTG];
    #pragma unroll
    for (int s = 0; s < TCSTG; s++) {
        sA[s] = base + s * STAGE_BYTES;
        sB[s] = base + TCSTG * STAGE_BYTES + s * STAGE_BYTES;
    }

#define TC_PREFETCH(kc, st) {                                                  \
        int seg = (kc) / CPS;                                                  \
        int ko = ((kc) % CPS) * 32;                                            \
        const bf16* Asrc = (seg == 2) ? Alo : Ahi;                             \
        const bf16* Bsrc = (seg == 1) ? Blo : Bhi;                             \
        const bf16* ag = Asrc + (size_t)(m0 + prow) * KDIM + ko + pc0 * 8;     \
        const bf16* bg = Bsrc + (size_t)(n0 + prow) * KDIM + ko + pc0 * 8;     \
        uint32_t sa = sA[st] + prow * 80 + pc0 * 16;                           \
        uint32_t sb = sB[st] + prow * 80 + pc0 * 16;                           \
        cp16(sa, ag); cp16(sa + 16, ag + 8);                                   \
        cp16(sb, bg); cp16(sb + 16, bg + 8);                                   \
        CP_COMMIT(); }

    int mat = lane >> 3, mr = lane & 7;
    uint32_t aoff = (uint32_t)((warp_m * 64 + (mat & 1) * 8 + mr) * 80
                               + ((mat >> 1) * 8) * 2);
    uint32_t boff = (uint32_t)((warp_n * 32 + (mat >> 1) * 8 + mr) * 80
                               + ((mat & 1) * 8) * 2);

    #pragma unroll
    for (int mi = 0; mi < 4; mi++)
        #pragma unroll
        for (int ni = 0; ni < 4; ni++)
            #pragma unroll
            for (int e = 0; e < 4; e++) acc[mi][ni][e] = 0.f;

    TC_PREFETCH(0, 0)
    TC_PREFETCH(1, 1)
    TC_PREFETCH(2, 2)

    for (int kc = 0; kc < NCHc; kc++) {
        CP_WAIT(TCSTG - 2);
        __syncthreads();
        int pkc = kc + TCSTG - 1;
        if (pkc < NCHc) { TC_PREFETCH(pkc, pkc & (TCSTG - 1)) }
        else { CP_COMMIT(); }
        int b = kc & (TCSTG - 1);
        #pragma unroll
        for (int ks = 0; ks < 32; ks += 16) {
            uint32_t afr[4][4];
            #pragma unroll
            for (int mi = 0; mi < 4; mi++)
                ldmx4(afr[mi], sA[b] + aoff + mi * (16 * 80) + ks * 2);
            uint32_t bfr[2][4];
            #pragma unroll
            for (int np = 0; np < 2; np++)
                ldmx4(bfr[np], sB[b] + boff + np * (16 * 80) + ks * 2);
            #pragma unroll
            for (int mi = 0; mi < 4; mi++)
                #pragma unroll
                for (int ni = 0; ni < 4; ni++)
                    mma_bf16(acc[mi][ni], afr[mi],
                             bfr[ni >> 1][(ni & 1) * 2],
                             bfr[ni >> 1][(ni & 1) * 2 + 1]);
        }
    }
#undef TC_PREFETCH
}

// --------- epilogue helper: write fp32 / bf16 hi-lo from acc -----------------
__device__ __forceinline__ void tc_epilogue(
    float acc[4][4][4], int m0, int n0, const float* bias,
    float* outF, bf16* outHi, bf16* outLo)
{
    int lane = threadIdx.x & 31, wid = threadIdx.x >> 5;
    int warp_m = wid >> 2, warp_n = wid & 3;
    int gid = lane >> 2, tig = lane & 3;
    #pragma unroll
    for (int ni = 0; ni < 4; ni++) {
        int cn = n0 + warp_n * 32 + ni * 8 + tig * 2;
        float bz0 = bias ? bias[cn] : 0.f;
        float bz1 = bias ? bias[cn + 1] : 0.f;
        #pragma unroll
        for (int mi = 0; mi < 4; mi++) {
            int rm = m0 + warp_m * 64 + mi * 16 + gid;
            float c0 = acc[mi][ni][0] + bz0, c1 = acc[mi][ni][1] + bz1;
            float c2 = acc[mi][ni][2] + bz0, c3 = acc[mi][ni][3] + bz1;
            if (outF) {
                *(float2*)&outF[(size_t)rm * DH + cn]       = make_float2(c0, c1);
                *(float2*)&outF[(size_t)(rm + 8) * DH + cn] = make_float2(c2, c3);
            }
            if (outHi) {
                bf16 h0 = __float2bfloat16(c0), h1 = __float2bfloat16(c1);
                bf16 h2 = __float2bfloat16(c2), h3 = __float2bfloat16(c3);
                __nv_bfloat162 hp0; hp0.x = h0; hp0.y = h1;
                __nv_bfloat162 hp1; hp1.x = h2; hp1.y = h3;
                __nv_bfloat162 lp0;
                lp0.x = __float2bfloat16(c0 - __bfloat162float(h0));
                lp0.y = __float2bfloat16(c1 - __bfloat162float(h1));
                __nv_bfloat162 lp1;
                lp1.x = __float2bfloat16(c2 - __bfloat162float(h2));
                lp1.y = __float2bfloat16(c3 - __bfloat162float(h3));
                *(__nv_bfloat162*)&outHi[(size_t)rm * DH + cn]       = hp0;
                *(__nv_bfloat162*)&outHi[(size_t)(rm + 8) * DH + cn] = hp1;
                *(__nv_bfloat162*)&outLo[(size_t)rm * DH + cn]       = lp0;
                *(__nv_bfloat162*)&outLo[(size_t)(rm + 8) * DH + cn] = lp1;
            }
        }
    }
}

// --------- composite-weight GEMMs: WcT[z] = (Wz2^T) @ (Wz1)^T ---------------
__global__ __launch_bounds__(256) void wgemm3_kernel()
{
    extern __shared__ char dsm[];
    int z = blockIdx.z;
    int m0 = blockIdx.y * 128, n0 = blockIdx.x * 128;
    const bf16 *Ah, *Al, *Bh, *Bl;
    if (z == 0)      { Ah = g_wftT_hi;  Al = g_wftT_lo;  Bh = g_wtars_hi; Bl = g_wtars_lo; }
    else if (z == 1) { Ah = g_wfoT_hi;  Al = g_wfoT_lo;  Bh = g_woris_hi; Bl = g_woris_lo; }
    else             { Ah = g_wfotT_hi; Al = g_wfotT_lo; Bh = g_woris_hi; Bl = g_woris_lo; }
    float acc[4][4][4];
    tc_core<1024>(Ah, Al, Bh, Bl, m0, n0, dsm, acc);
    tc_epilogue(acc, m0, n0, nullptr, nullptr,
                g_wc_hi + (size_t)z * WSZ, g_wc_lo + (size_t)z * WSZ);
}

// --------- fused 3 big GEMMs -------------------------------------------------
// z=0: tar (fp32 + hi/lo)  z=1: ofc (fp32 + hi/lo)  z=2: otp (fp32)
__global__ __launch_bounds__(256) void gemm3_tc_kernel()
{
    extern __shared__ char dsm[];
    int z = blockIdx.z;
    int m0 = blockIdx.y * 128, n0 = blockIdx.x * 128;
    const bf16 *Ah, *Al;
    float* outF;
    bf16 *oH, *oL;
    if (z == 0)      { Ah = g_thi; Al = g_tlo; outF = g_tar; oH = g_tarhi; oL = g_tarlo; }
    else if (z == 1) { Ah = g_ohi; Al = g_olo; outF = g_ofc; oH = g_ofchi; oL = g_ofclo; }
    else             { Ah = g_ohi; Al = g_olo; outF = g_otp; oH = nullptr; oL = nullptr; }
    const bf16* Bh = g_wc_hi + (size_t)z * WSZ;
    const bf16* Bl = g_wc_lo + (size_t)z * WSZ;
    float acc[4][4][4];
    tc_core<1024>(Ah, Al, Bh, Bl, m0, n0, dsm, acc);
    tc_epilogue(acc, m0, n0, g_bc[z], outF, oH, oL);
}

// ---------------- Q-GEMM (NT, batched): Q = exp(20*cos) + hi/lo split --------
__global__ __launch_bounds__(256) void qgemm_tc_kernel()
{
    extern __shared__ char dsm[];
    int b = blockIdx.z;
    int m0 = blockIdx.y * 128, n0 = blockIdx.x * 128;
    const bf16* Ah = g_tarhi + (size_t)b * LL * DH;
    const bf16* Al = g_tarlo + (size_t)b * LL * DH;
    const bf16* Bh = g_ofchi + (size_t)b * LL * DH;
    const bf16* Bl = g_ofclo + (size_t)b * LL * DH;
    float acc[4][4][4];
    tc_core<1024>(Ah, Al, Bh, Bl, m0, n0, dsm, acc);

    int lane = threadIdx.x & 31, wid = threadIdx.x >> 5;
    int warp_m = wid >> 2, warp_n = wid & 3;
    int gid = lane >> 2, tig = lane & 3;
    #pragma unroll
    for (int ni = 0; ni < 4; ni++) {
        int cn = n0 + warp_n * 32 + ni * 8 + tig * 2;
        float f0 = g_ifn[b * LL + cn], f1 = g_ifn[b * LL + cn + 1];
        #pragma unroll
        for (int mi = 0; mi < 4; mi++) {
            int rm = m0 + warp_m * 64 + mi * 16 + gid;
            float s0 = g_itn[b * LL + rm] * 20.0f;
            float s1 = g_itn[b * LL + rm + 8] * 20.0f;
            float c0 = expf(acc[mi][ni][0] * s0 * f0);
            float c1 = expf(acc[mi][ni][1] * s0 * f1);
            float c2 = expf(acc[mi][ni][2] * s1 * f0);
            float c3 = expf(acc[mi][ni][3] * s1 * f1);
            size_t r0 = ((size_t)b * LL + rm) * LL + cn;
            size_t r1 = ((size_t)b * LL + rm + 8) * LL + cn;
            *(float2*)&g_Q[r0] = make_float2(c0, c1);
            *(float2*)&g_Q[r1] = make_float2(c2, c3);
            bf16 h0 = __float2bfloat16(c0), h1 = __float2bfloat16(c1);
            bf16 h2 = __float2bfloat16(c2), h3 = __float2bfloat16(c3);
            __nv_bfloat162 hp0; hp0.x = h0; hp0.y = h1;
            __nv_bfloat162 hp1; hp1.x = h2; hp1.y = h3;
            __nv_bfloat162 lp0;
            lp0.x = __float2bfloat16(c0 - __bfloat162float(h0));
            lp0.y = __float2bfloat16(c1 - __bfloat162float(h1));
            __nv_bfloat162 lp1;
            lp1.x = __float2bfloat16(c2 - __bfloat162float(h2));
            lp1.y = __float2bfloat16(c3 - __bfloat162float(h3));
            *(__nv_bfloat162*)&g_Qhi[r0] = hp0;
            *(__nv_bfloat162*)&g_Qhi[r1] = hp1;
            *(__nv_bfloat162*)&g_Qlo[r0] = lp0;
            *(__nv_bfloat162*)&g_Qlo[r1] = lp1;
        }
    }
}

// ---------------- Final GEMM (NT, batched): out = rs*(Q @ votp^T) + tar ------
__global__ __launch_bounds__(256) void fgemm_tc_kernel()
{
    extern __shared__ char dsm[];
    int b = blockIdx.z;
    int m0 = blockIdx.y * 128, n0 = blockIdx.x * 128;
    const bf16* Ah = g_Qhi + (size_t)b * LL * LL;
    const bf16* Al = g_Qlo + (size_t)b * LL * LL;
    const bf16* Bh = g_vthi + (size_t)b * DH * LL;
    const bf16* Bl = g_vtlo + (size_t)b * DH * LL;
    float acc[4][4][4];
    tc_core<512>(Ah, Al, Bh, Bl, m0, n0, dsm, acc);

    int lane = threadIdx.x & 31, wid = threadIdx.x >> 5;
    int warp_m = wid >> 2, warp_n = wid & 3;
    int gid = lane >> 2, tig = lane & 3;
    #pragma unroll
    for (int ni = 0; ni < 4; ni++) {
        int cn = n0 + warp_n * 32 + ni * 8 + tig * 2;
        #pragma unroll
        for (int mi = 0; mi < 4; mi++) {
            int rm = m0 + warp_m * 64 + mi * 16 + gid;
            int g0 = b * LL + rm, g1 = b * LL + rm + 8;
            float r0 = g_rs[g0], r1 = g_rs[g1];
            float2 t0 = *(const float2*)&g_tar[(size_t)g0 * DH + cn];
            float2 t1 = *(const float2*)&g_tar[(size_t)g1 * DH + cn];
            float2 o0 = make_float2(r0 * acc[mi][ni][0] + t0.x,
                                    r0 * acc[mi][ni][1] + t0.y);
            float2 o1 = make_float2(r1 * acc[mi][ni][2] + t1.x,
                                    r1 * acc[mi][ni][3] + t1.y);
            *(float2*)&g_obuf[(size_t)g0 * DH + cn] = o0;
            *(float2*)&g_obuf[(size_t)g1 * DH + cn] = o1;
        }
    }
}

// ---------------- fp32 -> bf16 hi/lo split (paired launches) -----------------
__global__ __launch_bounds__(256) void split2_kernel(
    const float* __restrict__ x0, bf16* __restrict__ hi0, bf16* __restrict__ lo0,
    const float* __restrict__ x1, bf16* __restrict__ hi1, bf16* __restrict__ lo1,
    int n)
{
    const float* x = blockIdx.y ? x1 : x0;
    bf16* hi = blockIdx.y ? hi1 : hi0;
    bf16* lo = blockIdx.y ? lo1 : lo0;
    int i = (blockIdx.x * 256 + threadIdx.x) * 4;
    if (i >= n) return;
    float4 v = *(const float4*)(x + i);
    bf16 h0 = __float2bfloat16(v.x), h1 = __float2bfloat16(v.y);
    bf16 h2 = __float2bfloat16(v.z), h3 = __float2bfloat16(v.w);
    __nv_bfloat162 hp0; hp0.x = h0; hp0.y = h1;
    __nv_bfloat162 hp1; hp1.x = h2; hp1.y = h3;
    __nv_bfloat162 lp0;
    lp0.x = __float2bfloat16(v.x - __bfloat162float(h0));
    lp0.y = __float2bfloat16(v.y - __bfloat162float(h1));
    __nv_bfloat162 lp1;
    lp1.x = __float2bfloat16(v.z - __bfloat162float(h2));
    lp1.y = __float2bfloat16(v.w - __bfloat162float(h3));
    *(__nv_bfloat162*)&hi[i]     = hp0;
    *(__nv_bfloat162*)&hi[i + 2] = hp1;
    *(__nv_bfloat162*)&lo[i]     = lp0;
    *(__nv_bfloat162*)&lo[i + 2] = lp1;
}

// ------- weight transpose + split (3 weights in one launch, grid.z) ----------
__global__ void trans_split3_kernel(
    const float* __restrict__ W0, const float* __restrict__ W1,
    const float* __restrict__ W2)
{
    __shared__ float t[32][33];
    int z = blockIdx.z;
    const float* W = (z == 0) ? W0 : (z == 1) ? W1 : W2;
    bf16* hiT = (z == 0) ? g_wftT_hi : (z == 1) ? g_wfoT_hi : g_wfotT_hi;
    bf16* loT = (z == 0) ? g_wftT_lo : (z == 1) ? g_wfoT_lo : g_wfotT_lo;
    int n0 = blockIdx.x * 32, k0 = blockIdx.y * 32;
    int tx = threadIdx.x, ty = threadIdx.y;   // 32 x 8
    #pragma unroll
    for (int i = ty; i < 32; i += 8)
        t[i][tx] = W[(size_t)(k0 + i) * DH + n0 + tx];
    __syncthreads();
    #pragma unroll
    for (int i = ty; i < 32; i += 8) {
        float v = t[tx][i];
        bf16 h = __float2bfloat16(v);
        bf16 l = __float2bfloat16(v - __bfloat162float(h));
        hiT[(size_t)(n0 + i) * DH + k0 + tx] = h;
        loT[(size_t)(n0 + i) * DH + k0 + tx] = l;
    }
}

// ---------------- composite biases, phase 1: partial split-k sums ------------
// g_bcp[z][ks][n] = sum_{k in [ks*256,(ks+1)*256)} b1[k] * W2[k*DH+n]
// grid (DH/32, 4, 3), block (32 n, 8 k)
__global__ __launch_bounds__(256) void bias_comb_p1_kernel(
    const float* __restrict__ b_tar, const float* __restrict__ b_ori,
    const float* __restrict__ W_ft, const float* __restrict__ W_fo,
    const float* __restrict__ W_fot)
{
    __shared__ float red[8][33];
    int z = blockIdx.z;
    int ks = blockIdx.y;
    int n = blockIdx.x * 32 + threadIdx.x;
    int ky = threadIdx.y;   // 0..7
    const float* b1 = (z == 0) ? b_tar : b_ori;
    const float* W2 = (z == 0) ? W_ft : (z == 1) ? W_fo : W_fot;
    int k0 = ks * 256;
    float s = 0.f;
    #pragma unroll 4
    for (int k = k0 + ky; k < k0 + 256; k += 8)
        s += b1[k] * W2[(size_t)k * DH + n];
    red[ky][threadIdx.x] = s;
    __syncthreads();
    if (ky == 0) {
        float tot = 0.f;
        #pragma unroll
        for (int j = 0; j < 8; j++) tot += red[j][threadIdx.x];
        g_bcp[z][ks][n] = tot;
    }
}

// ---------------- composite biases, phase 2: reduce + add b2 -----------------
__global__ void bias_comb_p2_kernel(
    const float* __restrict__ b_ft, const float* __restrict__ b_fo,
    const float* __restrict__ b_fot)
{
    int z = blockIdx.y;
    int n = blockIdx.x * 256 + threadIdx.x;
    const float* b2 = (z == 0) ? b_ft : (z == 1) ? b_fo : b_fot;
    float s = g_bcp[z][0][n] + g_bcp[z][1][n] + g_bcp[z][2][n] + g_bcp[z][3][n];
    g_bc[z][n] = s + b2[n];
}

// ------- batched transpose+scale+split: vt[b][h][o] = otp[b][o][h]*v[b][o] ---
__global__ void vtrans_split_kernel()
{
    __shared__ float t[32][33];
    int b = blockIdx.z;
    int h0 = blockIdx.x * 32, o0 = blockIdx.y * 32;
    int tx = threadIdx.x, ty = threadIdx.y;   // 32 x 8
    const float* src = g_otp + (size_t)b * LL * DH;
    #pragma unroll
    for (int i = ty; i < 32; i += 8)
        t[i][tx] = src[(size_t)(o0 + i) * DH + h0 + tx] * g_v[b * LL + o0 + i];
    __syncthreads();
    bf16* hb = g_vthi + (size_t)b * DH * LL;
    bf16* lb = g_vtlo + (size_t)b * DH * LL;
    #pragma unroll
    for (int i = ty; i < 32; i += 8) {
        float x = t[tx][i];
        bf16 h = __float2bfloat16(x);
        bf16 l = __float2bfloat16(x - __bfloat162float(h));
        hb[(size_t)(h0 + i) * LL + o0 + tx] = h;
        lb[(size_t)(h0 + i) * LL + o0 + tx] = l;
    }
}

// ================= small SIMT kernels ========================================
__device__ __forceinline__ float block_reduce_sum_256(float val, float* red) {
    int tid = threadIdx.x;
    #pragma unroll
    for (int o = 16; o > 0; o >>= 1) val += __shfl_down_sync(0xffffffffu, val, o);
    if ((tid & 31) == 0) red[tid >> 5] = val;
    __syncthreads();
    if (tid < 8) {
        val = red[tid];
        #pragma unroll
        for (int o = 4; o > 0; o >>= 1) val += __shfl_down_sync(0xffu, val, o);
        if (tid == 0) red[0] = val;
    }
    __syncthreads();
    float r = red[0];
    __syncthreads();
    return r;
}

// inv row norms: y==0 -> tar->itn, y==1 -> ofc->ifn (one launch)
__global__ __launch_bounds__(256) void invnorm2_kernel()
{
    __shared__ float red[8];
    int row = blockIdx.x;
    int which = blockIdx.y;
    const float* x = which ? g_ofc : g_tar;
    float* inv = which ? g_ifn : g_itn;
    const float* p = x + (size_t)row * DH;
    float s = 0.f;
    for (int c = threadIdx.x; c < DH; c += 256) { float v = p[c]; s += v * v; }
    float tot = block_reduce_sum_256(s, red);
    if (threadIdx.x == 0) inv[row] = 1.0f / fmaxf(sqrtf(tot), 1e-8f);
}

// u[b,t] = 1 / rowsum(Q)     (first Sinkhorn iteration: v = 1 exactly)
__global__ void rowmv_first_kernel()
{
    int t = blockIdx.x * 8 + threadIdx.y;
    int b = blockIdx.y;
    const float* row = g_Q + ((size_t)b * LL + t) * LL;
    float s = 0.f;
    for (int o = threadIdx.x; o < LL; o += 32) s += row[o];
    #pragma unroll
    for (int off = 16; off > 0; off >>= 1) s += __shfl_down_sync(0xffffffffu, s, off);
    if (threadIdx.x == 0) g_u[b * LL + t] = 1.0f / s;
}

__global__ void rowmv_kernel()
{
    int t = blockIdx.x * 8 + threadIdx.y;
    int b = blockIdx.y;
    const float* row = g_Q + ((size_t)b * LL + t) * LL;
    const float* vv = g_v + b * LL;
    float s = 0.f;
    for (int o = threadIdx.x; o < LL; o += 32) s += row[o] * vv[o];
    #pragma unroll
    for (int off = 16; off > 0; off >>= 1) s += __shfl_down_sync(0xffffffffu, s, off);
    if (threadIdx.x == 0) g_u[b * LL + t] = 1.0f / s;
}

__global__ void colmv_kernel()
{
    __shared__ float red[8][32];
    int o = blockIdx.x * 32 + threadIdx.x;
    int b = blockIdx.y;
    const float* uu = g_u + b * LL;
    float s = 0.f;
    for (int t = threadIdx.y; t < LL; t += 8)
        s += g_Q[((size_t)b * LL + t) * LL + o] * uu[t];
    red[threadIdx.y][threadIdx.x] = s;
    __syncthreads();
    if (threadIdx.y == 0) {
        float tot = 0.f;
        #pragma unroll
        for (int j = 0; j < 8; j++) tot += red[j][threadIdx.x];
        g_v[b * LL + o] = 1.0f / tot;
    }
}

__global__ void rowscale_kernel()
{
    int t = blockIdx.x * 8 + threadIdx.y;
    int b = blockIdx.y;
    const float* row = g_Q + ((size_t)b * LL + t) * LL;
    const float* vv = g_v + b * LL;
    float s = 0.f;
    for (int o = threadIdx.x; o < LL; o += 32) {
        float q = row[o] * vv[o];
        s += q * q;
    }
    #pragma unroll
    for (int off = 16; off > 0; off >>= 1) s += __shfl_down_sync(0xffffffffu, s, off);
    if (threadIdx.x == 0) {
        float ut = g_u[b * LL + t];
        g_rs[b * LL + t] = ut / fmaxf(ut * sqrtf(s), 1e-12f);
    }
}

__global__ __launch_bounds__(256) void ln_kernel(
    const float* __restrict__ x, const float* __restrict__ g,
    const float* __restrict__ beta, float* __restrict__ y)
{
    __shared__ float buf[DH];
    __shared__ float red[8];
    int row = blockIdx.x;
    const float* p = x + (size_t)row * DH;
    float s = 0.f;
    for (int c = threadIdx.x; c < DH; c += 256) { float v = p[c]; buf[c] = v; s += v; }
    float mean = block_reduce_sum_256(s, red) * (1.0f / DH);
    float s2 = 0.f;
    for (int c = threadIdx.x; c < DH; c += 256) { float d = buf[c] - mean; s2 += d * d; }
    float var = block_reduce_sum_256(s2, red) * (1.0f / DH);
    float inv = rsqrtf(var + 1e-5f);
    for (int c = threadIdx.x; c < DH; c += 256)
        y[(size_t)row * DH + c] = (buf[c] - mean) * inv * g[c] + beta[c];
}

// ---------------- launch -----------------------------------------------------
extern "C" void kernel_launch(void* const* d_in, const int* in_sizes, int n_in,
                              void* d_out, int out_size)
{
    const float* origin = (const float*)d_in[0];
    const float* target = (const float*)d_in[1];
    const float* W_ori = (const float*)d_in[2];  const float* b_ori = (const float*)d_in[3];
    const float* W_tar = (const float*)d_in[4];  const float* b_tar = (const float*)d_in[5];
    const float* W_ft  = (const float*)d_in[6];  const float* b_ft  = (const float*)d_in[7];
    const float* W_fo  = (const float*)d_in[8];  const float* b_fo  = (const float*)d_in[9];
    const float* W_fot = (const float*)d_in[10]; const float* b_fot = (const float*)d_in[11];
    const float* ln_g  = (const float*)d_in[12]; const float* ln_b  = (const float*)d_in[13];
    float* out = (float*)d_out;

    bf16 *ohi, *olo, *thi, *tlo, *woris_hi, *woris_lo, *wtars_hi, *wtars_lo;
    float *obuf;
    cudaGetSymbolAddress((void**)&ohi,      g_ohi);
    cudaGetSymbolAddress((void**)&olo,      g_olo);
    cudaGetSymbolAddress((void**)&thi,      g_thi);
    cudaGetSymbolAddress((void**)&tlo,      g_tlo);
    cudaGetSymbolAddress((void**)&woris_hi, g_woris_hi);
    cudaGetSymbolAddress((void**)&woris_lo, g_woris_lo);
    cudaGetSymbolAddress((void**)&wtars_hi, g_wtars_hi);
    cudaGetSymbolAddress((void**)&wtars_lo, g_wtars_lo);
    cudaGetSymbolAddress((void**)&obuf,     g_obuf);

    const int NELEM = MTOT * DH;
    const int WELEM = (int)WSZ;

    cudaFuncSetAttribute(wgemm3_kernel,
                         cudaFuncAttributeMaxDynamicSharedMemorySize, TC_SMEM);
    cudaFuncSetAttribute(gemm3_tc_kernel,
                         cudaFuncAttributeMaxDynamicSharedMemorySize, TC_SMEM);
    cudaFuncSetAttribute(qgemm_tc_kernel,
                         cudaFuncAttributeMaxDynamicSharedMemorySize, TC_SMEM);
    cudaFuncSetAttribute(fgemm_tc_kernel,
                         cudaFuncAttributeMaxDynamicSharedMemorySize, TC_SMEM);

    dim3 blk(256);

    // activation splits (one launch) + plain weight splits (one launch)
    split2_kernel<<<dim3(NELEM / 4 / 256, 2), blk>>>(
        origin, ohi, olo, target, thi, tlo, NELEM);
    split2_kernel<<<dim3(WELEM / 4 / 256, 2), blk>>>(
        W_ori, woris_hi, woris_lo, W_tar, wtars_hi, wtars_lo, WELEM);

    // transposed splits of second-stage weights (one launch)
    trans_split3_kernel<<<dim3(32, 32, 3), dim3(32, 8)>>>(W_ft, W_fo, W_fot);

    // composite biases (two-phase split-k, 384 blocks)
    bias_comb_p1_kernel<<<dim3(DH / 32, 4, 3), dim3(32, 8)>>>(
        b_tar, b_ori, W_ft, W_fo, W_fot);
    bias_comb_p2_kernel<<<dim3(DH / 256, 3), blk>>>(b_ft, b_fo, b_fot);

    // composite weights: WcT[z] via tensor cores (192 CTAs)
    wgemm3_kernel<<<dim3(8, 8, 3), blk, TC_SMEM>>>();

    // fused 3 big GEMMs: tar / ofc / otp
    gemm3_tc_kernel<<<dim3(8, 64, 3), blk, TC_SMEM>>>();

    // row inverse norms (one launch, both arrays)
    invnorm2_kernel<<<dim3(MTOT, 2), blk>>>();

    // Q = exp(cos/0.05) with hi/lo split
    qgemm_tc_kernel<<<dim3(LL / 128, LL / 128, BB), blk, TC_SMEM>>>();

    // Sinkhorn: u = 1/(Qv), v = 1/(Q^T u), 5 iterations (first has v = 1)
    rowmv_first_kernel<<<dim3(LL / 8, BB), dim3(32, 8)>>>();
    colmv_kernel<<<dim3(LL / 32, BB), dim3(32, 8)>>>();
    for (int it = 0; it < 4; it++) {
        rowmv_kernel<<<dim3(LL / 8, BB), dim3(32, 8)>>>();
        colmv_kernel<<<dim3(LL / 32, BB), dim3(32, 8)>>>();
    }
    rowscale_kernel<<<dim3(LL / 8, BB), dim3(32, 8)>>>();

    // (v .* otp) transposed + split per batch
    vtrans_split_kernel<<<dim3(DH / 32, LL / 32, BB), dim3(32, 8)>>>();

    // out = rs_t * (Q @ vt^T) + tar
    fgemm_tc_kernel<<<dim3(DH / 128, LL / 128, BB), blk, TC_SMEM>>>();

    // LayerNorm
    ln_kernel<<<MTOT, blk>>>(obuf, ln_g, ln_b, out);
}

// round 16
// speedup vs baseline: 1.1241x; 1.0069x over previous
#include <cuda_runtime.h>
#include <cuda_bf16.h>
#include <math.h>
#include <stdint.h>

// Problem dims (fixed by the dataset)
#define BB   16
#define LL   512
#define DIN  1024
#define DH   1024
#define MTOT (BB * LL)   // 8192
#define WSZ  ((size_t)DH * DH)

typedef __nv_bfloat16 bf16;

// ---------------- scratch (static __device__: allocation-free) --------------
__device__ bf16 g_ohi [(size_t)MTOT * DH];
__device__ bf16 g_olo [(size_t)MTOT * DH];
__device__ bf16 g_thi [(size_t)MTOT * DH];
__device__ bf16 g_tlo [(size_t)MTOT * DH];
__device__ bf16 g_tarhi[(size_t)MTOT * DH];
__device__ bf16 g_tarlo[(size_t)MTOT * DH];
__device__ bf16 g_ofchi[(size_t)MTOT * DH];
__device__ bf16 g_ofclo[(size_t)MTOT * DH];
__device__ bf16 g_woris_hi[WSZ], g_woris_lo[WSZ];
__device__ bf16 g_wtars_hi[WSZ], g_wtars_lo[WSZ];
__device__ bf16 g_wftT_hi[WSZ],  g_wftT_lo[WSZ];
__device__ bf16 g_wfoT_hi[WSZ],  g_wfoT_lo[WSZ];
__device__ bf16 g_wfotT_hi[WSZ], g_wfotT_lo[WSZ];
__device__ bf16 g_wc_hi[3 * WSZ], g_wc_lo[3 * WSZ];
__device__ float g_bc[3][DH];
__device__ float g_bcp[3][4][DH];
__device__ bf16 g_Qhi [(size_t)BB * LL * LL];
__device__ bf16 g_Qlo [(size_t)BB * LL * LL];
__device__ bf16 g_vthi[(size_t)BB * DH * LL];
__device__ bf16 g_vtlo[(size_t)BB * DH * LL];
__device__ float g_tar  [(size_t)MTOT * DH];
__device__ float g_ofc  [(size_t)MTOT * DH];
__device__ float g_otp  [(size_t)MTOT * DH];
__device__ float g_obuf [(size_t)MTOT * DH];
__device__ float g_itn  [MTOT];
__device__ float g_ifn  [MTOT];
__device__ float g_u    [MTOT];
__device__ float g_v    [MTOT];
__device__ float g_rs   [MTOT];

// ================= portable tensor-core helpers (sm_80 PTX) ==================
__device__ __forceinline__ uint32_t smem_u32(const void* p) {
    uint32_t a;
    asm("{ .reg .u64 t; cvta.to.shared.u64 t, %1; cvt.u32.u64 %0, t; }"
        : "=r"(a) : "l"(p));
    return a;
}
__device__ __forceinline__ void cp16(uint32_t s, const void* g) {
    asm volatile("cp.async.cg.shared.global [%0], [%1], 16;"
                 :: "r"(s), "l"(g) : "memory");
}
#define CP_COMMIT() asm volatile("cp.async.commit_group;" ::: "memory")
#define CP_WAIT(n)  asm volatile("cp.async.wait_group %0;" :: "n"(n) : "memory")

__device__ __forceinline__ void ldmx4(uint32_t* r, uint32_t addr) {
    asm volatile("ldmatrix.sync.aligned.m8n8.x4.shared.b16 {%0,%1,%2,%3}, [%4];"
        : "=r"(r[0]), "=r"(r[1]), "=r"(r[2]), "=r"(r[3]) : "r"(addr));
}
__device__ __forceinline__ void mma_bf16(float* d, const uint32_t* a,
                                         uint32_t b0, uint32_t b1) {
    asm volatile(
        "mma.sync.aligned.m16n8k16.row.col.f32.bf16.bf16.f32 "
        "{%0,%1,%2,%3}, {%4,%5,%6,%7}, {%8,%9}, {%0,%1,%2,%3};"
        : "+f"(d[0]), "+f"(d[1]), "+f"(d[2]), "+f"(d[3])
        : "r"(a[0]), "r"(a[1]), "r"(a[2]), "r"(a[3]), "r"(b0), "r"(b1));
}

// ===== shared mainloop (round-8 proven): 3-term bf16-split, NT ==============
// 256 threads (8 warps), warp tile 64x32, K-chunk 32, 4-stage cp.async ring.
#define TCSTG 4
#define STAGE_BYTES 10240            // 128 rows * 80 B
#define TC_SMEM (2 * TCSTG * STAGE_BYTES)   // 81920

template<int KDIM>
__device__ __forceinline__ void tc_core(
    const bf16* __restrict__ Ahi, const bf16* __restrict__ Alo,
    const bf16* __restrict__ Bhi, const bf16* __restrict__ Blo,
    int m0, int n0, char* dsm, float acc[4][4][4])
{
    const int CPS = KDIM / 32;        // chunks per segment
    const int NCHc = 3 * CPS;
    int tid = threadIdx.x;
    int lane = tid & 31, wid = tid >> 5;
    int warp_m = wid >> 2, warp_n = wid & 3;
    int prow = tid >> 1, pc0 = (tid & 1) * 2;

    uint32_t base = smem_u32(dsm);
    uint32_t sA[TCSTG], sB[TCSTG];
    #pragma unroll
    for (int s = 0; s < TCSTG; s++) {
        sA[s] = base + s * STAGE_BYTES;
        sB[s] = base + TCSTG * STAGE_BYTES + s * STAGE_BYTES;
    }

#define TC_PREFETCH(kc, st) {                                                  \
        int seg = (kc) / CPS;                                                  \
        int ko = ((kc) % CPS) * 32;                                            \
        const bf16* Asrc = (seg == 2) ? Alo : Ahi;                             \
        const bf16* Bsrc = (seg == 1) ? Blo : Bhi;                             \
        const bf16* ag = Asrc + (size_t)(m0 + prow) * KDIM + ko + pc0 * 8;     \
        const bf16* bg = Bsrc + (size_t)(n0 + prow) * KDIM + ko + pc0 * 8;     \
        uint32_t sa = sA[st] + prow * 80 + pc0 * 16;                           \
        uint32_t sb = sB[st] + prow * 80 + pc0 * 16;                           \
        cp16(sa, ag); cp16(sa + 16, ag + 8);                                   \
        cp16(sb, bg); cp16(sb + 16, bg + 8);                                   \
        CP_COMMIT(); }

    int mat = lane >> 3, mr = lane & 7;
    uint32_t aoff = (uint32_t)((warp_m * 64 + (mat & 1) * 8 + mr) * 80
                               + ((mat >> 1) * 8) * 2);
    uint32_t boff = (uint32_t)((warp_n * 32 + (mat >> 1) * 8 + mr) * 80
                               + ((mat & 1) * 8) * 2);

    #pragma unroll
    for (int mi = 0; mi < 4; mi++)
        #pragma unroll
        for (int ni = 0; ni < 4; ni++)
            #pragma unroll
            for (int e = 0; e < 4; e++) acc[mi][ni][e] = 0.f;

    TC_PREFETCH(0, 0)
    TC_PREFETCH(1, 1)
    TC_PREFETCH(2, 2)

    for (int kc = 0; kc < NCHc; kc++) {
        CP_WAIT(TCSTG - 2);
        __syncthreads();
        int pkc = kc + TCSTG - 1;
        if (pkc < NCHc) { TC_PREFETCH(pkc, pkc & (TCSTG - 1)) }
        else { CP_COMMIT(); }
        int b = kc & (TCSTG - 1);
        #pragma unroll
        for (int ks = 0; ks < 32; ks += 16) {
            uint32_t afr[4][4];
            #pragma unroll
            for (int mi = 0; mi < 4; mi++)
                ldmx4(afr[mi], sA[b] + aoff + mi * (16 * 80) + ks * 2);
            uint32_t bfr[2][4];
            #pragma unroll
            for (int np = 0; np < 2; np++)
                ldmx4(bfr[np], sB[b] + boff + np * (16 * 80) + ks * 2);
            #pragma unroll
            for (int mi = 0; mi < 4; mi++)
                #pragma unroll
                for (int ni = 0; ni < 4; ni++)
                    mma_bf16(acc[mi][ni], afr[mi],
                             bfr[ni >> 1][(ni & 1) * 2],
                             bfr[ni >> 1][(ni & 1) * 2 + 1]);
        }
    }
#undef TC_PREFETCH
}

// --------- epilogue helper: write fp32 / bf16 hi-lo from acc -----------------
__device__ __forceinline__ void tc_epilogue(
    float acc[4][4][4], int m0, int n0, const float* bias,
    float* outF, bf16* outHi, bf16* outLo)
{
    int lane = threadIdx.x & 31, wid = threadIdx.x >> 5;
    int warp_m = wid >> 2, warp_n = wid & 3;
    int gid = lane >> 2, tig = lane & 3;
    #pragma unroll
    for (int ni = 0; ni < 4; ni++) {
        int cn = n0 + warp_n * 32 + ni * 8 + tig * 2;
        float bz0 = bias ? bias[cn] : 0.f;
        float bz1 = bias ? bias[cn + 1] : 0.f;
        #pragma unroll
        for (int mi = 0; mi < 4; mi++) {
            int rm = m0 + warp_m * 64 + mi * 16 + gid;
            float c0 = acc[mi][ni][0] + bz0, c1 = acc[mi][ni][1] + bz1;
            float c2 = acc[mi][ni][2] + bz0, c3 = acc[mi][ni][3] + bz1;
            if (outF) {
                *(float2*)&outF[(size_t)rm * DH + cn]       = make_float2(c0, c1);
                *(float2*)&outF[(size_t)(rm + 8) * DH + cn] = make_float2(c2, c3);
            }
            if (outHi) {
                bf16 h0 = __float2bfloat16(c0), h1 = __float2bfloat16(c1);
                bf16 h2 = __float2bfloat16(c2), h3 = __float2bfloat16(c3);
                __nv_bfloat162 hp0; hp0.x = h0; hp0.y = h1;
                __nv_bfloat162 hp1; hp1.x = h2; hp1.y = h3;
                __nv_bfloat162 lp0;
                lp0.x = __float2bfloat16(c0 - __bfloat162float(h0));
                lp0.y = __float2bfloat16(c1 - __bfloat162float(h1));
                __nv_bfloat162 lp1;
                lp1.x = __float2bfloat16(c2 - __bfloat162float(h2));
                lp1.y = __float2bfloat16(c3 - __bfloat162float(h3));
                *(__nv_bfloat162*)&outHi[(size_t)rm * DH + cn]       = hp0;
                *(__nv_bfloat162*)&outHi[(size_t)(rm + 8) * DH + cn] = hp1;
                *(__nv_bfloat162*)&outLo[(size_t)rm * DH + cn]       = lp0;
                *(__nv_bfloat162*)&outLo[(size_t)(rm + 8) * DH + cn] = lp1;
            }
        }
    }
}

// --------- composite-weight GEMMs: WcT[z] = (Wz2^T) @ (Wz1)^T ---------------
__global__ __launch_bounds__(256) void wgemm3_kernel()
{
    extern __shared__ char dsm[];
    int z = blockIdx.z;
    int m0 = blockIdx.y * 128, n0 = blockIdx.x * 128;
    const bf16 *Ah, *Al, *Bh, *Bl;
    if (z == 0)      { Ah = g_wftT_hi;  Al = g_wftT_lo;  Bh = g_wtars_hi; Bl = g_wtars_lo; }
    else if (z == 1) { Ah = g_wfoT_hi;  Al = g_wfoT_lo;  Bh = g_woris_hi; Bl = g_woris_lo; }
    else             { Ah = g_wfotT_hi; Al = g_wfotT_lo; Bh = g_woris_hi; Bl = g_woris_lo; }
    float acc[4][4][4];
    tc_core<1024>(Ah, Al, Bh, Bl, m0, n0, dsm, acc);
    tc_epilogue(acc, m0, n0, nullptr, nullptr,
                g_wc_hi + (size_t)z * WSZ, g_wc_lo + (size_t)z * WSZ);
}

// --------- fused 3 big GEMMs -------------------------------------------------
// z=0: tar (fp32 + hi/lo)  z=1: ofc (fp32 + hi/lo)  z=2: otp (fp32)
__global__ __launch_bounds__(256) void gemm3_tc_kernel()
{
    extern __shared__ char dsm[];
    int z = blockIdx.z;
    int m0 = blockIdx.y * 128, n0 = blockIdx.x * 128;
    const bf16 *Ah, *Al;
    float* outF;
    bf16 *oH, *oL;
    if (z == 0)      { Ah = g_thi; Al = g_tlo; outF = g_tar; oH = g_tarhi; oL = g_tarlo; }
    else if (z == 1) { Ah = g_ohi; Al = g_olo; outF = g_ofc; oH = g_ofchi; oL = g_ofclo; }
    else             { Ah = g_ohi; Al = g_olo; outF = g_otp; oH = nullptr; oL = nullptr; }
    const bf16* Bh = g_wc_hi + (size_t)z * WSZ;
    const bf16* Bl = g_wc_lo + (size_t)z * WSZ;
    float acc[4][4][4];
    tc_core<1024>(Ah, Al, Bh, Bl, m0, n0, dsm, acc);
    tc_epilogue(acc, m0, n0, g_bc[z], outF, oH, oL);
}

// ---------------- Q-GEMM (NT, batched): Qhi/Qlo = split(exp(20*cos)) ---------
__global__ __launch_bounds__(256) void qgemm_tc_kernel()
{
    extern __shared__ char dsm[];
    int b = blockIdx.z;
    int m0 = blockIdx.y * 128, n0 = blockIdx.x * 128;
    const bf16* Ah = g_tarhi + (size_t)b * LL * DH;
    const bf16* Al = g_tarlo + (size_t)b * LL * DH;
    const bf16* Bh = g_ofchi + (size_t)b * LL * DH;
    const bf16* Bl = g_ofclo + (size_t)b * LL * DH;
    float acc[4][4][4];
    tc_core<1024>(Ah, Al, Bh, Bl, m0, n0, dsm, acc);

    int lane = threadIdx.x & 31, wid = threadIdx.x >> 5;
    int warp_m = wid >> 2, warp_n = wid & 3;
    int gid = lane >> 2, tig = lane & 3;
    #pragma unroll
    for (int ni = 0; ni < 4; ni++) {
        int cn = n0 + warp_n * 32 + ni * 8 + tig * 2;
        float f0 = g_ifn[b * LL + cn], f1 = g_ifn[b * LL + cn + 1];
        #pragma unroll
        for (int mi = 0; mi < 4; mi++) {
            int rm = m0 + warp_m * 64 + mi * 16 + gid;
            float s0 = g_itn[b * LL + rm] * 20.0f;
            float s1 = g_itn[b * LL + rm + 8] * 20.0f;
            float c0 = expf(acc[mi][ni][0] * s0 * f0);
            float c1 = expf(acc[mi][ni][1] * s0 * f1);
            float c2 = expf(acc[mi][ni][2] * s1 * f0);
            float c3 = expf(acc[mi][ni][3] * s1 * f1);
            size_t r0 = ((size_t)b * LL + rm) * LL + cn;
            size_t r1 = ((size_t)b * LL + rm + 8) * LL + cn;
            bf16 h0 = __float2bfloat16(c0), h1 = __float2bfloat16(c1);
            bf16 h2 = __float2bfloat16(c2), h3 = __float2bfloat16(c3);
            __nv_bfloat162 hp0; hp0.x = h0; hp0.y = h1;
            __nv_bfloat162 hp1; hp1.x = h2; hp1.y = h3;
            __nv_bfloat162 lp0;
            lp0.x = __float2bfloat16(c0 - __bfloat162float(h0));
            lp0.y = __float2bfloat16(c1 - __bfloat162float(h1));
            __nv_bfloat162 lp1;
            lp1.x = __float2bfloat16(c2 - __bfloat162float(h2));
            lp1.y = __float2bfloat16(c3 - __bfloat162float(h3));
            *(__nv_bfloat162*)&g_Qhi[r0] = hp0;
            *(__nv_bfloat162*)&g_Qhi[r1] = hp1;
            *(__nv_bfloat162*)&g_Qlo[r0] = lp0;
            *(__nv_bfloat162*)&g_Qlo[r1] = lp1;
        }
    }
}

// ---------------- Final GEMM (NT, batched): out = rs*(Q @ votp^T) + tar ------
__global__ __launch_bounds__(256) void fgemm_tc_kernel()
{
    extern __shared__ char dsm[];
    int b = blockIdx.z;
    int m0 = blockIdx.y * 128, n0 = blockIdx.x * 128;
    const bf16* Ah = g_Qhi + (size_t)b * LL * LL;
    const bf16* Al = g_Qlo + (size_t)b * LL * LL;
    const bf16* Bh = g_vthi + (size_t)b * DH * LL;
    const bf16* Bl = g_vtlo + (size_t)b * DH * LL;
    float acc[4][4][4];
    tc_core<512>(Ah, Al, Bh, Bl, m0, n0, dsm, acc);

    int lane = threadIdx.x & 31, wid = threadIdx.x >> 5;
    int warp_m = wid >> 2, warp_n = wid & 3;
    int gid = lane >> 2, tig = lane & 3;
    #pragma unroll
    for (int ni = 0; ni < 4; ni++) {
        int cn = n0 + warp_n * 32 + ni * 8 + tig * 2;
        #pragma unroll
        for (int mi = 0; mi < 4; mi++) {
            int rm = m0 + warp_m * 64 + mi * 16 + gid;
            int g0 = b * LL + rm, g1 = b * LL + rm + 8;
            float r0 = g_rs[g0], r1 = g_rs[g1];
            float2 t0 = *(const float2*)&g_tar[(size_t)g0 * DH + cn];
            float2 t1 = *(const float2*)&g_tar[(size_t)g1 * DH + cn];
            float2 o0 = make_float2(r0 * acc[mi][ni][0] + t0.x,
                                    r0 * acc[mi][ni][1] + t0.y);
            float2 o1 = make_float2(r1 * acc[mi][ni][2] + t1.x,
                                    r1 * acc[mi][ni][3] + t1.y);
            *(float2*)&g_obuf[(size_t)g0 * DH + cn] = o0;
            *(float2*)&g_obuf[(size_t)g1 * DH + cn] = o1;
        }
    }
}

// ---------------- fp32 -> bf16 hi/lo split (paired launches) -----------------
__global__ __launch_bounds__(256) void split2_kernel(
    const float* __restrict__ x0, bf16* __restrict__ hi0, bf16* __restrict__ lo0,
    const float* __restrict__ x1, bf16* __restrict__ hi1, bf16* __restrict__ lo1,
    int n)
{
    const float* x = blockIdx.y ? x1 : x0;
    bf16* hi = blockIdx.y ? hi1 : hi0;
    bf16* lo = blockIdx.y ? lo1 : lo0;
    int i = (blockIdx.x * 256 + threadIdx.x) * 4;
    if (i >= n) return;
    float4 v = *(const float4*)(x + i);
    bf16 h0 = __float2bfloat16(v.x), h1 = __float2bfloat16(v.y);
    bf16 h2 = __float2bfloat16(v.z), h3 = __float2bfloat16(v.w);
    __nv_bfloat162 hp0; hp0.x = h0; hp0.y = h1;
    __nv_bfloat162 hp1; hp1.x = h2; hp1.y = h3;
    __nv_bfloat162 lp0;
    lp0.x = __float2bfloat16(v.x - __bfloat162float(h0));
    lp0.y = __float2bfloat16(v.y - __bfloat162float(h1));
    __nv_bfloat162 lp1;
    lp1.x = __float2bfloat16(v.z - __bfloat162float(h2));
    lp1.y = __float2bfloat16(v.w - __bfloat162float(h3));
    *(__nv_bfloat162*)&hi[i]     = hp0;
    *(__nv_bfloat162*)&hi[i + 2] = hp1;
    *(__nv_bfloat162*)&lo[i]     = lp0;
    *(__nv_bfloat162*)&lo[i + 2] = lp1;
}

// ------- weight transpose + split (3 weights in one launch, grid.z) ----------
__global__ void trans_split3_kernel(
    const float* __restrict__ W0, const float* __restrict__ W1,
    const float* __restrict__ W2)
{
    __shared__ float t[32][33];
    int z = blockIdx.z;
    const float* W = (z == 0) ? W0 : (z == 1) ? W1 : W2;
    bf16* hiT = (z == 0) ? g_wftT_hi : (z == 1) ? g_wfoT_hi : g_wfotT_hi;
    bf16* loT = (z == 0) ? g_wftT_lo : (z == 1) ? g_wfoT_lo : g_wfotT_lo;
    int n0 = blockIdx.x * 32, k0 = blockIdx.y * 32;
    int tx = threadIdx.x, ty = threadIdx.y;   // 32 x 8
    #pragma unroll
    for (int i = ty; i < 32; i += 8)
        t[i][tx] = W[(size_t)(k0 + i) * DH + n0 + tx];
    __syncthreads();
    #pragma unroll
    for (int i = ty; i < 32; i += 8) {
        float v = t[tx][i];
        bf16 h = __float2bfloat16(v);
        bf16 l = __float2bfloat16(v - __bfloat162float(h));
        hiT[(size_t)(n0 + i) * DH + k0 + tx] = h;
        loT[(size_t)(n0 + i) * DH + k0 + tx] = l;
    }
}

// ---------------- composite biases, phase 1: partial split-k sums ------------
__global__ __launch_bounds__(256) void bias_comb_p1_kernel(
    const float* __restrict__ b_tar, const float* __restrict__ b_ori,
    const float* __restrict__ W_ft, const float* __restrict__ W_fo,
    const float* __restrict__ W_fot)
{
    __shared__ float red[8][33];
    int z = blockIdx.z;
    int ks = blockIdx.y;
    int n = blockIdx.x * 32 + threadIdx.x;
    int ky = threadIdx.y;   // 0..7
    const float* b1 = (z == 0) ? b_tar : b_ori;
    const float* W2 = (z == 0) ? W_ft : (z == 1) ? W_fo : W_fot;
    int k0 = ks * 256;
    float s = 0.f;
    #pragma unroll 4
    for (int k = k0 + ky; k < k0 + 256; k += 8)
        s += b1[k] * W2[(size_t)k * DH + n];
    red[ky][threadIdx.x] = s;
    __syncthreads();
    if (ky == 0) {
        float tot = 0.f;
        #pragma unroll
        for (int j = 0; j < 8; j++) tot += red[j][threadIdx.x];
        g_bcp[z][ks][n] = tot;
    }
}

// ---------------- composite biases, phase 2: reduce + add b2 -----------------
__global__ void bias_comb_p2_kernel(
    const float* __restrict__ b_ft, const float* __restrict__ b_fo,
    const float* __restrict__ b_fot)
{
    int z = blockIdx.y;
    int n = blockIdx.x * 256 + threadIdx.x;
    const float* b2 = (z == 0) ? b_ft : (z == 1) ? b_fo : b_fot;
    float s = g_bcp[z][0][n] + g_bcp[z][1][n] + g_bcp[z][2][n] + g_bcp[z][3][n];
    g_bc[z][n] = s + b2[n];
}

// ------- batched transpose+scale+split: vt[b][h][o] = otp[b][o][h]*v[b][o] ---
__global__ void vtrans_split_kernel()
{
    __shared__ float t[32][33];
    int b = blockIdx.z;
    int h0 = blockIdx.x * 32, o0 = blockIdx.y * 32;
    int tx = threadIdx.x, ty = threadIdx.y;   // 32 x 8
    const float* src = g_otp + (size_t)b * LL * DH;
    #pragma unroll
    for (int i = ty; i < 32; i += 8)
        t[i][tx] = src[(size_t)(o0 + i) * DH + h0 + tx] * g_v[b * LL + o0 + i];
    __syncthreads();
    bf16* hb = g_vthi + (size_t)b * DH * LL;
    bf16* lb = g_vtlo + (size_t)b * DH * LL;
    #pragma unroll
    for (int i = ty; i < 32; i += 8) {
        float x = t[tx][i];
        bf16 h = __float2bfloat16(x);
        bf16 l = __float2bfloat16(x - __bfloat162float(h));
        hb[(size_t)(h0 + i) * LL + o0 + tx] = h;
        lb[(size_t)(h0 + i) * LL + o0 + tx] = l;
    }
}

// ================= small SIMT kernels ========================================
__device__ __forceinline__ float block_reduce_sum_256(float val, float* red) {
    int tid = threadIdx.x;
    #pragma unroll
    for (int o = 16; o > 0; o >>= 1) val += __shfl_down_sync(0xffffffffu, val, o);
    if ((tid & 31) == 0) red[tid >> 5] = val;
    __syncthreads();
    if (tid < 8) {
        val = red[tid];
        #pragma unroll
        for (int o = 4; o > 0; o >>= 1) val += __shfl_down_sync(0xffu, val, o);
        if (tid == 0) red[0] = val;
    }
    __syncthreads();
    float r = red[0];
    __syncthreads();
    return r;
}

// inv row norms: y==0 -> tar->itn, y==1 -> ofc->ifn (one launch)
__global__ __launch_bounds__(256) void invnorm2_kernel()
{
    __shared__ float red[8];
    int row = blockIdx.x;
    int which = blockIdx.y;
    const float* x = which ? g_ofc : g_tar;
    float* inv = which ? g_ifn : g_itn;
    const float* p = x + (size_t)row * DH;
    float s = 0.f;
    for (int c = threadIdx.x; c < DH; c += 256) { float v = p[c]; s += v * v; }
    float tot = block_reduce_sum_256(s, red);
    if (threadIdx.x == 0) inv[row] = 1.0f / fmaxf(sqrtf(tot), 1e-8f);
}

// ---- Sinkhorn on Qhi (bf16; round-9 validated numerics) ----------------------
// u[b,t] = 1 / rowsum(Qhi)   (first iteration: v = 1 exactly)
__global__ void rowmv_first_kernel()
{
    int t = blockIdx.x * 8 + threadIdx.y;
    int b = blockIdx.y;
    const bf16* row = g_Qhi + ((size_t)b * LL + t) * LL;
    float s = 0.f;
    for (int o = threadIdx.x * 2; o < LL; o += 64) {
        __nv_bfloat162 q = *(const __nv_bfloat162*)&row[o];
        s += __bfloat162float(q.x) + __bfloat162float(q.y);
    }
    #pragma unroll
    for (int off = 16; off > 0; off >>= 1) s += __shfl_down_sync(0xffffffffu, s, off);
    if (threadIdx.x == 0) g_u[b * LL + t] = 1.0f / s;
}

// u[b,t] = 1 / sum_o Qhi[b,t,o] * v[b,o]
__global__ void rowmv_kernel()
{
    int t = blockIdx.x * 8 + threadIdx.y;
    int b = blockIdx.y;
    const bf16* row = g_Qhi + ((size_t)b * LL + t) * LL;
    const float* vv = g_v + b * LL;
    float s = 0.f;
    for (int o = threadIdx.x * 2; o < LL; o += 64) {
        __nv_bfloat162 q = *(const __nv_bfloat162*)&row[o];
        float2 v2 = *(const float2*)&vv[o];
        s += __bfloat162float(q.x) * v2.x + __bfloat162float(q.y) * v2.y;
    }
    #pragma unroll
    for (int off = 16; off > 0; off >>= 1) s += __shfl_down_sync(0xffffffffu, s, off);
    if (threadIdx.x == 0) g_u[b * LL + t] = 1.0f / s;
}

// v[b,o] = 1 / sum_t Qhi[b,t,o] * u[b,t]
__global__ void colmv_kernel()
{
    __shared__ float red[8][32];
    int o = blockIdx.x * 32 + threadIdx.x;
    int b = blockIdx.y;
    const float* uu = g_u + b * LL;
    float s = 0.f;
    for (int t = threadIdx.y; t < LL; t += 8)
        s += __bfloat162float(g_Qhi[((size_t)b * LL + t) * LL + o]) * uu[t];
    red[threadIdx.y][threadIdx.x] = s;
    __syncthreads();
    if (threadIdx.y == 0) {
        float tot = 0.f;
        #pragma unroll
        for (int j = 0; j < 8; j++) tot += red[j][threadIdx.x];
        g_v[b * LL + o] = 1.0f / tot;
    }
}

// rs[b,t] = u_t / max(u_t * sqrt(sum_o (Q_to * v_o)^2), 1e-12)
__global__ void rowscale_kernel()
{
    int t = blockIdx.x * 8 + threadIdx.y;
    int b = blockIdx.y;
    const bf16* row = g_Qhi + ((size_t)b * LL + t) * LL;
    const float* vv = g_v + b * LL;
    float s = 0.f;
    for (int o = threadIdx.x * 2; o < LL; o += 64) {
        __nv_bfloat162 qp = *(const __nv_bfloat162*)&row[o];
        float2 v2 = *(const float2*)&vv[o];
        float q0 = __bfloat162float(qp.x) * v2.x;
        float q1 = __bfloat162float(qp.y) * v2.y;
        s += q0 * q0 + q1 * q1;
    }
    #pragma unroll
    for (int off = 16; off > 0; off >>= 1) s += __shfl_down_sync(0xffffffffu, s, off);
    if (threadIdx.x == 0) {
        float ut = g_u[b * LL + t];
        g_rs[b * LL + t] = ut / fmaxf(ut * sqrtf(s), 1e-12f);
    }
}

__global__ __launch_bounds__(256) void ln_kernel(
    const float* __restrict__ x, const float* __restrict__ g,
    const float* __restrict__ beta, float* __restrict__ y)
{
    __shared__ float buf[DH];
    __shared__ float red[8];
    int row = blockIdx.x;
    const float* p = x + (size_t)row * DH;
    float s = 0.f;
    for (int c = threadIdx.x; c < DH; c += 256) { float v = p[c]; buf[c] = v; s += v; }
    float mean = block_reduce_sum_256(s, red) * (1.0f / DH);
    float s2 = 0.f;
    for (int c = threadIdx.x; c < DH; c += 256) { float d = buf[c] - mean; s2 += d * d; }
    float var = block_reduce_sum_256(s2, red) * (1.0f / DH);
    float inv = rsqrtf(var + 1e-5f);
    for (int c = threadIdx.x; c < DH; c += 256)
        y[(size_t)row * DH + c] = (buf[c] - mean) * inv * g[c] + beta[c];
}

// ---------------- launch -----------------------------------------------------
extern "C" void kernel_launch(void* const* d_in, const int* in_sizes, int n_in,
                              void* d_out, int out_size)
{
    const float* origin = (const float*)d_in[0];
    const float* target = (const float*)d_in[1];
    const float* W_ori = (const float*)d_in[2];  const float* b_ori = (const float*)d_in[3];
    const float* W_tar = (const float*)d_in[4];  const float* b_tar = (const float*)d_in[5];
    const float* W_ft  = (const float*)d_in[6];  const float* b_ft  = (const float*)d_in[7];
    const float* W_fo  = (const float*)d_in[8];  const float* b_fo  = (const float*)d_in[9];
    const float* W_fot = (const float*)d_in[10]; const float* b_fot = (const float*)d_in[11];
    const float* ln_g  = (const float*)d_in[12]; const float* ln_b  = (const float*)d_in[13];
    float* out = (float*)d_out;

    bf16 *ohi, *olo, *thi, *tlo, *woris_hi, *woris_lo, *wtars_hi, *wtars_lo;
    float *obuf;
    cudaGetSymbolAddress((void**)&ohi,      g_ohi);
    cudaGetSymbolAddress((void**)&olo,      g_olo);
    cudaGetSymbolAddress((void**)&thi,      g_thi);
    cudaGetSymbolAddress((void**)&tlo,      g_tlo);
    cudaGetSymbolAddress((void**)&woris_hi, g_woris_hi);
    cudaGetSymbolAddress((void**)&woris_lo, g_woris_lo);
    cudaGetSymbolAddress((void**)&wtars_hi, g_wtars_hi);
    cudaGetSymbolAddress((void**)&wtars_lo, g_wtars_lo);
    cudaGetSymbolAddress((void**)&obuf,     g_obuf);

    const int NELEM = MTOT * DH;
    const int WELEM = (int)WSZ;

    cudaFuncSetAttribute(wgemm3_kernel,
                         cudaFuncAttributeMaxDynamicSharedMemorySize, TC_SMEM);
    cudaFuncSetAttribute(gemm3_tc_kernel,
                         cudaFuncAttributeMaxDynamicSharedMemorySize, TC_SMEM);
    cudaFuncSetAttribute(qgemm_tc_kernel,
                         cudaFuncAttributeMaxDynamicSharedMemorySize, TC_SMEM);
    cudaFuncSetAttribute(fgemm_tc_kernel,
                         cudaFuncAttributeMaxDynamicSharedMemorySize, TC_SMEM);

    dim3 blk(256);

    // activation splits (one launch) + plain weight splits (one launch)
    split2_kernel<<<dim3(NELEM / 4 / 256, 2), blk>>>(
        origin, ohi, olo, target, thi, tlo, NELEM);
    split2_kernel<<<dim3(WELEM / 4 / 256, 2), blk>>>(
        W_ori, woris_hi, woris_lo, W_tar, wtars_hi, wtars_lo, WELEM);

    // transposed splits of second-stage weights (one launch)
    trans_split3_kernel<<<dim3(32, 32, 3), dim3(32, 8)>>>(W_ft, W_fo, W_fot);

    // composite biases (two-phase split-k, 384 blocks)
    bias_comb_p1_kernel<<<dim3(DH / 32, 4, 3), dim3(32, 8)>>>(
        b_tar, b_ori, W_ft, W_fo, W_fot);
    bias_comb_p2_kernel<<<dim3(DH / 256, 3), blk>>>(b_ft, b_fo, b_fot);

    // composite weights: WcT[z] via tensor cores (192 CTAs)
    wgemm3_kernel<<<dim3(8, 8, 3), blk, TC_SMEM>>>();

    // fused 3 big GEMMs: tar / ofc / otp
    gemm3_tc_kernel<<<dim3(8, 64, 3), blk, TC_SMEM>>>();

    // row inverse norms (one launch, both arrays)
    invnorm2_kernel<<<dim3(MTOT, 2), blk>>>();

    // Q = exp(cos/0.05), bf16 hi/lo only (no fp32 Q)
    qgemm_tc_kernel<<<dim3(LL / 128, LL / 128, BB), blk, TC_SMEM>>>();

    // Sinkhorn on Qhi (bf16): u = 1/(Qv), v = 1/(Q^T u), 5 iterations
    rowmv_first_kernel<<<dim3(LL / 8, BB), dim3(32, 8)>>>();
    colmv_kernel<<<dim3(LL / 32, BB), dim3(32, 8)>>>();
    for (int it = 0; it < 4; it++) {
        rowmv_kernel<<<dim3(LL / 8, BB), dim3(32, 8)>>>();
        colmv_kernel<<<dim3(LL / 32, BB), dim3(32, 8)>>>();
    }
    rowscale_kernel<<<dim3(LL / 8, BB), dim3(32, 8)>>>();

    // (v .* otp) transposed + split per batch
    vtrans_split_kernel<<<dim3(DH / 32, LL / 32, BB), dim3(32, 8)>>>();

    // out = rs_t * (Q @ vt^T) + tar   (3-term Qhi+Qlo)
    fgemm_tc_kernel<<<dim3(DH / 128, LL / 128, BB), blk, TC_SMEM>>>();

    // LayerNorm
    ln_kernel<<<MTOT, blk>>>(obuf, ln_g, ln_b, out);
}

// round 17
// speedup vs baseline: 1.1264x; 1.0020x over previous
#include <cuda_runtime.h>
#include <cuda_bf16.h>
#include <math.h>
#include <stdint.h>

// Problem dims (fixed by the dataset)
#define BB   16
#define LL   512
#define DIN  1024
#define DH   1024
#define MTOT (BB * LL)   // 8192
#define WSZ  ((size_t)DH * DH)

typedef __nv_bfloat16 bf16;

// ---------------- scratch (static __device__: allocation-free) --------------
__device__ bf16 g_ohi [(size_t)MTOT * DH];
__device__ bf16 g_olo [(size_t)MTOT * DH];
__device__ bf16 g_thi [(size_t)MTOT * DH];
__device__ bf16 g_tlo [(size_t)MTOT * DH];
__device__ bf16 g_tarhi[(size_t)MTOT * DH];
__device__ bf16 g_tarlo[(size_t)MTOT * DH];
__device__ bf16 g_ofchi[(size_t)MTOT * DH];
__device__ bf16 g_ofclo[(size_t)MTOT * DH];
__device__ bf16 g_woris_hi[WSZ], g_woris_lo[WSZ];
__device__ bf16 g_wtars_hi[WSZ], g_wtars_lo[WSZ];
__device__ bf16 g_wftT_hi[WSZ],  g_wftT_lo[WSZ];
__device__ bf16 g_wfoT_hi[WSZ],  g_wfoT_lo[WSZ];
__device__ bf16 g_wfotT_hi[WSZ], g_wfotT_lo[WSZ];
__device__ bf16 g_wc_hi[3 * WSZ], g_wc_lo[3 * WSZ];
__device__ float g_bc[3][DH];
__device__ float g_bcp[3][4][DH];
__device__ bf16 g_Qhi [(size_t)BB * LL * LL];
__device__ bf16 g_Qlo [(size_t)BB * LL * LL];
__device__ bf16 g_vthi[(size_t)BB * DH * LL];
__device__ bf16 g_vtlo[(size_t)BB * DH * LL];
__device__ float g_tar  [(size_t)MTOT * DH];
__device__ float g_ofc  [(size_t)MTOT * DH];
__device__ float g_otp  [(size_t)MTOT * DH];
__device__ float g_obuf [(size_t)MTOT * DH];
__device__ float g_itn  [MTOT];
__device__ float g_ifn  [MTOT];
__device__ float g_u    [MTOT];
__device__ float g_v    [MTOT];
__device__ float g_rs   [MTOT];

// ================= portable tensor-core helpers (sm_80 PTX) ==================
__device__ __forceinline__ uint32_t smem_u32(const void* p) {
    uint32_t a;
    asm("{ .reg .u64 t; cvta.to.shared.u64 t, %1; cvt.u32.u64 %0, t; }"
        : "=r"(a) : "l"(p));
    return a;
}
__device__ __forceinline__ void cp16(uint32_t s, const void* g) {
    asm volatile("cp.async.cg.shared.global [%0], [%1], 16;"
                 :: "r"(s), "l"(g) : "memory");
}
#define CP_COMMIT() asm volatile("cp.async.commit_group;" ::: "memory")
#define CP_WAIT(n)  asm volatile("cp.async.wait_group %0;" :: "n"(n) : "memory")

__device__ __forceinline__ void ldmx4(uint32_t* r, uint32_t addr) {
    asm volatile("ldmatrix.sync.aligned.m8n8.x4.shared.b16 {%0,%1,%2,%3}, [%4];"
        : "=r"(r[0]), "=r"(r[1]), "=r"(r[2]), "=r"(r[3]) : "r"(addr));
}
__device__ __forceinline__ void mma_bf16(float* d, const uint32_t* a,
                                         uint32_t b0, uint32_t b1) {
    asm volatile(
        "mma.sync.aligned.m16n8k16.row.col.f32.bf16.bf16.f32 "
        "{%0,%1,%2,%3}, {%4,%5,%6,%7}, {%8,%9}, {%0,%1,%2,%3};"
        : "+f"(d[0]), "+f"(d[1]), "+f"(d[2]), "+f"(d[3])
        : "r"(a[0]), "r"(a[1]), "r"(a[2]), "r"(a[3]), "r"(b0), "r"(b1));
}

// ===== shared mainloop (round-8 proven): 3-term bf16-split, NT ==============
// 256 threads (8 warps), warp tile 64x32, K-chunk 32, 4-stage cp.async ring.
#define TCSTG 4
#define STAGE_BYTES 10240            // 128 rows * 80 B
#define TC_SMEM (2 * TCSTG * STAGE_BYTES)   // 81920

template<int KDIM>
__device__ __forceinline__ void tc_core(
    const bf16* __restrict__ Ahi, const bf16* __restrict__ Alo,
    const bf16* __restrict__ Bhi, const bf16* __restrict__ Blo,
    int m0, int n0, char* dsm, float acc[4][4][4])
{
    const int CPS = KDIM / 32;        // chunks per segment
    const int NCHc = 3 * CPS;
    int tid = threadIdx.x;
    int lane = tid & 31, wid = tid >> 5;
    int warp_m = wid >> 2, warp_n = wid & 3;
    int prow = tid >> 1, pc0 = (tid & 1) * 2;

    uint32_t base = smem_u32(dsm);
    uint32_t sA[TCSTG], sB[TCSTG];
    #pragma unroll
    for (int s = 0; s < TCSTG; s++) {
        sA[s] = base + s * STAGE_BYTES;
        sB[s] = base + TCSTG * STAGE_BYTES + s * STAGE_BYTES;
    }

#define TC_PREFETCH(kc, st) {                                                  \
        int seg = (kc) / CPS;                                                  \
        int ko = ((kc) % CPS) * 32;                                            \
        const bf16* Asrc = (seg == 2) ? Alo : Ahi;                             \
        const bf16* Bsrc = (seg == 1) ? Blo : Bhi;                             \
        const bf16* ag = Asrc + (size_t)(m0 + prow) * KDIM + ko + pc0 * 8;     \
        const bf16* bg = Bsrc + (size_t)(n0 + prow) * KDIM + ko + pc0 * 8;     \
        uint32_t sa = sA[st] + prow * 80 + pc0 * 16;                           \
        uint32_t sb = sB[st] + prow * 80 + pc0 * 16;                           \
        cp16(sa, ag); cp16(sa + 16, ag + 8);                                   \
        cp16(sb, bg); cp16(sb + 16, bg + 8);                                   \
        CP_COMMIT(); }

    int mat = lane >> 3, mr = lane & 7;
    uint32_t aoff = (uint32_t)((warp_m * 64 + (mat & 1) * 8 + mr) * 80
                               + ((mat >> 1) * 8) * 2);
    uint32_t boff = (uint32_t)((warp_n * 32 + (mat >> 1) * 8 + mr) * 80
                               + ((mat & 1) * 8) * 2);

    #pragma unroll
    for (int mi = 0; mi < 4; mi++)
        #pragma unroll
        for (int ni = 0; ni < 4; ni++)
            #pragma unroll
            for (int e = 0; e < 4; e++) acc[mi][ni][e] = 0.f;

    TC_PREFETCH(0, 0)
    TC_PREFETCH(1, 1)
    TC_PREFETCH(2, 2)

    for (int kc = 0; kc < NCHc; kc++) {
        CP_WAIT(TCSTG - 2);
        __syncthreads();
        int pkc = kc + TCSTG - 1;
        if (pkc < NCHc) { TC_PREFETCH(pkc, pkc & (TCSTG - 1)) }
        else { CP_COMMIT(); }
        int b = kc & (TCSTG - 1);
        #pragma unroll
        for (int ks = 0; ks < 32; ks += 16) {
            uint32_t afr[4][4];
            #pragma unroll
            for (int mi = 0; mi < 4; mi++)
                ldmx4(afr[mi], sA[b] + aoff + mi * (16 * 80) + ks * 2);
            uint32_t bfr[2][4];
            #pragma unroll
            for (int np = 0; np < 2; np++)
                ldmx4(bfr[np], sB[b] + boff + np * (16 * 80) + ks * 2);
            #pragma unroll
            for (int mi = 0; mi < 4; mi++)
                #pragma unroll
                for (int ni = 0; ni < 4; ni++)
                    mma_bf16(acc[mi][ni], afr[mi],
                             bfr[ni >> 1][(ni & 1) * 2],
                             bfr[ni >> 1][(ni & 1) * 2 + 1]);
        }
    }
#undef TC_PREFETCH
}

// --------- epilogue helper: write fp32 / bf16 hi-lo from acc -----------------
__device__ __forceinline__ void tc_epilogue(
    float acc[4][4][4], int m0, int n0, const float* bias,
    float* outF, bf16* outHi, bf16* outLo)
{
    int lane = threadIdx.x & 31, wid = threadIdx.x >> 5;
    int warp_m = wid >> 2, warp_n = wid & 3;
    int gid = lane >> 2, tig = lane & 3;
    #pragma unroll
    for (int ni = 0; ni < 4; ni++) {
        int cn = n0 + warp_n * 32 + ni * 8 + tig * 2;
        float bz0 = bias ? bias[cn] : 0.f;
        float bz1 = bias ? bias[cn + 1] : 0.f;
        #pragma unroll
        for (int mi = 0; mi < 4; mi++) {
            int rm = m0 + warp_m * 64 + mi * 16 + gid;
            float c0 = acc[mi][ni][0] + bz0, c1 = acc[mi][ni][1] + bz1;
            float c2 = acc[mi][ni][2] + bz0, c3 = acc[mi][ni][3] + bz1;
            if (outF) {
                *(float2*)&outF[(size_t)rm * DH + cn]       = make_float2(c0, c1);
                *(float2*)&outF[(size_t)(rm + 8) * DH + cn] = make_float2(c2, c3);
            }
            if (outHi) {
                bf16 h0 = __float2bfloat16(c0), h1 = __float2bfloat16(c1);
                bf16 h2 = __float2bfloat16(c2), h3 = __float2bfloat16(c3);
                __nv_bfloat162 hp0; hp0.x = h0; hp0.y = h1;
                __nv_bfloat162 hp1; hp1.x = h2; hp1.y = h3;
                __nv_bfloat162 lp0;
                lp0.x = __float2bfloat16(c0 - __bfloat162float(h0));
                lp0.y = __float2bfloat16(c1 - __bfloat162float(h1));
                __nv_bfloat162 lp1;
                lp1.x = __float2bfloat16(c2 - __bfloat162float(h2));
                lp1.y = __float2bfloat16(c3 - __bfloat162float(h3));
                *(__nv_bfloat162*)&outHi[(size_t)rm * DH + cn]       = hp0;
                *(__nv_bfloat162*)&outHi[(size_t)(rm + 8) * DH + cn] = hp1;
                *(__nv_bfloat162*)&outLo[(size_t)rm * DH + cn]       = lp0;
                *(__nv_bfloat162*)&outLo[(size_t)(rm + 8) * DH + cn] = lp1;
            }
        }
    }
}

// --------- composite-weight GEMMs: WcT[z] = (Wz2^T) @ (Wz1)^T ---------------
__global__ __launch_bounds__(256) void wgemm3_kernel()
{
    extern __shared__ char dsm[];
    int z = blockIdx.z;
    int m0 = blockIdx.y * 128, n0 = blockIdx.x * 128;
    const bf16 *Ah, *Al, *Bh, *Bl;
    if (z == 0)      { Ah = g_wftT_hi;  Al = g_wftT_lo;  Bh = g_wtars_hi; Bl = g_wtars_lo; }
    else if (z == 1) { Ah = g_wfoT_hi;  Al = g_wfoT_lo;  Bh = g_woris_hi; Bl = g_woris_lo; }
    else             { Ah = g_wfotT_hi; Al = g_wfotT_lo; Bh = g_woris_hi; Bl = g_woris_lo; }
    float acc[4][4][4];
    tc_core<1024>(Ah, Al, Bh, Bl, m0, n0, dsm, acc);
    tc_epilogue(acc, m0, n0, nullptr, nullptr,
                g_wc_hi + (size_t)z * WSZ, g_wc_lo + (size_t)z * WSZ);
}

// --------- fused 3 big GEMMs -------------------------------------------------
// z=0: tar (fp32 + hi/lo)  z=1: ofc (fp32 + hi/lo)  z=2: otp (fp32)
__global__ __launch_bounds__(256) void gemm3_tc_kernel()
{
    extern __shared__ char dsm[];
    int z = blockIdx.z;
    int m0 = blockIdx.y * 128, n0 = blockIdx.x * 128;
    const bf16 *Ah, *Al;
    float* outF;
    bf16 *oH, *oL;
    if (z == 0)      { Ah = g_thi; Al = g_tlo; outF = g_tar; oH = g_tarhi; oL = g_tarlo; }
    else if (z == 1) { Ah = g_ohi; Al = g_olo; outF = g_ofc; oH = g_ofchi; oL = g_ofclo; }
    else             { Ah = g_ohi; Al = g_olo; outF = g_otp; oH = nullptr; oL = nullptr; }
    const bf16* Bh = g_wc_hi + (size_t)z * WSZ;
    const bf16* Bl = g_wc_lo + (size_t)z * WSZ;
    float acc[4][4][4];
    tc_core<1024>(Ah, Al, Bh, Bl, m0, n0, dsm, acc);
    tc_epilogue(acc, m0, n0, g_bc[z], outF, oH, oL);
}

// ---------------- Q-GEMM (NT, batched): Qhi/Qlo = split(exp(20*cos)) ---------
__global__ __launch_bounds__(256) void qgemm_tc_kernel()
{
    extern __shared__ char dsm[];
    int b = blockIdx.z;
    int m0 = blockIdx.y * 128, n0 = blockIdx.x * 128;
    const bf16* Ah = g_tarhi + (size_t)b * LL * DH;
    const bf16* Al = g_tarlo + (size_t)b * LL * DH;
    const bf16* Bh = g_ofchi + (size_t)b * LL * DH;
    const bf16* Bl = g_ofclo + (size_t)b * LL * DH;
    float acc[4][4][4];
    tc_core<1024>(Ah, Al, Bh, Bl, m0, n0, dsm, acc);

    int lane = threadIdx.x & 31, wid = threadIdx.x >> 5;
    int warp_m = wid >> 2, warp_n = wid & 3;
    int gid = lane >> 2, tig = lane & 3;
    #pragma unroll
    for (int ni = 0; ni < 4; ni++) {
        int cn = n0 + warp_n * 32 + ni * 8 + tig * 2;
        float f0 = g_ifn[b * LL + cn], f1 = g_ifn[b * LL + cn + 1];
        #pragma unroll
        for (int mi = 0; mi < 4; mi++) {
            int rm = m0 + warp_m * 64 + mi * 16 + gid;
            float s0 = g_itn[b * LL + rm] * 20.0f;
            float s1 = g_itn[b * LL + rm + 8] * 20.0f;
            float c0 = expf(acc[mi][ni][0] * s0 * f0);
            float c1 = expf(acc[mi][ni][1] * s0 * f1);
            float c2 = expf(acc[mi][ni][2] * s1 * f0);
            float c3 = expf(acc[mi][ni][3] * s1 * f1);
            size_t r0 = ((size_t)b * LL + rm) * LL + cn;
            size_t r1 = ((size_t)b * LL + rm + 8) * LL + cn;
            bf16 h0 = __float2bfloat16(c0), h1 = __float2bfloat16(c1);
            bf16 h2 = __float2bfloat16(c2), h3 = __float2bfloat16(c3);
            __nv_bfloat162 hp0; hp0.x = h0; hp0.y = h1;
            __nv_bfloat162 hp1; hp1.x = h2; hp1.y = h3;
            __nv_bfloat162 lp0;
            lp0.x = __float2bfloat16(c0 - __bfloat162float(h0));
            lp0.y = __float2bfloat16(c1 - __bfloat162float(h1));
            __nv_bfloat162 lp1;
            lp1.x = __float2bfloat16(c2 - __bfloat162float(h2));
            lp1.y = __float2bfloat16(c3 - __bfloat162float(h3));
            *(__nv_bfloat162*)&g_Qhi[r0] = hp0;
            *(__nv_bfloat162*)&g_Qhi[r1] = hp1;
            *(__nv_bfloat162*)&g_Qlo[r0] = lp0;
            *(__nv_bfloat162*)&g_Qlo[r1] = lp1;
        }
    }
}

// ---------------- Final GEMM (NT, batched): out = rs*(Q @ votp^T) + tar ------
__global__ __launch_bounds__(256) void fgemm_tc_kernel()
{
    extern __shared__ char dsm[];
    int b = blockIdx.z;
    int m0 = blockIdx.y * 128, n0 = blockIdx.x * 128;
    const bf16* Ah = g_Qhi + (size_t)b * LL * LL;
    const bf16* Al = g_Qlo + (size_t)b * LL * LL;
    const bf16* Bh = g_vthi + (size_t)b * DH * LL;
    const bf16* Bl = g_vtlo + (size_t)b * DH * LL;
    float acc[4][4][4];
    tc_core<512>(Ah, Al, Bh, Bl, m0, n0, dsm, acc);

    int lane = threadIdx.x & 31, wid = threadIdx.x >> 5;
    int warp_m = wid >> 2, warp_n = wid & 3;
    int gid = lane >> 2, tig = lane & 3;
    #pragma unroll
    for (int ni = 0; ni < 4; ni++) {
        int cn = n0 + warp_n * 32 + ni * 8 + tig * 2;
        #pragma unroll
        for (int mi = 0; mi < 4; mi++) {
            int rm = m0 + warp_m * 64 + mi * 16 + gid;
            int g0 = b * LL + rm, g1 = b * LL + rm + 8;
            float r0 = g_rs[g0], r1 = g_rs[g1];
            float2 t0 = *(const float2*)&g_tar[(size_t)g0 * DH + cn];
            float2 t1 = *(const float2*)&g_tar[(size_t)g1 * DH + cn];
            float2 o0 = make_float2(r0 * acc[mi][ni][0] + t0.x,
                                    r0 * acc[mi][ni][1] + t0.y);
            float2 o1 = make_float2(r1 * acc[mi][ni][2] + t1.x,
                                    r1 * acc[mi][ni][3] + t1.y);
            *(float2*)&g_obuf[(size_t)g0 * DH + cn] = o0;
            *(float2*)&g_obuf[(size_t)g1 * DH + cn] = o1;
        }
    }
}

// ---------------- fp32 -> bf16 hi/lo split (paired launches) -----------------
__global__ __launch_bounds__(256) void split2_kernel(
    const float* __restrict__ x0, bf16* __restrict__ hi0, bf16* __restrict__ lo0,
    const float* __restrict__ x1, bf16* __restrict__ hi1, bf16* __restrict__ lo1,
    int n)
{
    const float* x = blockIdx.y ? x1 : x0;
    bf16* hi = blockIdx.y ? hi1 : hi0;
    bf16* lo = blockIdx.y ? lo1 : lo0;
    int i = (blockIdx.x * 256 + threadIdx.x) * 4;
    if (i >= n) return;
    float4 v = *(const float4*)(x + i);
    bf16 h0 = __float2bfloat16(v.x), h1 = __float2bfloat16(v.y);
    bf16 h2 = __float2bfloat16(v.z), h3 = __float2bfloat16(v.w);
    __nv_bfloat162 hp0; hp0.x = h0; hp0.y = h1;
    __nv_bfloat162 hp1; hp1.x = h2; hp1.y = h3;
    __nv_bfloat162 lp0;
    lp0.x = __float2bfloat16(v.x - __bfloat162float(h0));
    lp0.y = __float2bfloat16(v.y - __bfloat162float(h1));
    __nv_bfloat162 lp1;
    lp1.x = __float2bfloat16(v.z - __bfloat162float(h2));
    lp1.y = __float2bfloat16(v.w - __bfloat162float(h3));
    *(__nv_bfloat162*)&hi[i]     = hp0;
    *(__nv_bfloat162*)&hi[i + 2] = hp1;
    *(__nv_bfloat162*)&lo[i]     = lp0;
    *(__nv_bfloat162*)&lo[i + 2] = lp1;
}

// ------- weight transpose + split (3 weights in one launch, grid.z) ----------
__global__ void trans_split3_kernel(
    const float* __restrict__ W0, const float* __restrict__ W1,
    const float* __restrict__ W2)
{
    __shared__ float t[32][33];
    int z = blockIdx.z;
    const float* W = (z == 0) ? W0 : (z == 1) ? W1 : W2;
    bf16* hiT = (z == 0) ? g_wftT_hi : (z == 1) ? g_wfoT_hi : g_wfotT_hi;
    bf16* loT = (z == 0) ? g_wftT_lo : (z == 1) ? g_wfoT_lo : g_wfotT_lo;
    int n0 = blockIdx.x * 32, k0 = blockIdx.y * 32;
    int tx = threadIdx.x, ty = threadIdx.y;   // 32 x 8
    #pragma unroll
    for (int i = ty; i < 32; i += 8)
        t[i][tx] = W[(size_t)(k0 + i) * DH + n0 + tx];
    __syncthreads();
    #pragma unroll
    for (int i = ty; i < 32; i += 8) {
        float v = t[tx][i];
        bf16 h = __float2bfloat16(v);
        bf16 l = __float2bfloat16(v - __bfloat162float(h));
        hiT[(size_t)(n0 + i) * DH + k0 + tx] = h;
        loT[(size_t)(n0 + i) * DH + k0 + tx] = l;
    }
}

// ---------------- composite biases, phase 1: partial split-k sums ------------
__global__ __launch_bounds__(256) void bias_comb_p1_kernel(
    const float* __restrict__ b_tar, const float* __restrict__ b_ori,
    const float* __restrict__ W_ft, const float* __restrict__ W_fo,
    const float* __restrict__ W_fot)
{
    __shared__ float red[8][33];
    int z = blockIdx.z;
    int ks = blockIdx.y;
    int n = blockIdx.x * 32 + threadIdx.x;
    int ky = threadIdx.y;   // 0..7
    const float* b1 = (z == 0) ? b_tar : b_ori;
    const float* W2 = (z == 0) ? W_ft : (z == 1) ? W_fo : W_fot;
    int k0 = ks * 256;
    float s = 0.f;
    #pragma unroll 4
    for (int k = k0 + ky; k < k0 + 256; k += 8)
        s += b1[k] * W2[(size_t)k * DH + n];
    red[ky][threadIdx.x] = s;
    __syncthreads();
    if (ky == 0) {
        float tot = 0.f;
        #pragma unroll
        for (int j = 0; j < 8; j++) tot += red[j][threadIdx.x];
        g_bcp[z][ks][n] = tot;
    }
}

// ---------------- composite biases, phase 2: reduce + add b2 -----------------
__global__ void bias_comb_p2_kernel(
    const float* __restrict__ b_ft, const float* __restrict__ b_fo,
    const float* __restrict__ b_fot)
{
    int z = blockIdx.y;
    int n = blockIdx.x * 256 + threadIdx.x;
    const float* b2 = (z == 0) ? b_ft : (z == 1) ? b_fo : b_fot;
    float s = g_bcp[z][0][n] + g_bcp[z][1][n] + g_bcp[z][2][n] + g_bcp[z][3][n];
    g_bc[z][n] = s + b2[n];
}

// ------- batched transpose+scale+split: vt[b][h][o] = otp[b][o][h]*v[b][o] ---
__global__ void vtrans_split_kernel()
{
    __shared__ float t[32][33];
    int b = blockIdx.z;
    int h0 = blockIdx.x * 32, o0 = blockIdx.y * 32;
    int tx = threadIdx.x, ty = threadIdx.y;   // 32 x 8
    const float* src = g_otp + (size_t)b * LL * DH;
    #pragma unroll
    for (int i = ty; i < 32; i += 8)
        t[i][tx] = src[(size_t)(o0 + i) * DH + h0 + tx] * g_v[b * LL + o0 + i];
    __syncthreads();
    bf16* hb = g_vthi + (size_t)b * DH * LL;
    bf16* lb = g_vtlo + (size_t)b * DH * LL;
    #pragma unroll
    for (int i = ty; i < 32; i += 8) {
        float x = t[tx][i];
        bf16 h = __float2bfloat16(x);
        bf16 l = __float2bfloat16(x - __bfloat162float(h));
        hb[(size_t)(h0 + i) * LL + o0 + tx] = h;
        lb[(size_t)(h0 + i) * LL + o0 + tx] = l;
    }
}

// ================= small SIMT kernels ========================================
__device__ __forceinline__ float block_reduce_sum_256(float val, float* red) {
    int tid = threadIdx.x;
    #pragma unroll
    for (int o = 16; o > 0; o >>= 1) val += __shfl_down_sync(0xffffffffu, val, o);
    if ((tid & 31) == 0) red[tid >> 5] = val;
    __syncthreads();
    if (tid < 8) {
        val = red[tid];
        #pragma unroll
        for (int o = 4; o > 0; o >>= 1) val += __shfl_down_sync(0xffu, val, o);
        if (tid == 0) red[0] = val;
    }
    __syncthreads();
    float r = red[0];
    __syncthreads();
    return r;
}

// inv row norms: y==0 -> tar->itn, y==1 -> ofc->ifn (one launch)
__global__ __launch_bounds__(256) void invnorm2_kernel()
{
    __shared__ float red[8];
    int row = blockIdx.x;
    int which = blockIdx.y;
    const float* x = which ? g_ofc : g_tar;
    float* inv = which ? g_ifn : g_itn;
    const float* p = x + (size_t)row * DH;
    float s = 0.f;
    for (int c = threadIdx.x; c < DH; c += 256) { float v = p[c]; s += v * v; }
    float tot = block_reduce_sum_256(s, red);
    if (threadIdx.x == 0) inv[row] = 1.0f / fmaxf(sqrtf(tot), 1e-8f);
}

// ---- Sinkhorn on Qhi (bf16; round-9/16 validated numerics) -------------------
__global__ void rowmv_first_kernel()
{
    int t = blockIdx.x * 8 + threadIdx.y;
    int b = blockIdx.y;
    const bf16* row = g_Qhi + ((size_t)b * LL + t) * LL;
    float s = 0.f;
    for (int o = threadIdx.x * 2; o < LL; o += 64) {
        __nv_bfloat162 q = *(const __nv_bfloat162*)&row[o];
        s += __bfloat162float(q.x) + __bfloat162float(q.y);
    }
    #pragma unroll
    for (int off = 16; off > 0; off >>= 1) s += __shfl_down_sync(0xffffffffu, s, off);
    if (threadIdx.x == 0) g_u[b * LL + t] = 1.0f / s;
}

__global__ void rowmv_kernel()
{
    int t = blockIdx.x * 8 + threadIdx.y;
    int b = blockIdx.y;
    const bf16* row = g_Qhi + ((size_t)b * LL + t) * LL;
    const float* vv = g_v + b * LL;
    float s = 0.f;
    for (int o = threadIdx.x * 2; o < LL; o += 64) {
        __nv_bfloat162 q = *(const __nv_bfloat162*)&row[o];
        float2 v2 = *(const float2*)&vv[o];
        s += __bfloat162float(q.x) * v2.x + __bfloat162float(q.y) * v2.y;
    }
    #pragma unroll
    for (int off = 16; off > 0; off >>= 1) s += __shfl_down_sync(0xffffffffu, s, off);
    if (threadIdx.x == 0) g_u[b * LL + t] = 1.0f / s;
}

__global__ void colmv_kernel()
{
    __shared__ float red[8][32];
    int o = blockIdx.x * 32 + threadIdx.x;
    int b = blockIdx.y;
    const float* uu = g_u + b * LL;
    float s = 0.f;
    for (int t = threadIdx.y; t < LL; t += 8)
        s += __bfloat162float(g_Qhi[((size_t)b * LL + t) * LL + o]) * uu[t];
    red[threadIdx.y][threadIdx.x] = s;
    __syncthreads();
    if (threadIdx.y == 0) {
        float tot = 0.f;
        #pragma unroll
        for (int j = 0; j < 8; j++) tot += red[j][threadIdx.x];
        g_v[b * LL + o] = 1.0f / tot;
    }
}

__global__ void rowscale_kernel()
{
    int t = blockIdx.x * 8 + threadIdx.y;
    int b = blockIdx.y;
    const bf16* row = g_Qhi + ((size_t)b * LL + t) * LL;
    const float* vv = g_v + b * LL;
    float s = 0.f;
    for (int o = threadIdx.x * 2; o < LL; o += 64) {
        __nv_bfloat162 qp = *(const __nv_bfloat162*)&row[o];
        float2 v2 = *(const float2*)&vv[o];
        float q0 = __bfloat162float(qp.x) * v2.x;
        float q1 = __bfloat162float(qp.y) * v2.y;
        s += q0 * q0 + q1 * q1;
    }
    #pragma unroll
    for (int off = 16; off > 0; off >>= 1) s += __shfl_down_sync(0xffffffffu, s, off);
    if (threadIdx.x == 0) {
        float ut = g_u[b * LL + t];
        g_rs[b * LL + t] = ut / fmaxf(ut * sqrtf(s), 1e-12f);
    }
}

__global__ __launch_bounds__(256) void ln_kernel(
    const float* __restrict__ x, const float* __restrict__ g,
    const float* __restrict__ beta, float* __restrict__ y)
{
    __shared__ float buf[DH];
    __shared__ float red[8];
    int row = blockIdx.x;
    const float* p = x + (size_t)row * DH;
    float s = 0.f;
    for (int c = threadIdx.x; c < DH; c += 256) { float v = p[c]; buf[c] = v; s += v; }
    float mean = block_reduce_sum_256(s, red) * (1.0f / DH);
    float s2 = 0.f;
    for (int c = threadIdx.x; c < DH; c += 256) { float d = buf[c] - mean; s2 += d * d; }
    float var = block_reduce_sum_256(s2, red) * (1.0f / DH);
    float inv = rsqrtf(var + 1e-5f);
    for (int c = threadIdx.x; c < DH; c += 256)
        y[(size_t)row * DH + c] = (buf[c] - mean) * inv * g[c] + beta[c];
}

// ---------------- launch -----------------------------------------------------
extern "C" void kernel_launch(void* const* d_in, const int* in_sizes, int n_in,
                              void* d_out, int out_size)
{
    const float* origin = (const float*)d_in[0];
    const float* target = (const float*)d_in[1];
    const float* W_ori = (const float*)d_in[2];  const float* b_ori = (const float*)d_in[3];
    const float* W_tar = (const float*)d_in[4];  const float* b_tar = (const float*)d_in[5];
    const float* W_ft  = (const float*)d_in[6];  const float* b_ft  = (const float*)d_in[7];
    const float* W_fo  = (const float*)d_in[8];  const float* b_fo  = (const float*)d_in[9];
    const float* W_fot = (const float*)d_in[10]; const float* b_fot = (const float*)d_in[11];
    const float* ln_g  = (const float*)d_in[12]; const float* ln_b  = (const float*)d_in[13];
    float* out = (float*)d_out;

    bf16 *ohi, *olo, *thi, *tlo, *woris_hi, *woris_lo, *wtars_hi, *wtars_lo;
    float *obuf;
    cudaGetSymbolAddress((void**)&ohi,      g_ohi);
    cudaGetSymbolAddress((void**)&olo,      g_olo);
    cudaGetSymbolAddress((void**)&thi,      g_thi);
    cudaGetSymbolAddress((void**)&tlo,      g_tlo);
    cudaGetSymbolAddress((void**)&woris_hi, g_woris_hi);
    cudaGetSymbolAddress((void**)&woris_lo, g_woris_lo);
    cudaGetSymbolAddress((void**)&wtars_hi, g_wtars_hi);
    cudaGetSymbolAddress((void**)&wtars_lo, g_wtars_lo);
    cudaGetSymbolAddress((void**)&obuf,     g_obuf);

    const int NELEM = MTOT * DH;
    const int WELEM = (int)WSZ;

    cudaFuncSetAttribute(wgemm3_kernel,
                         cudaFuncAttributeMaxDynamicSharedMemorySize, TC_SMEM);
    cudaFuncSetAttribute(gemm3_tc_kernel,
                         cudaFuncAttributeMaxDynamicSharedMemorySize, TC_SMEM);
    cudaFuncSetAttribute(qgemm_tc_kernel,
                         cudaFuncAttributeMaxDynamicSharedMemorySize, TC_SMEM);
    cudaFuncSetAttribute(fgemm_tc_kernel,
                         cudaFuncAttributeMaxDynamicSharedMemorySize, TC_SMEM);

    // lazy one-time stream/event creation (first call is the uncaptured
    // correctness run; the captured work is identical on every call)
    static cudaStream_t s2 = nullptr;
    static cudaEvent_t evFork = nullptr, evJoin = nullptr;
    static cudaEvent_t evFork2 = nullptr, evJoin2 = nullptr;
    if (!s2) {
        cudaStreamCreateWithFlags(&s2, cudaStreamNonBlocking);
        cudaEventCreateWithFlags(&evFork,  cudaEventDisableTiming);
        cudaEventCreateWithFlags(&evJoin,  cudaEventDisableTiming);
        cudaEventCreateWithFlags(&evFork2, cudaEventDisableTiming);
        cudaEventCreateWithFlags(&evJoin2, cudaEventDisableTiming);
    }

    dim3 blk(256);

    // ---- fork: activation split (branch B) || weight-prep chain (branch A) --
    cudaEventRecord(evFork, 0);
    cudaStreamWaitEvent(s2, evFork, 0);

    // branch B (s2): activation splits
    split2_kernel<<<dim3(NELEM / 4 / 256, 2), blk, 0, s2>>>(
        origin, ohi, olo, target, thi, tlo, NELEM);

    // branch A (stream 0): weight splits -> trans -> bias -> composite weights
    split2_kernel<<<dim3(WELEM / 4 / 256, 2), blk>>>(
        W_ori, woris_hi, woris_lo, W_tar, wtars_hi, wtars_lo, WELEM);
    trans_split3_kernel<<<dim3(32, 32, 3), dim3(32, 8)>>>(W_ft, W_fo, W_fot);
    bias_comb_p1_kernel<<<dim3(DH / 32, 4, 3), dim3(32, 8)>>>(
        b_tar, b_ori, W_ft, W_fo, W_fot);
    bias_comb_p2_kernel<<<dim3(DH / 256, 3), blk>>>(b_ft, b_fo, b_fot);
    wgemm3_kernel<<<dim3(8, 8, 3), blk, TC_SMEM>>>();

    // join
    cudaEventRecord(evJoin, s2);
    cudaStreamWaitEvent(0, evJoin, 0);

    // fused 3 big GEMMs: tar / ofc / otp
    gemm3_tc_kernel<<<dim3(8, 64, 3), blk, TC_SMEM>>>();

    // row inverse norms (one launch, both arrays)
    invnorm2_kernel<<<dim3(MTOT, 2), blk>>>();

    // Q = exp(cos/0.05), bf16 hi/lo only
    qgemm_tc_kernel<<<dim3(LL / 128, LL / 128, BB), blk, TC_SMEM>>>();

    // Sinkhorn on Qhi (bf16): u = 1/(Qv), v = 1/(Q^T u), 5 iterations
    rowmv_first_kernel<<<dim3(LL / 8, BB), dim3(32, 8)>>>();
    colmv_kernel<<<dim3(LL / 32, BB), dim3(32, 8)>>>();
    for (int it = 0; it < 4; it++) {
        rowmv_kernel<<<dim3(LL / 8, BB), dim3(32, 8)>>>();
        colmv_kernel<<<dim3(LL / 32, BB), dim3(32, 8)>>>();
    }

    // ---- fork 2: rowscale (branch B) || vtrans (branch A) -------------------
    cudaEventRecord(evFork2, 0);
    cudaStreamWaitEvent(s2, evFork2, 0);
    rowscale_kernel<<<dim3(LL / 8, BB), dim3(32, 8), 0, s2>>>();
    vtrans_split_kernel<<<dim3(DH / 32, LL / 32, BB), dim3(32, 8)>>>();
    cudaEventRecord(evJoin2, s2);
    cudaStreamWaitEvent(0, evJoin2, 0);

    // out = rs_t * (Q @ vt^T) + tar   (3-term Qhi+Qlo)
    fgemm_tc_kernel<<<dim3(DH / 128, LL / 128, BB), blk, TC_SMEM>>>();

    // LayerNorm
    ln_kernel<<<MTOT, blk>>>(obuf, ln_g, ln_b, out);
}